// round 1
// baseline (speedup 1.0000x reference)
#include <cuda_runtime.h>

#define GS 128
#define OBS 1024
#define HH 256
#define OUTD 1024
#define NO 18
#define BB 256
#define M_ROWS (BB * GS)   // 32768

// ---------------- scratch (device globals: no allocation allowed) -------------
__device__ float g_Y[(size_t)M_ROWS * 512];    // [B*GS][512] = [x@W0_rel | x@W0_root]
__device__ float g_h0[(size_t)M_ROWS * HH];    // [B*GS][256]
__device__ float g_rh[BB * 512];               // [r1 | h0_n] per batch
__device__ float g_no[BB * OUTD];              // node_out per batch
__device__ const float* g_rowptr[M_ROWS];      // gathered X row pointers

// ---------------- kernel 0: build X row pointer table ------------------------
__global__ void k_rowptr(const float* __restrict__ flat,
                         const float* __restrict__ nodes,
                         const int* __restrict__ num_nodes)
{
    int r = blockIdx.x * blockDim.x + threadIdx.x;
    if (r >= M_ROWS) return;
    int b = r >> 7, j = r & 127;
    g_rowptr[r] = (j == num_nodes[b]) ? (flat + (size_t)b * OBS)
                                      : (nodes + (size_t)r * OBS);
}

// ---------------- kernel 1: Y = X @ [W0_rel | W0_root]  (M=32768,K=1024,N=512)
__global__ __launch_bounds__(256) void k_gemm0(const float* __restrict__ W0_rel,
                                               const float* __restrict__ W0_root)
{
    __shared__ float As[8][128];
    __shared__ float Bs[8][128];
    int tid = threadIdx.x;
    int m0 = blockIdx.y * 128;
    int n0 = blockIdx.x * 128;
    const float* Wb = (n0 < 256) ? (W0_rel + n0) : (W0_root + (n0 - 256));

    int arow = tid >> 1, ak = (tid & 1) * 4;
    const float* aptr = g_rowptr[m0 + arow];
    int bk = tid >> 5, bn = (tid & 31) * 4;
    int tx = tid & 15, ty = tid >> 4;

    float acc[8][8];
#pragma unroll
    for (int i = 0; i < 8; ++i)
#pragma unroll
        for (int j = 0; j < 8; ++j) acc[i][j] = 0.f;

    for (int kt = 0; kt < 1024; kt += 8) {
        float4 av = *(const float4*)(aptr + kt + ak);
        float4 bv = *(const float4*)(Wb + (size_t)(kt + bk) * 256 + bn);
        As[ak + 0][arow] = av.x;
        As[ak + 1][arow] = av.y;
        As[ak + 2][arow] = av.z;
        As[ak + 3][arow] = av.w;
        *(float4*)&Bs[bk][bn] = bv;
        __syncthreads();
#pragma unroll
        for (int k = 0; k < 8; ++k) {
            float a[8], bb[8];
            *(float4*)(a)     = *(const float4*)&As[k][ty * 8];
            *(float4*)(a + 4) = *(const float4*)&As[k][ty * 8 + 4];
            *(float4*)(bb)     = *(const float4*)&Bs[k][tx * 8];
            *(float4*)(bb + 4) = *(const float4*)&Bs[k][tx * 8 + 4];
#pragma unroll
            for (int i = 0; i < 8; ++i)
#pragma unroll
                for (int j = 0; j < 8; ++j) acc[i][j] += a[i] * bb[j];
        }
        __syncthreads();
    }
#pragma unroll
    for (int i = 0; i < 8; ++i) {
        float* yr = g_Y + (size_t)(m0 + ty * 8 + i) * 512 + n0 + tx * 8;
        *(float4*)(yr)     = make_float4(acc[i][0], acc[i][1], acc[i][2], acc[i][3]);
        *(float4*)(yr + 4) = make_float4(acc[i][4], acc[i][5], acc[i][6], acc[i][7]);
    }
}

// ---------------- kernel 2: h0 = relu(A^T @ Yrel + b0 + Yroot) ----------------
// grid (4 c-tiles of 64, B batches), 256 threads. A kept as a 128x128 bitset.
__global__ __launch_bounds__(256) void k_h0(const int* __restrict__ adj,
                                            const int* __restrict__ num_nodes,
                                            const float* __restrict__ b0)
{
    __shared__ float2 Ysh[128][32];      // Yrel tile [k][c-pair], 32 KB
    __shared__ unsigned bitw[128][4];    // bit j of bitw[k] <=> A[k][j] != 0
    int b = blockIdx.y;
    int c0 = blockIdx.x * 64;
    int tid = threadIdx.x;
    int c2 = tid & 31, ty = tid >> 5;

    // load Yrel[b][0:128][c0:c0+64] (8192 floats)
#pragma unroll
    for (int r = 0; r < 8; ++r) {
        int fi = r * 256 + tid;          // float4 index, 2048 total
        int k = fi >> 4;
        int c4 = (fi & 15) * 4;
        float4 v = *(const float4*)(g_Y + (size_t)(b * 128 + k) * 512 + c0 + c4);
        float2* dst = &Ysh[k][c4 >> 1];
        dst[0] = make_float2(v.x, v.y);
        dst[1] = make_float2(v.z, v.w);
    }
    // build bitset via ballot (coalesced adj reads)
    const int* adjb = adj + (size_t)b * GS * GS;
#pragma unroll 4
    for (int it = 0; it < 64; ++it) {
        int idx = it * 256 + tid;
        unsigned m = __ballot_sync(0xffffffffu, adjb[idx] != 0);
        if ((tid & 31) == 0) bitw[idx >> 7][(idx & 127) >> 5] = m;
    }
    __syncthreads();
    if (tid == 0) {  // apply the three edge insertions
        int n = num_nodes[b];
        bitw[n][n >> 5] |= 1u << (n & 31);
        if (n > 0) {
            bitw[n][(n - 1) >> 5] |= 1u << ((n - 1) & 31);
            bitw[n - 1][n >> 5] |= 1u << (n & 31);
        }
    }
    __syncthreads();

    float2 acc[16];
#pragma unroll
    for (int i = 0; i < 16; ++i) acc[i] = make_float2(0.f, 0.f);

    for (int k = 0; k < 128; ++k) {
        float2 y = Ysh[k][c2];
        unsigned bits = bitw[k][ty >> 1] >> ((ty & 1) * 16);
#pragma unroll
        for (int i = 0; i < 16; ++i) {
            if ((bits >> i) & 1u) { acc[i].x += y.x; acc[i].y += y.y; }
        }
    }
    int c = c0 + c2 * 2;
    float2 bbv = *(const float2*)(b0 + c);
#pragma unroll
    for (int i = 0; i < 16; ++i) {
        int j = ty * 16 + i;
        float2 root = *(const float2*)(g_Y + (size_t)(b * 128 + j) * 512 + 256 + c);
        float2 o;
        o.x = fmaxf(acc[i].x + root.x + bbv.x, 0.f);
        o.y = fmaxf(acc[i].y + root.y + bbv.y, 0.f);
        *(float2*)(g_h0 + (size_t)(b * 128 + j) * 256 + c) = o;
    }
}

// ---------------- kernel 3: r1 = A[:,n]^T @ h0 ; gather h0_n ------------------
__global__ __launch_bounds__(256) void k_row(const int* __restrict__ adj,
                                             const int* __restrict__ num_nodes)
{
    __shared__ unsigned colw[4];
    __shared__ int sn;
    int b = blockIdx.x, tid = threadIdx.x;
    if (tid == 0) sn = num_nodes[b];
    __syncthreads();
    int n = sn;
    if (tid < 128) {
        int pred = adj[((size_t)b * 128 + tid) * 128 + n] != 0;
        unsigned m = __ballot_sync(0xffffffffu, pred);
        if ((tid & 31) == 0) colw[tid >> 5] = m;
    }
    __syncthreads();
    if (tid == 0) {
        colw[n >> 5] |= 1u << (n & 31);
        if (n > 0) colw[(n - 1) >> 5] |= 1u << ((n - 1) & 31);
    }
    __syncthreads();
    float acc = 0.f;
#pragma unroll
    for (int w = 0; w < 4; ++w) {
        unsigned bits = colw[w];
        while (bits) {
            int t = __ffs(bits) - 1;
            bits &= bits - 1;
            acc += g_h0[(size_t)(b * 128 + w * 32 + t) * 256 + tid];
        }
    }
    g_rh[b * 512 + tid] = acc;
    g_rh[b * 512 + 256 + tid] = g_h0[(size_t)(b * 128 + n) * 256 + tid];
}

// ---------------- kernel 4: node_out = relu(rh @ [W1_rel;W1_root] + b1) -------
// M=256, N=1024, K=512; 64x64 tiles, 4x4 microtiles.
__global__ __launch_bounds__(256) void k_gemm1(const float* __restrict__ W1_rel,
                                               const float* __restrict__ W1_root,
                                               const float* __restrict__ b1)
{
    __shared__ float As[8][64];
    __shared__ float Bs[8][64];
    int tid = threadIdx.x;
    int n0 = blockIdx.x * 64, m0 = blockIdx.y * 64;
    int arow = tid >> 2, ak = (tid & 3) * 2;
    int bk = tid >> 5, bn = (tid & 31) * 2;
    int tx = tid & 15, ty = tid >> 4;

    float acc[4][4];
#pragma unroll
    for (int i = 0; i < 4; ++i)
#pragma unroll
        for (int j = 0; j < 4; ++j) acc[i][j] = 0.f;

    for (int kt = 0; kt < 512; kt += 8) {
        float2 av = *(const float2*)(g_rh + (m0 + arow) * 512 + kt + ak);
        const float* Wb = (kt < 256) ? (W1_rel + (size_t)kt * 1024)
                                     : (W1_root + (size_t)(kt - 256) * 1024);
        float2 bv = *(const float2*)(Wb + (size_t)bk * 1024 + n0 + bn);
        As[ak][arow] = av.x;
        As[ak + 1][arow] = av.y;
        *(float2*)&Bs[bk][bn] = bv;
        __syncthreads();
#pragma unroll
        for (int k = 0; k < 8; ++k) {
            float a[4], bb[4];
            *(float4*)a  = *(const float4*)&As[k][ty * 4];
            *(float4*)bb = *(const float4*)&Bs[k][tx * 4];
#pragma unroll
            for (int i = 0; i < 4; ++i)
#pragma unroll
                for (int j = 0; j < 4; ++j) acc[i][j] += a[i] * bb[j];
        }
        __syncthreads();
    }
#pragma unroll
    for (int i = 0; i < 4; ++i) {
        int row = m0 + ty * 4 + i;
#pragma unroll
        for (int j = 0; j < 4; ++j) {
            int col = n0 + tx * 4 + j;
            g_no[(size_t)row * 1024 + col] = fmaxf(acc[i][j] + b1[col], 0.f);
        }
    }
}

// ---------------- kernel 5: logits + value -----------------------------------
__global__ __launch_bounds__(256) void k_out(const float* __restrict__ Wl,
                                             const float* __restrict__ bl,
                                             const float* __restrict__ Wv,
                                             const float* __restrict__ bv,
                                             float* __restrict__ out, int out_size)
{
    int b = blockIdx.x;
    int w = threadIdx.x >> 5, lane = threadIdx.x & 31;
    const float* nb = g_no + (size_t)b * 1024;
    for (int o = w; o < 19; o += 8) {
        float acc = 0.f;
        if (o < 18) {
            for (int i = lane; i < 1024; i += 32) acc += nb[i] * Wl[i * 18 + o];
        } else {
            for (int i = lane; i < 1024; i += 32) acc += nb[i] * Wv[i];
        }
#pragma unroll
        for (int s = 16; s; s >>= 1) acc += __shfl_down_sync(0xffffffffu, acc, s);
        if (lane == 0) {
            if (o < 18) {
                int idx = b * NO + o;
                if (idx < out_size) out[idx] = acc + bl[o];
            } else {
                int idx = BB * NO + b;
                if (idx < out_size) out[idx] = acc + bv[0];
            }
        }
    }
}

// ---------------- launch ------------------------------------------------------
extern "C" void kernel_launch(void* const* d_in, const int* in_sizes, int n_in,
                              void* d_out, int out_size)
{
    const float* flat      = (const float*)d_in[0];
    const float* nodes     = (const float*)d_in[1];
    const int*   num_nodes = (const int*)d_in[2];
    const int*   adj       = (const int*)d_in[3];
    // d_in[4] = seq_lens (unused)
    const float* W0_rel  = (const float*)d_in[5];
    const float* b0      = (const float*)d_in[6];
    const float* W0_root = (const float*)d_in[7];
    const float* W1_rel  = (const float*)d_in[8];
    const float* b1      = (const float*)d_in[9];
    const float* W1_root = (const float*)d_in[10];
    const float* Wl      = (const float*)d_in[11];
    const float* bl      = (const float*)d_in[12];
    const float* Wv      = (const float*)d_in[13];
    const float* bv      = (const float*)d_in[14];
    float* out = (float*)d_out;

    k_rowptr<<<M_ROWS / 256, 256>>>(flat, nodes, num_nodes);
    k_gemm0<<<dim3(4, 256), 256>>>(W0_rel, W0_root);
    k_h0<<<dim3(4, BB), 256>>>(adj, num_nodes, b0);
    k_row<<<BB, 256>>>(adj, num_nodes);
    k_gemm1<<<dim3(16, 4), 256>>>(W1_rel, W1_root, b1);
    k_out<<<BB, 256>>>(Wl, bl, Wv, bv, out, out_size);
}

// round 2
// speedup vs baseline: 1.0041x; 1.0041x over previous
#include <cuda_runtime.h>

#define GS 128
#define OBS 1024
#define HH 256
#define OUTD 1024
#define NO 18
#define BB 256
#define M_ROWS (BB * GS)   // 32768

// ---------------- scratch (device globals: no allocation allowed) -------------
__device__ float g_Y[(size_t)M_ROWS * 512];    // [B*GS][512] = [x@W0_rel | x@W0_root]
__device__ float g_h0[(size_t)M_ROWS * HH];    // [B*GS][256]
__device__ float g_rh[BB * 512];               // [r1 | h0_n] per batch
__device__ float g_no[BB * OUTD];              // node_out per batch
__device__ const float* g_rowptr[M_ROWS];      // gathered X row pointers

// ---------------- kernel 0: build X row pointer table ------------------------
__global__ void k_rowptr(const float* __restrict__ flat,
                         const float* __restrict__ nodes,
                         const int* __restrict__ num_nodes)
{
    int r = blockIdx.x * blockDim.x + threadIdx.x;
    if (r >= M_ROWS) return;
    int b = r >> 7, j = r & 127;
    g_rowptr[r] = (j == num_nodes[b]) ? (flat + (size_t)b * OBS)
                                      : (nodes + (size_t)r * OBS);
}

// ---------------- kernel 1: Y = X @ [W0_rel | W0_root]  (M=32768,K=1024,N=512)
__global__ __launch_bounds__(256) void k_gemm0(const float* __restrict__ W0_rel,
                                               const float* __restrict__ W0_root)
{
    __shared__ float As[8][128];
    __shared__ float Bs[8][128];
    int tid = threadIdx.x;
    int m0 = blockIdx.y * 128;
    int n0 = blockIdx.x * 128;
    const float* Wb = (n0 < 256) ? (W0_rel + n0) : (W0_root + (n0 - 256));

    int arow = tid >> 1, ak = (tid & 1) * 4;
    const float* aptr = g_rowptr[m0 + arow];
    int bk = tid >> 5, bn = (tid & 31) * 4;
    int tx = tid & 15, ty = tid >> 4;

    float acc[8][8];
#pragma unroll
    for (int i = 0; i < 8; ++i)
#pragma unroll
        for (int j = 0; j < 8; ++j) acc[i][j] = 0.f;

    for (int kt = 0; kt < 1024; kt += 8) {
        float4 av = *(const float4*)(aptr + kt + ak);
        float4 bv = *(const float4*)(Wb + (size_t)(kt + bk) * 256 + bn);
        As[ak + 0][arow] = av.x;
        As[ak + 1][arow] = av.y;
        As[ak + 2][arow] = av.z;
        As[ak + 3][arow] = av.w;
        *(float4*)&Bs[bk][bn] = bv;
        __syncthreads();
#pragma unroll
        for (int k = 0; k < 8; ++k) {
            float a[8], bb[8];
            *(float4*)(a)     = *(const float4*)&As[k][ty * 8];
            *(float4*)(a + 4) = *(const float4*)&As[k][ty * 8 + 4];
            *(float4*)(bb)     = *(const float4*)&Bs[k][tx * 8];
            *(float4*)(bb + 4) = *(const float4*)&Bs[k][tx * 8 + 4];
#pragma unroll
            for (int i = 0; i < 8; ++i)
#pragma unroll
                for (int j = 0; j < 8; ++j) acc[i][j] += a[i] * bb[j];
        }
        __syncthreads();
    }
#pragma unroll
    for (int i = 0; i < 8; ++i) {
        float* yr = g_Y + (size_t)(m0 + ty * 8 + i) * 512 + n0 + tx * 8;
        *(float4*)(yr)     = make_float4(acc[i][0], acc[i][1], acc[i][2], acc[i][3]);
        *(float4*)(yr + 4) = make_float4(acc[i][4], acc[i][5], acc[i][6], acc[i][7]);
    }
}

// ---------------- kernel 2: h0 = relu(A^T @ Yrel + b0 + Yroot) ----------------
// grid (4 c-tiles of 64, B batches), 256 threads. A kept as a 128x128 bitset.
__global__ __launch_bounds__(256) void k_h0(const int* __restrict__ adj,
                                            const int* __restrict__ num_nodes,
                                            const float* __restrict__ b0)
{
    __shared__ float2 Ysh[128][32];      // Yrel tile [k][c-pair], 32 KB
    __shared__ unsigned bitw[128][4];    // bit j of bitw[k] <=> A[k][j] != 0
    int b = blockIdx.y;
    int c0 = blockIdx.x * 64;
    int tid = threadIdx.x;
    int c2 = tid & 31, ty = tid >> 5;

    // load Yrel[b][0:128][c0:c0+64] (8192 floats)
#pragma unroll
    for (int r = 0; r < 8; ++r) {
        int fi = r * 256 + tid;          // float4 index, 2048 total
        int k = fi >> 4;
        int c4 = (fi & 15) * 4;
        float4 v = *(const float4*)(g_Y + (size_t)(b * 128 + k) * 512 + c0 + c4);
        float2* dst = &Ysh[k][c4 >> 1];
        dst[0] = make_float2(v.x, v.y);
        dst[1] = make_float2(v.z, v.w);
    }
    // build bitset via ballot (coalesced adj reads)
    const int* adjb = adj + (size_t)b * GS * GS;
#pragma unroll 4
    for (int it = 0; it < 64; ++it) {
        int idx = it * 256 + tid;
        unsigned m = __ballot_sync(0xffffffffu, adjb[idx] != 0);
        if ((tid & 31) == 0) bitw[idx >> 7][(idx & 127) >> 5] = m;
    }
    __syncthreads();
    if (tid == 0) {  // apply the three edge insertions
        int n = num_nodes[b];
        bitw[n][n >> 5] |= 1u << (n & 31);
        if (n > 0) {
            bitw[n][(n - 1) >> 5] |= 1u << ((n - 1) & 31);
            bitw[n - 1][n >> 5] |= 1u << (n & 31);
        }
    }
    __syncthreads();

    float2 acc[16];
#pragma unroll
    for (int i = 0; i < 16; ++i) acc[i] = make_float2(0.f, 0.f);

    for (int k = 0; k < 128; ++k) {
        float2 y = Ysh[k][c2];
        unsigned bits = bitw[k][ty >> 1] >> ((ty & 1) * 16);
#pragma unroll
        for (int i = 0; i < 16; ++i) {
            if ((bits >> i) & 1u) { acc[i].x += y.x; acc[i].y += y.y; }
        }
    }
    int c = c0 + c2 * 2;
    float2 bbv = *(const float2*)(b0 + c);
#pragma unroll
    for (int i = 0; i < 16; ++i) {
        int j = ty * 16 + i;
        float2 root = *(const float2*)(g_Y + (size_t)(b * 128 + j) * 512 + 256 + c);
        float2 o;
        o.x = fmaxf(acc[i].x + root.x + bbv.x, 0.f);
        o.y = fmaxf(acc[i].y + root.y + bbv.y, 0.f);
        *(float2*)(g_h0 + (size_t)(b * 128 + j) * 256 + c) = o;
    }
}

// ---------------- kernel 3: r1 = A[:,n]^T @ h0 ; gather h0_n ------------------
__global__ __launch_bounds__(256) void k_row(const int* __restrict__ adj,
                                             const int* __restrict__ num_nodes)
{
    __shared__ unsigned colw[4];
    __shared__ int sn;
    int b = blockIdx.x, tid = threadIdx.x;
    if (tid == 0) sn = num_nodes[b];
    __syncthreads();
    int n = sn;
    if (tid < 128) {
        int pred = adj[((size_t)b * 128 + tid) * 128 + n] != 0;
        unsigned m = __ballot_sync(0xffffffffu, pred);
        if ((tid & 31) == 0) colw[tid >> 5] = m;
    }
    __syncthreads();
    if (tid == 0) {
        colw[n >> 5] |= 1u << (n & 31);
        if (n > 0) colw[(n - 1) >> 5] |= 1u << ((n - 1) & 31);
    }
    __syncthreads();
    float acc = 0.f;
#pragma unroll
    for (int w = 0; w < 4; ++w) {
        unsigned bits = colw[w];
        while (bits) {
            int t = __ffs(bits) - 1;
            bits &= bits - 1;
            acc += g_h0[(size_t)(b * 128 + w * 32 + t) * 256 + tid];
        }
    }
    g_rh[b * 512 + tid] = acc;
    g_rh[b * 512 + 256 + tid] = g_h0[(size_t)(b * 128 + n) * 256 + tid];
}

// ---------------- kernel 4: node_out = relu(rh @ [W1_rel;W1_root] + b1) -------
// M=256, N=1024, K=512; 64x64 tiles, 4x4 microtiles.
__global__ __launch_bounds__(256) void k_gemm1(const float* __restrict__ W1_rel,
                                               const float* __restrict__ W1_root,
                                               const float* __restrict__ b1)
{
    __shared__ float As[8][64];
    __shared__ float Bs[8][64];
    int tid = threadIdx.x;
    int n0 = blockIdx.x * 64, m0 = blockIdx.y * 64;
    int arow = tid >> 2, ak = (tid & 3) * 2;
    int bk = tid >> 5, bn = (tid & 31) * 2;
    int tx = tid & 15, ty = tid >> 4;

    float acc[4][4];
#pragma unroll
    for (int i = 0; i < 4; ++i)
#pragma unroll
        for (int j = 0; j < 4; ++j) acc[i][j] = 0.f;

    for (int kt = 0; kt < 512; kt += 8) {
        float2 av = *(const float2*)(g_rh + (m0 + arow) * 512 + kt + ak);
        const float* Wb = (kt < 256) ? (W1_rel + (size_t)kt * 1024)
                                     : (W1_root + (size_t)(kt - 256) * 1024);
        float2 bv = *(const float2*)(Wb + (size_t)bk * 1024 + n0 + bn);
        As[ak][arow] = av.x;
        As[ak + 1][arow] = av.y;
        *(float2*)&Bs[bk][bn] = bv;
        __syncthreads();
#pragma unroll
        for (int k = 0; k < 8; ++k) {
            float a[4], bb[4];
            *(float4*)a  = *(const float4*)&As[k][ty * 4];
            *(float4*)bb = *(const float4*)&Bs[k][tx * 4];
#pragma unroll
            for (int i = 0; i < 4; ++i)
#pragma unroll
                for (int j = 0; j < 4; ++j) acc[i][j] += a[i] * bb[j];
        }
        __syncthreads();
    }
#pragma unroll
    for (int i = 0; i < 4; ++i) {
        int row = m0 + ty * 4 + i;
#pragma unroll
        for (int j = 0; j < 4; ++j) {
            int col = n0 + tx * 4 + j;
            g_no[(size_t)row * 1024 + col] = fmaxf(acc[i][j] + b1[col], 0.f);
        }
    }
}

// ---------------- kernel 5: logits + value -----------------------------------
__global__ __launch_bounds__(256) void k_out(const float* __restrict__ Wl,
                                             const float* __restrict__ bl,
                                             const float* __restrict__ Wv,
                                             const float* __restrict__ bv,
                                             float* __restrict__ out, int out_size)
{
    int b = blockIdx.x;
    int w = threadIdx.x >> 5, lane = threadIdx.x & 31;
    const float* nb = g_no + (size_t)b * 1024;
    for (int o = w; o < 19; o += 8) {
        float acc = 0.f;
        if (o < 18) {
            for (int i = lane; i < 1024; i += 32) acc += nb[i] * Wl[i * 18 + o];
        } else {
            for (int i = lane; i < 1024; i += 32) acc += nb[i] * Wv[i];
        }
#pragma unroll
        for (int s = 16; s; s >>= 1) acc += __shfl_down_sync(0xffffffffu, acc, s);
        if (lane == 0) {
            if (o < 18) {
                int idx = b * NO + o;
                if (idx < out_size) out[idx] = acc + bl[o];
            } else {
                int idx = BB * NO + b;
                if (idx < out_size) out[idx] = acc + bv[0];
            }
        }
    }
}

// ---------------- launch ------------------------------------------------------
extern "C" void kernel_launch(void* const* d_in, const int* in_sizes, int n_in,
                              void* d_out, int out_size)
{
    const float* flat      = (const float*)d_in[0];
    const float* nodes     = (const float*)d_in[1];
    const int*   num_nodes = (const int*)d_in[2];
    const int*   adj       = (const int*)d_in[3];
    // d_in[4] = seq_lens (unused)
    const float* W0_rel  = (const float*)d_in[5];
    const float* b0      = (const float*)d_in[6];
    const float* W0_root = (const float*)d_in[7];
    const float* W1_rel  = (const float*)d_in[8];
    const float* b1      = (const float*)d_in[9];
    const float* W1_root = (const float*)d_in[10];
    const float* Wl      = (const float*)d_in[11];
    const float* bl      = (const float*)d_in[12];
    const float* Wv      = (const float*)d_in[13];
    const float* bv      = (const float*)d_in[14];
    float* out = (float*)d_out;

    k_rowptr<<<M_ROWS / 256, 256>>>(flat, nodes, num_nodes);
    k_gemm0<<<dim3(4, 256), 256>>>(W0_rel, W0_root);
    k_h0<<<dim3(4, BB), 256>>>(adj, num_nodes, b0);
    k_row<<<BB, 256>>>(adj, num_nodes);
    k_gemm1<<<dim3(16, 4), 256>>>(W1_rel, W1_root, b1);
    k_out<<<BB, 256>>>(Wl, bl, Wv, bv, out, out_size);
}

// round 3
// speedup vs baseline: 1.0046x; 1.0005x over previous
#include <cuda_runtime.h>

#define GS 128
#define OBS 1024
#define HH 256
#define OUTD 1024
#define NO 18
#define BB 256
#define M_ROWS (BB * GS)   // 32768

// ---------------- scratch (device globals: no allocation allowed) -------------
__device__ float g_Y[(size_t)M_ROWS * 512];    // [B*GS][512] = [x@W0_rel | x@W0_root]
__device__ float g_h0[(size_t)M_ROWS * HH];    // [B*GS][256]
__device__ float g_rh[BB * 512];               // [r1 | h0_n] per batch
__device__ float g_no[BB * OUTD];              // node_out per batch
__device__ const float* g_rowptr[M_ROWS];      // gathered X row pointers

// ---------------- kernel 0: build X row pointer table ------------------------
__global__ void k_rowptr(const float* __restrict__ flat,
                         const float* __restrict__ nodes,
                         const int* __restrict__ num_nodes)
{
    int r = blockIdx.x * blockDim.x + threadIdx.x;
    if (r >= M_ROWS) return;
    int b = r >> 7, j = r & 127;
    g_rowptr[r] = (j == num_nodes[b]) ? (flat + (size_t)b * OBS)
                                      : (nodes + (size_t)r * OBS);
}

// ---------------- kernel 1: Y = X @ [W0_rel | W0_root]  (M=32768,K=1024,N=512)
__global__ __launch_bounds__(256) void k_gemm0(const float* __restrict__ W0_rel,
                                               const float* __restrict__ W0_root)
{
    __shared__ float As[8][128];
    __shared__ float Bs[8][128];
    int tid = threadIdx.x;
    int m0 = blockIdx.y * 128;
    int n0 = blockIdx.x * 128;
    const float* Wb = (n0 < 256) ? (W0_rel + n0) : (W0_root + (n0 - 256));

    int arow = tid >> 1, ak = (tid & 1) * 4;
    const float* aptr = g_rowptr[m0 + arow];
    int bk = tid >> 5, bn = (tid & 31) * 4;
    int tx = tid & 15, ty = tid >> 4;

    float acc[8][8];
#pragma unroll
    for (int i = 0; i < 8; ++i)
#pragma unroll
        for (int j = 0; j < 8; ++j) acc[i][j] = 0.f;

    for (int kt = 0; kt < 1024; kt += 8) {
        float4 av = *(const float4*)(aptr + kt + ak);
        float4 bv = *(const float4*)(Wb + (size_t)(kt + bk) * 256 + bn);
        As[ak + 0][arow] = av.x;
        As[ak + 1][arow] = av.y;
        As[ak + 2][arow] = av.z;
        As[ak + 3][arow] = av.w;
        *(float4*)&Bs[bk][bn] = bv;
        __syncthreads();
#pragma unroll
        for (int k = 0; k < 8; ++k) {
            float a[8], bb[8];
            *(float4*)(a)     = *(const float4*)&As[k][ty * 8];
            *(float4*)(a + 4) = *(const float4*)&As[k][ty * 8 + 4];
            *(float4*)(bb)     = *(const float4*)&Bs[k][tx * 8];
            *(float4*)(bb + 4) = *(const float4*)&Bs[k][tx * 8 + 4];
#pragma unroll
            for (int i = 0; i < 8; ++i)
#pragma unroll
                for (int j = 0; j < 8; ++j) acc[i][j] += a[i] * bb[j];
        }
        __syncthreads();
    }
#pragma unroll
    for (int i = 0; i < 8; ++i) {
        float* yr = g_Y + (size_t)(m0 + ty * 8 + i) * 512 + n0 + tx * 8;
        *(float4*)(yr)     = make_float4(acc[i][0], acc[i][1], acc[i][2], acc[i][3]);
        *(float4*)(yr + 4) = make_float4(acc[i][4], acc[i][5], acc[i][6], acc[i][7]);
    }
}

// ---------------- kernel 2: h0 = relu(A^T @ Yrel + b0 + Yroot) ----------------
// grid (4 c-tiles of 64, B batches), 256 threads. A kept as a 128x128 bitset.
__global__ __launch_bounds__(256) void k_h0(const int* __restrict__ adj,
                                            const int* __restrict__ num_nodes,
                                            const float* __restrict__ b0)
{
    __shared__ float2 Ysh[128][32];      // Yrel tile [k][c-pair], 32 KB
    __shared__ unsigned bitw[128][4];    // bit j of bitw[k] <=> A[k][j] != 0
    int b = blockIdx.y;
    int c0 = blockIdx.x * 64;
    int tid = threadIdx.x;
    int c2 = tid & 31, ty = tid >> 5;

    // load Yrel[b][0:128][c0:c0+64] (8192 floats)
#pragma unroll
    for (int r = 0; r < 8; ++r) {
        int fi = r * 256 + tid;          // float4 index, 2048 total
        int k = fi >> 4;
        int c4 = (fi & 15) * 4;
        float4 v = *(const float4*)(g_Y + (size_t)(b * 128 + k) * 512 + c0 + c4);
        float2* dst = &Ysh[k][c4 >> 1];
        dst[0] = make_float2(v.x, v.y);
        dst[1] = make_float2(v.z, v.w);
    }
    // build bitset via ballot (coalesced adj reads)
    const int* adjb = adj + (size_t)b * GS * GS;
#pragma unroll 4
    for (int it = 0; it < 64; ++it) {
        int idx = it * 256 + tid;
        unsigned m = __ballot_sync(0xffffffffu, adjb[idx] != 0);
        if ((tid & 31) == 0) bitw[idx >> 7][(idx & 127) >> 5] = m;
    }
    __syncthreads();
    if (tid == 0) {  // apply the three edge insertions
        int n = num_nodes[b];
        bitw[n][n >> 5] |= 1u << (n & 31);
        if (n > 0) {
            bitw[n][(n - 1) >> 5] |= 1u << ((n - 1) & 31);
            bitw[n - 1][n >> 5] |= 1u << (n & 31);
        }
    }
    __syncthreads();

    float2 acc[16];
#pragma unroll
    for (int i = 0; i < 16; ++i) acc[i] = make_float2(0.f, 0.f);

    for (int k = 0; k < 128; ++k) {
        float2 y = Ysh[k][c2];
        unsigned bits = bitw[k][ty >> 1] >> ((ty & 1) * 16);
#pragma unroll
        for (int i = 0; i < 16; ++i) {
            if ((bits >> i) & 1u) { acc[i].x += y.x; acc[i].y += y.y; }
        }
    }
    int c = c0 + c2 * 2;
    float2 bbv = *(const float2*)(b0 + c);
#pragma unroll
    for (int i = 0; i < 16; ++i) {
        int j = ty * 16 + i;
        float2 root = *(const float2*)(g_Y + (size_t)(b * 128 + j) * 512 + 256 + c);
        float2 o;
        o.x = fmaxf(acc[i].x + root.x + bbv.x, 0.f);
        o.y = fmaxf(acc[i].y + root.y + bbv.y, 0.f);
        *(float2*)(g_h0 + (size_t)(b * 128 + j) * 256 + c) = o;
    }
}

// ---------------- kernel 3: r1 = A[:,n]^T @ h0 ; gather h0_n ------------------
__global__ __launch_bounds__(256) void k_row(const int* __restrict__ adj,
                                             const int* __restrict__ num_nodes)
{
    __shared__ unsigned colw[4];
    __shared__ int sn;
    int b = blockIdx.x, tid = threadIdx.x;
    if (tid == 0) sn = num_nodes[b];
    __syncthreads();
    int n = sn;
    if (tid < 128) {
        int pred = adj[((size_t)b * 128 + tid) * 128 + n] != 0;
        unsigned m = __ballot_sync(0xffffffffu, pred);
        if ((tid & 31) == 0) colw[tid >> 5] = m;
    }
    __syncthreads();
    if (tid == 0) {
        colw[n >> 5] |= 1u << (n & 31);
        if (n > 0) colw[(n - 1) >> 5] |= 1u << ((n - 1) & 31);
    }
    __syncthreads();
    float acc = 0.f;
#pragma unroll
    for (int w = 0; w < 4; ++w) {
        unsigned bits = colw[w];
        while (bits) {
            int t = __ffs(bits) - 1;
            bits &= bits - 1;
            acc += g_h0[(size_t)(b * 128 + w * 32 + t) * 256 + tid];
        }
    }
    g_rh[b * 512 + tid] = acc;
    g_rh[b * 512 + 256 + tid] = g_h0[(size_t)(b * 128 + n) * 256 + tid];
}

// ---------------- kernel 4: node_out = relu(rh @ [W1_rel;W1_root] + b1) -------
// M=256, N=1024, K=512; 64x64 tiles, 4x4 microtiles.
__global__ __launch_bounds__(256) void k_gemm1(const float* __restrict__ W1_rel,
                                               const float* __restrict__ W1_root,
                                               const float* __restrict__ b1)
{
    __shared__ float As[8][64];
    __shared__ float Bs[8][64];
    int tid = threadIdx.x;
    int n0 = blockIdx.x * 64, m0 = blockIdx.y * 64;
    int arow = tid >> 2, ak = (tid & 3) * 2;
    int bk = tid >> 5, bn = (tid & 31) * 2;
    int tx = tid & 15, ty = tid >> 4;

    float acc[4][4];
#pragma unroll
    for (int i = 0; i < 4; ++i)
#pragma unroll
        for (int j = 0; j < 4; ++j) acc[i][j] = 0.f;

    for (int kt = 0; kt < 512; kt += 8) {
        float2 av = *(const float2*)(g_rh + (m0 + arow) * 512 + kt + ak);
        const float* Wb = (kt < 256) ? (W1_rel + (size_t)kt * 1024)
                                     : (W1_root + (size_t)(kt - 256) * 1024);
        float2 bv = *(const float2*)(Wb + (size_t)bk * 1024 + n0 + bn);
        As[ak][arow] = av.x;
        As[ak + 1][arow] = av.y;
        *(float2*)&Bs[bk][bn] = bv;
        __syncthreads();
#pragma unroll
        for (int k = 0; k < 8; ++k) {
            float a[4], bb[4];
            *(float4*)a  = *(const float4*)&As[k][ty * 4];
            *(float4*)bb = *(const float4*)&Bs[k][tx * 4];
#pragma unroll
            for (int i = 0; i < 4; ++i)
#pragma unroll
                for (int j = 0; j < 4; ++j) acc[i][j] += a[i] * bb[j];
        }
        __syncthreads();
    }
#pragma unroll
    for (int i = 0; i < 4; ++i) {
        int row = m0 + ty * 4 + i;
#pragma unroll
        for (int j = 0; j < 4; ++j) {
            int col = n0 + tx * 4 + j;
            g_no[(size_t)row * 1024 + col] = fmaxf(acc[i][j] + b1[col], 0.f);
        }
    }
}

// ---------------- kernel 5: logits + value -----------------------------------
__global__ __launch_bounds__(256) void k_out(const float* __restrict__ Wl,
                                             const float* __restrict__ bl,
                                             const float* __restrict__ Wv,
                                             const float* __restrict__ bv,
                                             float* __restrict__ out, int out_size)
{
    int b = blockIdx.x;
    int w = threadIdx.x >> 5, lane = threadIdx.x & 31;
    const float* nb = g_no + (size_t)b * 1024;
    for (int o = w; o < 19; o += 8) {
        float acc = 0.f;
        if (o < 18) {
            for (int i = lane; i < 1024; i += 32) acc += nb[i] * Wl[i * 18 + o];
        } else {
            for (int i = lane; i < 1024; i += 32) acc += nb[i] * Wv[i];
        }
#pragma unroll
        for (int s = 16; s; s >>= 1) acc += __shfl_down_sync(0xffffffffu, acc, s);
        if (lane == 0) {
            if (o < 18) {
                int idx = b * NO + o;
                if (idx < out_size) out[idx] = acc + bl[o];
            } else {
                int idx = BB * NO + b;
                if (idx < out_size) out[idx] = acc + bv[0];
            }
        }
    }
}

// ---------------- launch ------------------------------------------------------
extern "C" void kernel_launch(void* const* d_in, const int* in_sizes, int n_in,
                              void* d_out, int out_size)
{
    const float* flat      = (const float*)d_in[0];
    const float* nodes     = (const float*)d_in[1];
    const int*   num_nodes = (const int*)d_in[2];
    const int*   adj       = (const int*)d_in[3];
    // d_in[4] = seq_lens (unused)
    const float* W0_rel  = (const float*)d_in[5];
    const float* b0      = (const float*)d_in[6];
    const float* W0_root = (const float*)d_in[7];
    const float* W1_rel  = (const float*)d_in[8];
    const float* b1      = (const float*)d_in[9];
    const float* W1_root = (const float*)d_in[10];
    const float* Wl      = (const float*)d_in[11];
    const float* bl      = (const float*)d_in[12];
    const float* Wv      = (const float*)d_in[13];
    const float* bv      = (const float*)d_in[14];
    float* out = (float*)d_out;

    k_rowptr<<<M_ROWS / 256, 256>>>(flat, nodes, num_nodes);
    k_gemm0<<<dim3(4, 256), 256>>>(W0_rel, W0_root);
    k_h0<<<dim3(4, BB), 256>>>(adj, num_nodes, b0);
    k_row<<<BB, 256>>>(adj, num_nodes);
    k_gemm1<<<dim3(16, 4), 256>>>(W1_rel, W1_root, b1);
    k_out<<<BB, 256>>>(Wl, bl, Wv, bv, out, out_size);
}

// round 5
// speedup vs baseline: 1.9715x; 1.9625x over previous
#include <cuda_runtime.h>
#include <cuda_bf16.h>
#include <cstdint>

#define GS 128
#define OBS 1024
#define HH 256
#define OUTD 1024
#define NO 18
#define BB 256
#define M_ROWS (BB * GS)   // 32768

// ---------------- scratch (device globals: no allocation allowed) -------------
__device__ float g_Y[(size_t)M_ROWS * 512];    // [B*GS][512] = [x@W0_rel | x@W0_root]
__device__ float g_h0[(size_t)M_ROWS * HH];    // [B*GS][256]
__device__ float g_rh[BB * 512];               // [r1 | h0_n] per batch
__device__ float g_no[BB * OUTD];              // node_out per batch
__device__ const float* g_rowptr[M_ROWS];      // gathered X row pointers
__device__ __nv_bfloat16 g_Wth[512 * 1024];    // Wt[n][k] = [W0_rel|W0_root]^T hi
__device__ __nv_bfloat16 g_Wtl[512 * 1024];    // lo split

// ---------------- helpers -----------------------------------------------------
__device__ __forceinline__ unsigned su32(const void* p) {
    return (unsigned)__cvta_generic_to_shared(p);
}
__device__ __forceinline__ float bfhi(float x) {
    return __bfloat162float(__float2bfloat16(x));
}
__device__ __forceinline__ unsigned pckbf(float a, float b) {
    return (unsigned)__bfloat16_as_ushort(__float2bfloat16(a))
         | ((unsigned)__bfloat16_as_ushort(__float2bfloat16(b)) << 16);
}
#define STS8(addr, v) \
    asm volatile("st.shared.v2.u32 [%0], {%1, %2};" :: "r"(addr), "r"((v).x), "r"((v).y))
#define LDSM4(r0, r1, r2, r3, a) \
    asm volatile("ldmatrix.sync.aligned.m8n8.x4.shared.b16 {%0,%1,%2,%3}, [%4];" \
                 : "=r"(r0), "=r"(r1), "=r"(r2), "=r"(r3) : "r"(a))
#define LDSM2(r0, r1, a) \
    asm volatile("ldmatrix.sync.aligned.m8n8.x2.shared.b16 {%0,%1}, [%2];" \
                 : "=r"(r0), "=r"(r1) : "r"(a))

__device__ __forceinline__ void mma_bf16(float* c, const unsigned* a, const unsigned* b) {
    asm volatile(
        "mma.sync.aligned.m16n8k16.row.col.f32.bf16.bf16.f32 "
        "{%0,%1,%2,%3}, {%4,%5,%6,%7}, {%8,%9}, {%0,%1,%2,%3};"
        : "+f"(c[0]), "+f"(c[1]), "+f"(c[2]), "+f"(c[3])
        : "r"(a[0]), "r"(a[1]), "r"(a[2]), "r"(a[3]), "r"(b[0]), "r"(b[1]));
}

// ---------------- kernel 0: build X row pointer table ------------------------
__global__ void k_rowptr(const float* __restrict__ flat,
                         const float* __restrict__ nodes,
                         const int* __restrict__ num_nodes)
{
    int r = blockIdx.x * blockDim.x + threadIdx.x;
    if (r >= M_ROWS) return;
    int b = r >> 7, j = r & 127;
    g_rowptr[r] = (j == num_nodes[b]) ? (flat + (size_t)b * OBS)
                                      : (nodes + (size_t)r * OBS);
}

// ---------------- kernel 0b: transpose + hi/lo bf16 split of [W0_rel|W0_root]
__global__ void k_wsplit(const float* __restrict__ W0_rel,
                         const float* __restrict__ W0_root)
{
    __shared__ float tile[32][33];
    int kb = blockIdx.x * 32, nb = blockIdx.y * 32;
    int tx = threadIdx.x, ty = threadIdx.y;  // (32, 8)
#pragma unroll
    for (int j = 0; j < 32; j += 8) {
        int k = kb + ty + j, n = nb + tx;
        float v = (n < 256) ? W0_rel[(size_t)k * 256 + n]
                            : W0_root[(size_t)k * 256 + (n - 256)];
        tile[ty + j][tx] = v;
    }
    __syncthreads();
#pragma unroll
    for (int j = 0; j < 32; j += 8) {
        int n = nb + ty + j, k = kb + tx;
        float v = tile[tx][ty + j];
        float h = bfhi(v);
        g_Wth[(size_t)n * 1024 + k] = __float2bfloat16(h);
        g_Wtl[(size_t)n * 1024 + k] = __float2bfloat16(v - h);
    }
}

// ---------------- kernel 1: Y = X @ Wt^T via mma.sync bf16 hi/lo --------------
// CTA tile 128(m) x 128(n), K chunks of 64, double-buffered smem.
// smem row stride: 72 bf16 = 144 B (conflict-free for ldmatrix).
#define RS 72
#define ABYTES (128 * RS * 2)          // 18432 per split
#define BUFBYTES (4 * ABYTES)          // Ah|Al|Bh|Bl = 73728
#define SMEM_DYN (2 * BUFBYTES)        // 147456

__global__ __launch_bounds__(256) void k_gemm0_mma()
{
    extern __shared__ char dynsmem[];
    unsigned sm = su32(dynsmem);
    int tid = threadIdx.x, lane = tid & 31, wid = tid >> 5;
    int wm = wid >> 2, wn = wid & 3;               // warp tile: 64m x 32n
    int m0 = blockIdx.y * 128, n0 = blockIdx.x * 128;

    // ---- per-thread load geometry (constant across chunks) ----
    const float* rp[8];
    int a_c4[8], a_sts[8];
    int b_off[8], b_sts[8];
#pragma unroll
    for (int i = 0; i < 8; ++i) {
        int f = i * 256 + tid;                     // float4 slot 0..2047
        int row = f >> 4, c4 = f & 15;             // 128 rows x 16 float4
        rp[i] = g_rowptr[m0 + row];
        a_c4[i] = c4 * 4;
        a_sts[i] = row * (RS * 2) + c4 * 8;        // byte offset in A split
        // B: same slot shape, uint2 (4 bf16) granules
        b_off[i] = (n0 + row) * 1024 + c4 * 4;     // element offset in g_Wt*
        b_sts[i] = row * (RS * 2) + c4 * 8;
    }

    // ---- ldmatrix base offsets ----
    int a_ld = (wm * 64 + (lane & 15)) * (RS * 2) + (lane >> 4) * 16;
    int b_ld = (wn * 32 + (lane & 7)) * (RS * 2) + ((lane >> 3) & 1) * 16;

    float acc[4][4][4];
#pragma unroll
    for (int mt = 0; mt < 4; ++mt)
#pragma unroll
        for (int nt = 0; nt < 4; ++nt)
#pragma unroll
            for (int r = 0; r < 4; ++r) acc[mt][nt][r] = 0.f;

    float4 areg[8];
    uint2 bhreg[8], blreg[8];

    // ---- prologue: stage chunk 0 ----
#pragma unroll
    for (int i = 0; i < 8; ++i) {
        areg[i] = *(const float4*)(rp[i] + a_c4[i]);
        bhreg[i] = *(const uint2*)(g_Wth + b_off[i]);
        blreg[i] = *(const uint2*)(g_Wtl + b_off[i]);
    }
#pragma unroll
    for (int i = 0; i < 8; ++i) {
        float4 v = areg[i];
        float h0f = bfhi(v.x), h1f = bfhi(v.y), h2f = bfhi(v.z), h3f = bfhi(v.w);
        uint2 hv = make_uint2(pckbf(h0f, h1f), pckbf(h2f, h3f));
        uint2 lv = make_uint2(pckbf(v.x - h0f, v.y - h1f), pckbf(v.z - h2f, v.w - h3f));
        STS8(sm + a_sts[i], hv);
        STS8(sm + ABYTES + a_sts[i], lv);
        STS8(sm + 2 * ABYTES + b_sts[i], bhreg[i]);
        STS8(sm + 3 * ABYTES + b_sts[i], blreg[i]);
    }
    __syncthreads();

    for (int c = 0; c < 16; ++c) {
        int p = c & 1;
        unsigned base = sm + p * BUFBYTES;
        int ktn = (c + 1) * 64;
        if (c < 15) {   // issue next-chunk global loads early
#pragma unroll
            for (int i = 0; i < 8; ++i) {
                areg[i] = *(const float4*)(rp[i] + ktn + a_c4[i]);
                bhreg[i] = *(const uint2*)(g_Wth + b_off[i] + ktn);
                blreg[i] = *(const uint2*)(g_Wtl + b_off[i] + ktn);
            }
        }
        // ---- compute on buffer p ----
#pragma unroll
        for (int s = 0; s < 4; ++s) {
            unsigned ah[4][4], al[4][4], bh[4][2], bl[4][2];
#pragma unroll
            for (int mt = 0; mt < 4; ++mt) {
                unsigned aaddr = base + a_ld + mt * 16 * (RS * 2) + s * 32;
                LDSM4(ah[mt][0], ah[mt][1], ah[mt][2], ah[mt][3], aaddr);
                LDSM4(al[mt][0], al[mt][1], al[mt][2], al[mt][3], aaddr + ABYTES);
            }
#pragma unroll
            for (int nt = 0; nt < 4; ++nt) {
                unsigned baddr = base + 2 * ABYTES + b_ld + nt * 8 * (RS * 2) + s * 32;
                LDSM2(bh[nt][0], bh[nt][1], baddr);
                LDSM2(bl[nt][0], bl[nt][1], baddr + ABYTES);
            }
#pragma unroll
            for (int mt = 0; mt < 4; ++mt)
#pragma unroll
                for (int nt = 0; nt < 4; ++nt) {
                    mma_bf16(acc[mt][nt], ah[mt], bh[nt]);
                    mma_bf16(acc[mt][nt], ah[mt], bl[nt]);
                    mma_bf16(acc[mt][nt], al[mt], bh[nt]);
                }
        }
        if (c < 15) {   // stage next chunk into the other buffer
            unsigned nb = sm + (p ^ 1) * BUFBYTES;
#pragma unroll
            for (int i = 0; i < 8; ++i) {
                float4 v = areg[i];
                float h0f = bfhi(v.x), h1f = bfhi(v.y), h2f = bfhi(v.z), h3f = bfhi(v.w);
                uint2 hv = make_uint2(pckbf(h0f, h1f), pckbf(h2f, h3f));
                uint2 lv = make_uint2(pckbf(v.x - h0f, v.y - h1f),
                                      pckbf(v.z - h2f, v.w - h3f));
                STS8(nb + a_sts[i], hv);
                STS8(nb + ABYTES + a_sts[i], lv);
                STS8(nb + 2 * ABYTES + b_sts[i], bhreg[i]);
                STS8(nb + 3 * ABYTES + b_sts[i], blreg[i]);
            }
        }
        __syncthreads();
    }

    // ---- epilogue: write accumulators to g_Y ----
#pragma unroll
    for (int mt = 0; mt < 4; ++mt) {
        int m = m0 + wm * 64 + mt * 16 + (lane >> 2);
#pragma unroll
        for (int nt = 0; nt < 4; ++nt) {
            int n = n0 + wn * 32 + nt * 8 + (lane & 3) * 2;
            *(float2*)(g_Y + (size_t)m * 512 + n) =
                make_float2(acc[mt][nt][0], acc[mt][nt][1]);
            *(float2*)(g_Y + (size_t)(m + 8) * 512 + n) =
                make_float2(acc[mt][nt][2], acc[mt][nt][3]);
        }
    }
}

// ---------------- kernel 2: h0 = relu(A^T @ Yrel + b0 + Yroot) ----------------
__global__ __launch_bounds__(256) void k_h0(const int* __restrict__ adj,
                                            const int* __restrict__ num_nodes,
                                            const float* __restrict__ b0)
{
    __shared__ float2 Ysh[128][32];
    __shared__ unsigned bitw[128][4];
    int b = blockIdx.y;
    int c0 = blockIdx.x * 64;
    int tid = threadIdx.x;
    int c2 = tid & 31, ty = tid >> 5;

#pragma unroll
    for (int r = 0; r < 8; ++r) {
        int fi = r * 256 + tid;
        int k = fi >> 4;
        int c4 = (fi & 15) * 4;
        float4 v = *(const float4*)(g_Y + (size_t)(b * 128 + k) * 512 + c0 + c4);
        float2* dst = &Ysh[k][c4 >> 1];
        dst[0] = make_float2(v.x, v.y);
        dst[1] = make_float2(v.z, v.w);
    }
    const int* adjb = adj + (size_t)b * GS * GS;
#pragma unroll 4
    for (int it = 0; it < 64; ++it) {
        int idx = it * 256 + tid;
        unsigned m = __ballot_sync(0xffffffffu, adjb[idx] != 0);
        if ((tid & 31) == 0) bitw[idx >> 7][(idx & 127) >> 5] = m;
    }
    __syncthreads();
    if (tid == 0) {
        int n = num_nodes[b];
        bitw[n][n >> 5] |= 1u << (n & 31);
        if (n > 0) {
            bitw[n][(n - 1) >> 5] |= 1u << ((n - 1) & 31);
            bitw[n - 1][n >> 5] |= 1u << (n & 31);
        }
    }
    __syncthreads();

    float2 acc[16];
#pragma unroll
    for (int i = 0; i < 16; ++i) acc[i] = make_float2(0.f, 0.f);

    for (int k = 0; k < 128; ++k) {
        float2 y = Ysh[k][c2];
        unsigned bits = bitw[k][ty >> 1] >> ((ty & 1) * 16);
#pragma unroll
        for (int i = 0; i < 16; ++i) {
            if ((bits >> i) & 1u) { acc[i].x += y.x; acc[i].y += y.y; }
        }
    }
    int c = c0 + c2 * 2;
    float2 bbv = *(const float2*)(b0 + c);
#pragma unroll
    for (int i = 0; i < 16; ++i) {
        int j = ty * 16 + i;
        float2 root = *(const float2*)(g_Y + (size_t)(b * 128 + j) * 512 + 256 + c);
        float2 o;
        o.x = fmaxf(acc[i].x + root.x + bbv.x, 0.f);
        o.y = fmaxf(acc[i].y + root.y + bbv.y, 0.f);
        *(float2*)(g_h0 + (size_t)(b * 128 + j) * 256 + c) = o;
    }
}

// ---------------- kernel 3: r1 = A[:,n]^T @ h0 ; gather h0_n ------------------
__global__ __launch_bounds__(256) void k_row(const int* __restrict__ adj,
                                             const int* __restrict__ num_nodes)
{
    __shared__ unsigned colw[4];
    __shared__ int sn;
    int b = blockIdx.x, tid = threadIdx.x;
    if (tid == 0) sn = num_nodes[b];
    __syncthreads();
    int n = sn;
    if (tid < 128) {
        int pred = adj[((size_t)b * 128 + tid) * 128 + n] != 0;
        unsigned m = __ballot_sync(0xffffffffu, pred);
        if ((tid & 31) == 0) colw[tid >> 5] = m;
    }
    __syncthreads();
    if (tid == 0) {
        colw[n >> 5] |= 1u << (n & 31);
        if (n > 0) colw[(n - 1) >> 5] |= 1u << ((n - 1) & 31);
    }
    __syncthreads();
    float acc = 0.f;
#pragma unroll
    for (int w = 0; w < 4; ++w) {
        unsigned bits = colw[w];
        while (bits) {
            int t = __ffs(bits) - 1;
            bits &= bits - 1;
            acc += g_h0[(size_t)(b * 128 + w * 32 + t) * 256 + tid];
        }
    }
    g_rh[b * 512 + tid] = acc;
    g_rh[b * 512 + 256 + tid] = g_h0[(size_t)(b * 128 + n) * 256 + tid];
}

// ---------------- kernel 4: node_out = relu(rh @ [W1_rel;W1_root] + b1) -------
__global__ __launch_bounds__(256) void k_gemm1(const float* __restrict__ W1_rel,
                                               const float* __restrict__ W1_root,
                                               const float* __restrict__ b1)
{
    __shared__ float As[8][64];
    __shared__ float Bs[8][64];
    int tid = threadIdx.x;
    int n0 = blockIdx.x * 64, m0 = blockIdx.y * 64;
    int arow = tid >> 2, ak = (tid & 3) * 2;
    int bk = tid >> 5, bn = (tid & 31) * 2;
    int tx = tid & 15, ty = tid >> 4;

    float acc[4][4];
#pragma unroll
    for (int i = 0; i < 4; ++i)
#pragma unroll
        for (int j = 0; j < 4; ++j) acc[i][j] = 0.f;

    for (int kt = 0; kt < 512; kt += 8) {
        float2 av = *(const float2*)(g_rh + (m0 + arow) * 512 + kt + ak);
        const float* Wb = (kt < 256) ? (W1_rel + (size_t)kt * 1024)
                                     : (W1_root + (size_t)(kt - 256) * 1024);
        float2 bv = *(const float2*)(Wb + (size_t)bk * 1024 + n0 + bn);
        As[ak][arow] = av.x;
        As[ak + 1][arow] = av.y;
        *(float2*)&Bs[bk][bn] = bv;
        __syncthreads();
#pragma unroll
        for (int k = 0; k < 8; ++k) {
            float a[4], bb[4];
            *(float4*)a  = *(const float4*)&As[k][ty * 4];
            *(float4*)bb = *(const float4*)&Bs[k][tx * 4];
#pragma unroll
            for (int i = 0; i < 4; ++i)
#pragma unroll
                for (int j = 0; j < 4; ++j) acc[i][j] += a[i] * bb[j];
        }
        __syncthreads();
    }
#pragma unroll
    for (int i = 0; i < 4; ++i) {
        int row = m0 + ty * 4 + i;
#pragma unroll
        for (int j = 0; j < 4; ++j) {
            int col = n0 + tx * 4 + j;
            g_no[(size_t)row * 1024 + col] = fmaxf(acc[i][j] + b1[col], 0.f);
        }
    }
}

// ---------------- kernel 5: logits + value -----------------------------------
__global__ __launch_bounds__(256) void k_out(const float* __restrict__ Wl,
                                             const float* __restrict__ bl,
                                             const float* __restrict__ Wv,
                                             const float* __restrict__ bv,
                                             float* __restrict__ out, int out_size)
{
    int b = blockIdx.x;
    int w = threadIdx.x >> 5, lane = threadIdx.x & 31;
    const float* nb = g_no + (size_t)b * 1024;
    for (int o = w; o < 19; o += 8) {
        float acc = 0.f;
        if (o < 18) {
            for (int i = lane; i < 1024; i += 32) acc += nb[i] * Wl[i * 18 + o];
        } else {
            for (int i = lane; i < 1024; i += 32) acc += nb[i] * Wv[i];
        }
#pragma unroll
        for (int s = 16; s; s >>= 1) acc += __shfl_down_sync(0xffffffffu, acc, s);
        if (lane == 0) {
            if (o < 18) {
                int idx = b * NO + o;
                if (idx < out_size) out[idx] = acc + bl[o];
            } else {
                int idx = BB * NO + b;
                if (idx < out_size) out[idx] = acc + bv[0];
            }
        }
    }
}

// ---------------- launch ------------------------------------------------------
extern "C" void kernel_launch(void* const* d_in, const int* in_sizes, int n_in,
                              void* d_out, int out_size)
{
    const float* flat      = (const float*)d_in[0];
    const float* nodes     = (const float*)d_in[1];
    const int*   num_nodes = (const int*)d_in[2];
    const int*   adj       = (const int*)d_in[3];
    // d_in[4] = seq_lens (unused)
    const float* W0_rel  = (const float*)d_in[5];
    const float* b0      = (const float*)d_in[6];
    const float* W0_root = (const float*)d_in[7];
    const float* W1_rel  = (const float*)d_in[8];
    const float* b1      = (const float*)d_in[9];
    const float* W1_root = (const float*)d_in[10];
    const float* Wl      = (const float*)d_in[11];
    const float* bl      = (const float*)d_in[12];
    const float* Wv      = (const float*)d_in[13];
    const float* bv      = (const float*)d_in[14];
    float* out = (float*)d_out;

    static int s_attr_done = 0;
    if (!s_attr_done) {
        cudaFuncSetAttribute(k_gemm0_mma,
                             cudaFuncAttributeMaxDynamicSharedMemorySize, SMEM_DYN);
        s_attr_done = 1;
    }

    k_rowptr<<<M_ROWS / 256, 256>>>(flat, nodes, num_nodes);
    k_wsplit<<<dim3(32, 16), dim3(32, 8)>>>(W0_rel, W0_root);
    k_gemm0_mma<<<dim3(4, 256), 256, SMEM_DYN>>>();
    k_h0<<<dim3(4, BB), 256>>>(adj, num_nodes, b0);
    k_row<<<BB, 256>>>(adj, num_nodes);
    k_gemm1<<<dim3(16, 4), 256>>>(W1_rel, W1_root, b1);
    k_out<<<BB, 256>>>(Wl, bl, Wv, bv, out, out_size);
}

// round 6
// speedup vs baseline: 2.1165x; 1.0736x over previous
#include <cuda_runtime.h>
#include <cuda_bf16.h>
#include <cstdint>

#define GS 128
#define OBS 1024
#define HH 256
#define OUTD 1024
#define NO 18
#define BB 256
#define M_ROWS (BB * GS)   // 32768

// ---------------- scratch (device globals: no allocation allowed) -------------
__device__ float g_Y[(size_t)M_ROWS * 512];    // [B*GS][512] = [x@W0_rel | x@W0_root]
__device__ float g_rh[BB * 512];               // [r1 | h0_n] per batch
__device__ float g_no[BB * OUTD];              // node_out per batch
__device__ const float* g_rowptr[M_ROWS];      // gathered X row pointers
__device__ __nv_bfloat16 g_Wth[512 * 1024];    // Wt[n][k] = [W0_rel|W0_root]^T hi
__device__ __nv_bfloat16 g_Wtl[512 * 1024];    // lo split

// ---------------- helpers -----------------------------------------------------
__device__ __forceinline__ unsigned su32(const void* p) {
    return (unsigned)__cvta_generic_to_shared(p);
}
__device__ __forceinline__ float bfhi(float x) {
    return __bfloat162float(__float2bfloat16(x));
}
__device__ __forceinline__ unsigned pckbf(float a, float b) {
    return (unsigned)__bfloat16_as_ushort(__float2bfloat16(a))
         | ((unsigned)__bfloat16_as_ushort(__float2bfloat16(b)) << 16);
}
#define STS8(addr, v) \
    asm volatile("st.shared.v2.u32 [%0], {%1, %2};" :: "r"(addr), "r"((v).x), "r"((v).y))
#define LDSM4(r0, r1, r2, r3, a) \
    asm volatile("ldmatrix.sync.aligned.m8n8.x4.shared.b16 {%0,%1,%2,%3}, [%4];" \
                 : "=r"(r0), "=r"(r1), "=r"(r2), "=r"(r3) : "r"(a))
#define LDSM2(r0, r1, a) \
    asm volatile("ldmatrix.sync.aligned.m8n8.x2.shared.b16 {%0,%1}, [%2];" \
                 : "=r"(r0), "=r"(r1) : "r"(a))

__device__ __forceinline__ void mma_bf16(float* c, const unsigned* a, const unsigned* b) {
    asm volatile(
        "mma.sync.aligned.m16n8k16.row.col.f32.bf16.bf16.f32 "
        "{%0,%1,%2,%3}, {%4,%5,%6,%7}, {%8,%9}, {%0,%1,%2,%3};"
        : "+f"(c[0]), "+f"(c[1]), "+f"(c[2]), "+f"(c[3])
        : "r"(a[0]), "r"(a[1]), "r"(a[2]), "r"(a[3]), "r"(b[0]), "r"(b[1]));
}

// ---------------- kernel 0: build X row pointer table ------------------------
__global__ void k_rowptr(const float* __restrict__ flat,
                         const float* __restrict__ nodes,
                         const int* __restrict__ num_nodes)
{
    int r = blockIdx.x * blockDim.x + threadIdx.x;
    if (r >= M_ROWS) return;
    int b = r >> 7, j = r & 127;
    g_rowptr[r] = (j == num_nodes[b]) ? (flat + (size_t)b * OBS)
                                      : (nodes + (size_t)r * OBS);
}

// ---------------- kernel 0b: transpose + hi/lo bf16 split of [W0_rel|W0_root]
__global__ void k_wsplit(const float* __restrict__ W0_rel,
                         const float* __restrict__ W0_root)
{
    __shared__ float tile[32][33];
    int kb = blockIdx.x * 32, nb = blockIdx.y * 32;
    int tx = threadIdx.x, ty = threadIdx.y;  // (32, 8)
#pragma unroll
    for (int j = 0; j < 32; j += 8) {
        int k = kb + ty + j, n = nb + tx;
        float v = (n < 256) ? W0_rel[(size_t)k * 256 + n]
                            : W0_root[(size_t)k * 256 + (n - 256)];
        tile[ty + j][tx] = v;
    }
    __syncthreads();
#pragma unroll
    for (int j = 0; j < 32; j += 8) {
        int n = nb + ty + j, k = kb + tx;
        float v = tile[tx][ty + j];
        float h = bfhi(v);
        g_Wth[(size_t)n * 1024 + k] = __float2bfloat16(h);
        g_Wtl[(size_t)n * 1024 + k] = __float2bfloat16(v - h);
    }
}

// ---------------- kernel 1: Y = X @ Wt^T via mma.sync bf16 hi/lo --------------
// CTA tile 128(m) x 128(n), K chunks of 64, double-buffered smem.
#define RS 72
#define ABYTES (128 * RS * 2)          // 18432 per split
#define BUFBYTES (4 * ABYTES)          // Ah|Al|Bh|Bl = 73728
#define SMEM_DYN (2 * BUFBYTES)        // 147456

__global__ __launch_bounds__(256) void k_gemm0_mma()
{
    extern __shared__ char dynsmem[];
    unsigned sm = su32(dynsmem);
    int tid = threadIdx.x, lane = tid & 31, wid = tid >> 5;
    int wm = wid >> 2, wn = wid & 3;               // warp tile: 64m x 32n
    int m0 = blockIdx.y * 128, n0 = blockIdx.x * 128;

    const float* rp[8];
    int a_c4[8], a_sts[8];
    int b_off[8], b_sts[8];
#pragma unroll
    for (int i = 0; i < 8; ++i) {
        int f = i * 256 + tid;
        int row = f >> 4, c4 = f & 15;
        rp[i] = g_rowptr[m0 + row];
        a_c4[i] = c4 * 4;
        a_sts[i] = row * (RS * 2) + c4 * 8;
        b_off[i] = (n0 + row) * 1024 + c4 * 4;
        b_sts[i] = row * (RS * 2) + c4 * 8;
    }

    int a_ld = (wm * 64 + (lane & 15)) * (RS * 2) + (lane >> 4) * 16;
    int b_ld = (wn * 32 + (lane & 7)) * (RS * 2) + ((lane >> 3) & 1) * 16;

    float acc[4][4][4];
#pragma unroll
    for (int mt = 0; mt < 4; ++mt)
#pragma unroll
        for (int nt = 0; nt < 4; ++nt)
#pragma unroll
            for (int r = 0; r < 4; ++r) acc[mt][nt][r] = 0.f;

    float4 areg[8];
    uint2 bhreg[8], blreg[8];

#pragma unroll
    for (int i = 0; i < 8; ++i) {
        areg[i] = *(const float4*)(rp[i] + a_c4[i]);
        bhreg[i] = *(const uint2*)(g_Wth + b_off[i]);
        blreg[i] = *(const uint2*)(g_Wtl + b_off[i]);
    }
#pragma unroll
    for (int i = 0; i < 8; ++i) {
        float4 v = areg[i];
        float h0f = bfhi(v.x), h1f = bfhi(v.y), h2f = bfhi(v.z), h3f = bfhi(v.w);
        uint2 hv = make_uint2(pckbf(h0f, h1f), pckbf(h2f, h3f));
        uint2 lv = make_uint2(pckbf(v.x - h0f, v.y - h1f), pckbf(v.z - h2f, v.w - h3f));
        STS8(sm + a_sts[i], hv);
        STS8(sm + ABYTES + a_sts[i], lv);
        STS8(sm + 2 * ABYTES + b_sts[i], bhreg[i]);
        STS8(sm + 3 * ABYTES + b_sts[i], blreg[i]);
    }
    __syncthreads();

    for (int c = 0; c < 16; ++c) {
        int p = c & 1;
        unsigned base = sm + p * BUFBYTES;
        int ktn = (c + 1) * 64;
        if (c < 15) {
#pragma unroll
            for (int i = 0; i < 8; ++i) {
                areg[i] = *(const float4*)(rp[i] + ktn + a_c4[i]);
                bhreg[i] = *(const uint2*)(g_Wth + b_off[i] + ktn);
                blreg[i] = *(const uint2*)(g_Wtl + b_off[i] + ktn);
            }
        }
#pragma unroll
        for (int s = 0; s < 4; ++s) {
            unsigned ah[4][4], al[4][4], bh[4][2], bl[4][2];
#pragma unroll
            for (int mt = 0; mt < 4; ++mt) {
                unsigned aaddr = base + a_ld + mt * 16 * (RS * 2) + s * 32;
                LDSM4(ah[mt][0], ah[mt][1], ah[mt][2], ah[mt][3], aaddr);
                LDSM4(al[mt][0], al[mt][1], al[mt][2], al[mt][3], aaddr + ABYTES);
            }
#pragma unroll
            for (int nt = 0; nt < 4; ++nt) {
                unsigned baddr = base + 2 * ABYTES + b_ld + nt * 8 * (RS * 2) + s * 32;
                LDSM2(bh[nt][0], bh[nt][1], baddr);
                LDSM2(bl[nt][0], bl[nt][1], baddr + ABYTES);
            }
#pragma unroll
            for (int mt = 0; mt < 4; ++mt)
#pragma unroll
                for (int nt = 0; nt < 4; ++nt) {
                    mma_bf16(acc[mt][nt], ah[mt], bh[nt]);
                    mma_bf16(acc[mt][nt], ah[mt], bl[nt]);
                    mma_bf16(acc[mt][nt], al[mt], bh[nt]);
                }
        }
        if (c < 15) {
            unsigned nb = sm + (p ^ 1) * BUFBYTES;
#pragma unroll
            for (int i = 0; i < 8; ++i) {
                float4 v = areg[i];
                float h0f = bfhi(v.x), h1f = bfhi(v.y), h2f = bfhi(v.z), h3f = bfhi(v.w);
                uint2 hv = make_uint2(pckbf(h0f, h1f), pckbf(h2f, h3f));
                uint2 lv = make_uint2(pckbf(v.x - h0f, v.y - h1f),
                                      pckbf(v.z - h2f, v.w - h3f));
                STS8(nb + a_sts[i], hv);
                STS8(nb + ABYTES + a_sts[i], lv);
                STS8(nb + 2 * ABYTES + b_sts[i], bhreg[i]);
                STS8(nb + 3 * ABYTES + b_sts[i], blreg[i]);
            }
        }
        __syncthreads();
    }

#pragma unroll
    for (int mt = 0; mt < 4; ++mt) {
        int m = m0 + wm * 64 + mt * 16 + (lane >> 2);
#pragma unroll
        for (int nt = 0; nt < 4; ++nt) {
            int n = n0 + wn * 32 + nt * 8 + (lane & 3) * 2;
            *(float2*)(g_Y + (size_t)m * 512 + n) =
                make_float2(acc[mt][nt][0], acc[mt][nt][1]);
            *(float2*)(g_Y + (size_t)(m + 8) * 512 + n) =
                make_float2(acc[mt][nt][2], acc[mt][nt][3]);
        }
    }
}

// ---------------- kernel 2: fused h0 + masked column-reduce -------------------
// h0 = relu(A^T @ Yrel + b0 + Yroot); r1[c] = sum_{j: A[j][n]!=0} h0[j][c];
// also grabs h0[n][c]. No h0 matrix is materialized.
__global__ __launch_bounds__(256) void k_h0row(const int* __restrict__ adj,
                                               const int* __restrict__ num_nodes,
                                               const float* __restrict__ b0)
{
    __shared__ float2 Ysh[128][32];      // 32 KB; reused as reduction scratch
    __shared__ unsigned bitw[128][4];
    __shared__ int s_n;
    int b = blockIdx.y;
    int c0 = blockIdx.x * 64;
    int tid = threadIdx.x;
    int c2 = tid & 31, ty = tid >> 5;

#pragma unroll
    for (int r = 0; r < 8; ++r) {
        int fi = r * 256 + tid;
        int k = fi >> 4;
        int c4 = (fi & 15) * 4;
        float4 v = *(const float4*)(g_Y + (size_t)(b * 128 + k) * 512 + c0 + c4);
        float2* dst = &Ysh[k][c4 >> 1];
        dst[0] = make_float2(v.x, v.y);
        dst[1] = make_float2(v.z, v.w);
    }
    const int* adjb = adj + (size_t)b * GS * GS;
#pragma unroll 4
    for (int it = 0; it < 64; ++it) {
        int idx = it * 256 + tid;
        unsigned m = __ballot_sync(0xffffffffu, adjb[idx] != 0);
        if ((tid & 31) == 0) bitw[idx >> 7][(idx & 127) >> 5] = m;
    }
    __syncthreads();
    if (tid == 0) {
        int n = num_nodes[b];
        s_n = n;
        bitw[n][n >> 5] |= 1u << (n & 31);
        if (n > 0) {
            bitw[n][(n - 1) >> 5] |= 1u << ((n - 1) & 31);
            bitw[n - 1][n >> 5] |= 1u << (n & 31);
        }
    }
    __syncthreads();

    float2 acc[16];
#pragma unroll
    for (int i = 0; i < 16; ++i) acc[i] = make_float2(0.f, 0.f);

    for (int k = 0; k < 128; ++k) {
        float2 y = Ysh[k][c2];
        unsigned bits = bitw[k][ty >> 1] >> ((ty & 1) * 16);
#pragma unroll
        for (int i = 0; i < 16; ++i) {
            if ((bits >> i) & 1u) { acc[i].x += y.x; acc[i].y += y.y; }
        }
    }

    int n = s_n;
    int c = c0 + c2 * 2;
    float2 bbv = *(const float2*)(b0 + c);
    float2 r1 = make_float2(0.f, 0.f);
    // per-row "is j a neighbor of n" bits, for j in this thread's 16 rows
#pragma unroll
    for (int i = 0; i < 16; ++i) {
        int j = ty * 16 + i;
        float2 root = *(const float2*)(g_Y + (size_t)(b * 128 + j) * 512 + 256 + c);
        float2 o;
        o.x = fmaxf(acc[i].x + root.x + bbv.x, 0.f);
        o.y = fmaxf(acc[i].y + root.y + bbv.y, 0.f);
        if ((bitw[j][n >> 5] >> (n & 31)) & 1u) { r1.x += o.x; r1.y += o.y; }
        if (j == n) *(float2*)(g_rh + b * 512 + 256 + c) = o;
    }
    __syncthreads();                 // Ysh reads done; reuse as scratch
    float2* part = (float2*)Ysh;     // [8][32]
    part[ty * 32 + c2] = r1;
    __syncthreads();
    if (tid < 32) {
        float2 s = part[tid];
#pragma unroll
        for (int w = 1; w < 8; ++w) {
            float2 v = part[w * 32 + tid];
            s.x += v.x; s.y += v.y;
        }
        *(float2*)(g_rh + b * 512 + c0 + tid * 2) = s;
    }
}

// ---------------- kernel 4: node_out = relu(rh @ [W1_rel;W1_root] + b1) -------
__global__ __launch_bounds__(256) void k_gemm1(const float* __restrict__ W1_rel,
                                               const float* __restrict__ W1_root,
                                               const float* __restrict__ b1)
{
    __shared__ float As[8][64];
    __shared__ float Bs[8][64];
    int tid = threadIdx.x;
    int n0 = blockIdx.x * 64, m0 = blockIdx.y * 64;
    int arow = tid >> 2, ak = (tid & 3) * 2;
    int bk = tid >> 5, bn = (tid & 31) * 2;
    int tx = tid & 15, ty = tid >> 4;

    float acc[4][4];
#pragma unroll
    for (int i = 0; i < 4; ++i)
#pragma unroll
        for (int j = 0; j < 4; ++j) acc[i][j] = 0.f;

    for (int kt = 0; kt < 512; kt += 8) {
        float2 av = *(const float2*)(g_rh + (m0 + arow) * 512 + kt + ak);
        const float* Wb = (kt < 256) ? (W1_rel + (size_t)kt * 1024)
                                     : (W1_root + (size_t)(kt - 256) * 1024);
        float2 bv = *(const float2*)(Wb + (size_t)bk * 1024 + n0 + bn);
        As[ak][arow] = av.x;
        As[ak + 1][arow] = av.y;
        *(float2*)&Bs[bk][bn] = bv;
        __syncthreads();
#pragma unroll
        for (int k = 0; k < 8; ++k) {
            float a[4], bb[4];
            *(float4*)a  = *(const float4*)&As[k][ty * 4];
            *(float4*)bb = *(const float4*)&Bs[k][tx * 4];
#pragma unroll
            for (int i = 0; i < 4; ++i)
#pragma unroll
                for (int j = 0; j < 4; ++j) acc[i][j] += a[i] * bb[j];
        }
        __syncthreads();
    }
#pragma unroll
    for (int i = 0; i < 4; ++i) {
        int row = m0 + ty * 4 + i;
#pragma unroll
        for (int j = 0; j < 4; ++j) {
            int col = n0 + tx * 4 + j;
            g_no[(size_t)row * 1024 + col] = fmaxf(acc[i][j] + b1[col], 0.f);
        }
    }
}

// ---------------- kernel 5: logits + value -----------------------------------
__global__ __launch_bounds__(256) void k_out(const float* __restrict__ Wl,
                                             const float* __restrict__ bl,
                                             const float* __restrict__ Wv,
                                             const float* __restrict__ bv,
                                             float* __restrict__ out, int out_size)
{
    int b = blockIdx.x;
    int w = threadIdx.x >> 5, lane = threadIdx.x & 31;
    const float* nb = g_no + (size_t)b * 1024;
    for (int o = w; o < 19; o += 8) {
        float acc = 0.f;
        if (o < 18) {
            for (int i = lane; i < 1024; i += 32) acc += nb[i] * Wl[i * 18 + o];
        } else {
            for (int i = lane; i < 1024; i += 32) acc += nb[i] * Wv[i];
        }
#pragma unroll
        for (int s = 16; s; s >>= 1) acc += __shfl_down_sync(0xffffffffu, acc, s);
        if (lane == 0) {
            if (o < 18) {
                int idx = b * NO + o;
                if (idx < out_size) out[idx] = acc + bl[o];
            } else {
                int idx = BB * NO + b;
                if (idx < out_size) out[idx] = acc + bv[0];
            }
        }
    }
}

// ---------------- launch ------------------------------------------------------
extern "C" void kernel_launch(void* const* d_in, const int* in_sizes, int n_in,
                              void* d_out, int out_size)
{
    const float* flat      = (const float*)d_in[0];
    const float* nodes     = (const float*)d_in[1];
    const int*   num_nodes = (const int*)d_in[2];
    const int*   adj       = (const int*)d_in[3];
    // d_in[4] = seq_lens (unused)
    const float* W0_rel  = (const float*)d_in[5];
    const float* b0      = (const float*)d_in[6];
    const float* W0_root = (const float*)d_in[7];
    const float* W1_rel  = (const float*)d_in[8];
    const float* b1      = (const float*)d_in[9];
    const float* W1_root = (const float*)d_in[10];
    const float* Wl      = (const float*)d_in[11];
    const float* bl      = (const float*)d_in[12];
    const float* Wv      = (const float*)d_in[13];
    const float* bv      = (const float*)d_in[14];
    float* out = (float*)d_out;

    static int s_attr_done = 0;
    if (!s_attr_done) {
        cudaFuncSetAttribute(k_gemm0_mma,
                             cudaFuncAttributeMaxDynamicSharedMemorySize, SMEM_DYN);
        s_attr_done = 1;
    }

    k_rowptr<<<M_ROWS / 256, 256>>>(flat, nodes, num_nodes);
    k_wsplit<<<dim3(32, 16), dim3(32, 8)>>>(W0_rel, W0_root);
    k_gemm0_mma<<<dim3(4, 256), 256, SMEM_DYN>>>();
    k_h0row<<<dim3(4, BB), 256>>>(adj, num_nodes, b0);
    k_gemm1<<<dim3(16, 4), 256>>>(W1_rel, W1_root, b1);
    k_out<<<BB, 256>>>(Wl, bl, Wv, bv, out, out_size);
}

// round 7
// speedup vs baseline: 2.1953x; 1.0372x over previous
#include <cuda_runtime.h>
#include <cuda_bf16.h>
#include <cstdint>

#define GS 128
#define OBS 1024
#define HH 256
#define OUTD 1024
#define NO 18
#define BB 256
#define M_ROWS (BB * GS)   // 32768

// ---------------- scratch (device globals: no allocation allowed) -------------
__device__ float g_Y[(size_t)M_ROWS * 512];    // [B*GS][512] = [x@W0_rel | x@W0_root]
__device__ float g_rh[BB * 512];               // [r1 | h0_n] per batch
__device__ float g_no[BB * OUTD];              // node_out per batch
__device__ __nv_bfloat16 g_Xh[(size_t)M_ROWS * OBS];   // gathered X hi split
__device__ __nv_bfloat16 g_Xl[(size_t)M_ROWS * OBS];   // gathered X lo split
__device__ __nv_bfloat16 g_Wth[512 * 1024];    // Wt[n][k] = [W0_rel|W0_root]^T hi
__device__ __nv_bfloat16 g_Wtl[512 * 1024];    // lo split

// ---------------- helpers -----------------------------------------------------
__device__ __forceinline__ unsigned su32(const void* p) {
    return (unsigned)__cvta_generic_to_shared(p);
}
__device__ __forceinline__ float bfhi(float x) {
    return __bfloat162float(__float2bfloat16(x));
}
__device__ __forceinline__ unsigned pckbf(float a, float b) {
    return (unsigned)__bfloat16_as_ushort(__float2bfloat16(a))
         | ((unsigned)__bfloat16_as_ushort(__float2bfloat16(b)) << 16);
}
#define CPASYNC16(saddr, gptr) \
    asm volatile("cp.async.cg.shared.global [%0], [%1], 16;" \
                 :: "r"(saddr), "l"(gptr))
#define CPCOMMIT() asm volatile("cp.async.commit_group;")
#define CPWAIT1()  asm volatile("cp.async.wait_group 1;")
#define LDSM4(r0, r1, r2, r3, a) \
    asm volatile("ldmatrix.sync.aligned.m8n8.x4.shared.b16 {%0,%1,%2,%3}, [%4];" \
                 : "=r"(r0), "=r"(r1), "=r"(r2), "=r"(r3) : "r"(a))
#define LDSM2(r0, r1, a) \
    asm volatile("ldmatrix.sync.aligned.m8n8.x2.shared.b16 {%0,%1}, [%2];" \
                 : "=r"(r0), "=r"(r1) : "r"(a))

__device__ __forceinline__ void mma_bf16(float* c, const unsigned* a, const unsigned* b) {
    asm volatile(
        "mma.sync.aligned.m16n8k16.row.col.f32.bf16.bf16.f32 "
        "{%0,%1,%2,%3}, {%4,%5,%6,%7}, {%8,%9}, {%0,%1,%2,%3};"
        : "+f"(c[0]), "+f"(c[1]), "+f"(c[2]), "+f"(c[3])
        : "r"(a[0]), "r"(a[1]), "r"(a[2]), "r"(a[3]), "r"(b[0]), "r"(b[1]));
}

// ---------------- kernel 0: gather X rows + hi/lo bf16 split ------------------
// one thread handles 16 consecutive elements (64 threads per 1024-wide row)
__global__ __launch_bounds__(256) void k_xsplit(const float* __restrict__ flat,
                                                const float* __restrict__ nodes,
                                                const int* __restrict__ num_nodes)
{
    int gid = blockIdx.x * 256 + threadIdx.x;       // 0 .. 2M-1
    int row = gid >> 6;
    int c0 = (gid & 63) * 16;
    int b = row >> 7, j = row & 127;
    const float* src = (j == num_nodes[b]) ? (flat + (size_t)b * OBS)
                                           : (nodes + (size_t)row * OBS);
    __nv_bfloat16* dh = g_Xh + (size_t)row * OBS + c0;
    __nv_bfloat16* dl = g_Xl + (size_t)row * OBS + c0;
#pragma unroll
    for (int i = 0; i < 4; ++i) {
        float4 v = *(const float4*)(src + c0 + i * 4);
        float h0f = bfhi(v.x), h1f = bfhi(v.y), h2f = bfhi(v.z), h3f = bfhi(v.w);
        *(uint2*)(dh + i * 4) = make_uint2(pckbf(h0f, h1f), pckbf(h2f, h3f));
        *(uint2*)(dl + i * 4) = make_uint2(pckbf(v.x - h0f, v.y - h1f),
                                           pckbf(v.z - h2f, v.w - h3f));
    }
}

// ---------------- kernel 0b: transpose + hi/lo bf16 split of [W0_rel|W0_root]
__global__ void k_wsplit(const float* __restrict__ W0_rel,
                         const float* __restrict__ W0_root)
{
    __shared__ float tile[32][33];
    int kb = blockIdx.x * 32, nb = blockIdx.y * 32;
    int tx = threadIdx.x, ty = threadIdx.y;  // (32, 8)
#pragma unroll
    for (int j = 0; j < 32; j += 8) {
        int k = kb + ty + j, n = nb + tx;
        float v = (n < 256) ? W0_rel[(size_t)k * 256 + n]
                            : W0_root[(size_t)k * 256 + (n - 256)];
        tile[ty + j][tx] = v;
    }
    __syncthreads();
#pragma unroll
    for (int j = 0; j < 32; j += 8) {
        int n = nb + ty + j, k = kb + tx;
        float v = tile[tx][ty + j];
        float h = bfhi(v);
        g_Wth[(size_t)n * 1024 + k] = __float2bfloat16(h);
        g_Wtl[(size_t)n * 1024 + k] = __float2bfloat16(v - h);
    }
}

// ---------------- kernel 1: Y = X @ Wt^T, cp.async 3-stage + mma hi/lo --------
// CTA tile 128m x 128n, K chunks of 64. Stage = Ah|Al|Bh|Bl, 16KB each.
// XOR swizzle: addr(r, cb16) = r*128 + ((cb16 ^ (r&7))<<4)
#define STAGE_BYTES 65536
#define SMEM_DYN (3 * STAGE_BYTES)     // 196608

__global__ __launch_bounds__(256) void k_gemm0_mma()
{
    extern __shared__ char dynsmem[];
    unsigned sm = su32(dynsmem);
    int tid = threadIdx.x, lane = tid & 31, wid = tid >> 5;
    int wm = wid >> 2, wn = wid & 3;               // warp tile: 64m x 32n
    int m0 = blockIdx.y * 128, n0 = blockIdx.x * 128;

    // cp.async slot geometry: slot idx = i*256 + tid -> r = idx>>3, cb = tid&7
    int cb = tid & 7;
    int r_lo = tid >> 3;                           // + i*32
    unsigned swo = (unsigned)((cb ^ (r_lo & 7)) << 4);

    // fragment geometry
    int l7 = lane & 7;
    unsigned a_row = (unsigned)(wm * 64 + (lane & 15)) * 128;
    unsigned a_cbx = (unsigned)(lane >> 4);
    unsigned b_row = (unsigned)(wn * 32 + l7) * 128;
    unsigned b_cbx = (unsigned)((lane >> 3) & 1);

    float acc[4][4][4];
#pragma unroll
    for (int mt = 0; mt < 4; ++mt)
#pragma unroll
        for (int nt = 0; nt < 4; ++nt)
#pragma unroll
            for (int r = 0; r < 4; ++r) acc[mt][nt][r] = 0.f;

#define ISSUE(cc)                                                              \
    {                                                                          \
        unsigned sb = sm + ((cc) % 3) * STAGE_BYTES;                           \
        int kt = (cc) * 64;                                                    \
        _Pragma("unroll")                                                      \
        for (int i = 0; i < 4; ++i) {                                          \
            int r = i * 32 + r_lo;                                             \
            unsigned so = (unsigned)(r * 128) + swo;                           \
            size_t goA = (size_t)(m0 + r) * 1024 + kt + cb * 8;                \
            size_t goB = (size_t)(n0 + r) * 1024 + kt + cb * 8;                \
            CPASYNC16(sb + so,         g_Xh + goA);                            \
            CPASYNC16(sb + 16384 + so, g_Xl + goA);                            \
            CPASYNC16(sb + 32768 + so, g_Wth + goB);                           \
            CPASYNC16(sb + 49152 + so, g_Wtl + goB);                           \
        }                                                                      \
        CPCOMMIT();                                                            \
    }

    ISSUE(0);
    ISSUE(1);

    for (int c = 0; c < 16; ++c) {
        CPWAIT1();
        __syncthreads();
        if (c + 2 < 16) ISSUE(c + 2);
        unsigned base = sm + (c % 3) * STAGE_BYTES;
#pragma unroll
        for (int s = 0; s < 4; ++s) {
            unsigned ah[4][4], al[4][4], bh[4][2], bl[4][2];
            unsigned asw = (unsigned)((((unsigned)(s * 2) + a_cbx) ^ (unsigned)l7) << 4);
            unsigned bsw = (unsigned)((((unsigned)(s * 2) + b_cbx) ^ (unsigned)l7) << 4);
#pragma unroll
            for (int mt = 0; mt < 4; ++mt) {
                unsigned aaddr = base + a_row + mt * 2048 + asw;
                LDSM4(ah[mt][0], ah[mt][1], ah[mt][2], ah[mt][3], aaddr);
                LDSM4(al[mt][0], al[mt][1], al[mt][2], al[mt][3], aaddr + 16384);
            }
#pragma unroll
            for (int nt = 0; nt < 4; ++nt) {
                unsigned baddr = base + 32768 + b_row + nt * 1024 + bsw;
                LDSM2(bh[nt][0], bh[nt][1], baddr);
                LDSM2(bl[nt][0], bl[nt][1], baddr + 16384);
            }
#pragma unroll
            for (int mt = 0; mt < 4; ++mt)
#pragma unroll
                for (int nt = 0; nt < 4; ++nt) {
                    mma_bf16(acc[mt][nt], ah[mt], bh[nt]);
                    mma_bf16(acc[mt][nt], ah[mt], bl[nt]);
                    mma_bf16(acc[mt][nt], al[mt], bh[nt]);
                }
        }
    }

#pragma unroll
    for (int mt = 0; mt < 4; ++mt) {
        int m = m0 + wm * 64 + mt * 16 + (lane >> 2);
#pragma unroll
        for (int nt = 0; nt < 4; ++nt) {
            int n = n0 + wn * 32 + nt * 8 + (lane & 3) * 2;
            *(float2*)(g_Y + (size_t)m * 512 + n) =
                make_float2(acc[mt][nt][0], acc[mt][nt][1]);
            *(float2*)(g_Y + (size_t)(m + 8) * 512 + n) =
                make_float2(acc[mt][nt][2], acc[mt][nt][3]);
        }
    }
#undef ISSUE
}

// ---------------- kernel 2: fused h0 + masked column-reduce -------------------
__global__ __launch_bounds__(256) void k_h0row(const int* __restrict__ adj,
                                               const int* __restrict__ num_nodes,
                                               const float* __restrict__ b0)
{
    __shared__ float2 Ysh[128][32];
    __shared__ unsigned bitw[128][4];
    __shared__ int s_n;
    int b = blockIdx.y;
    int c0 = blockIdx.x * 64;
    int tid = threadIdx.x;
    int c2 = tid & 31, ty = tid >> 5;

#pragma unroll
    for (int r = 0; r < 8; ++r) {
        int fi = r * 256 + tid;
        int k = fi >> 4;
        int c4 = (fi & 15) * 4;
        float4 v = *(const float4*)(g_Y + (size_t)(b * 128 + k) * 512 + c0 + c4);
        float2* dst = &Ysh[k][c4 >> 1];
        dst[0] = make_float2(v.x, v.y);
        dst[1] = make_float2(v.z, v.w);
    }
    const int* adjb = adj + (size_t)b * GS * GS;
#pragma unroll 4
    for (int it = 0; it < 64; ++it) {
        int idx = it * 256 + tid;
        unsigned m = __ballot_sync(0xffffffffu, adjb[idx] != 0);
        if ((tid & 31) == 0) bitw[idx >> 7][(idx & 127) >> 5] = m;
    }
    __syncthreads();
    if (tid == 0) {
        int n = num_nodes[b];
        s_n = n;
        bitw[n][n >> 5] |= 1u << (n & 31);
        if (n > 0) {
            bitw[n][(n - 1) >> 5] |= 1u << ((n - 1) & 31);
            bitw[n - 1][n >> 5] |= 1u << (n & 31);
        }
    }
    __syncthreads();

    float2 acc[16];
#pragma unroll
    for (int i = 0; i < 16; ++i) acc[i] = make_float2(0.f, 0.f);

    for (int k = 0; k < 128; ++k) {
        float2 y = Ysh[k][c2];
        unsigned bits = bitw[k][ty >> 1] >> ((ty & 1) * 16);
#pragma unroll
        for (int i = 0; i < 16; ++i) {
            if ((bits >> i) & 1u) { acc[i].x += y.x; acc[i].y += y.y; }
        }
    }

    int n = s_n;
    int c = c0 + c2 * 2;
    float2 bbv = *(const float2*)(b0 + c);
    float2 r1 = make_float2(0.f, 0.f);
#pragma unroll
    for (int i = 0; i < 16; ++i) {
        int j = ty * 16 + i;
        float2 root = *(const float2*)(g_Y + (size_t)(b * 128 + j) * 512 + 256 + c);
        float2 o;
        o.x = fmaxf(acc[i].x + root.x + bbv.x, 0.f);
        o.y = fmaxf(acc[i].y + root.y + bbv.y, 0.f);
        if ((bitw[j][n >> 5] >> (n & 31)) & 1u) { r1.x += o.x; r1.y += o.y; }
        if (j == n) *(float2*)(g_rh + b * 512 + 256 + c) = o;
    }
    __syncthreads();
    float2* part = (float2*)Ysh;
    part[ty * 32 + c2] = r1;
    __syncthreads();
    if (tid < 32) {
        float2 s = part[tid];
#pragma unroll
        for (int w = 1; w < 8; ++w) {
            float2 v = part[w * 32 + tid];
            s.x += v.x; s.y += v.y;
        }
        *(float2*)(g_rh + b * 512 + c0 + tid * 2) = s;
    }
}

// ---------------- kernel 4: node_out = relu(rh @ [W1_rel;W1_root] + b1) -------
__global__ __launch_bounds__(256) void k_gemm1(const float* __restrict__ W1_rel,
                                               const float* __restrict__ W1_root,
                                               const float* __restrict__ b1)
{
    __shared__ float As[8][64];
    __shared__ float Bs[8][64];
    int tid = threadIdx.x;
    int n0 = blockIdx.x * 64, m0 = blockIdx.y * 64;
    int arow = tid >> 2, ak = (tid & 3) * 2;
    int bk = tid >> 5, bn = (tid & 31) * 2;
    int tx = tid & 15, ty = tid >> 4;

    float acc[4][4];
#pragma unroll
    for (int i = 0; i < 4; ++i)
#pragma unroll
        for (int j = 0; j < 4; ++j) acc[i][j] = 0.f;

    for (int kt = 0; kt < 512; kt += 8) {
        float2 av = *(const float2*)(g_rh + (m0 + arow) * 512 + kt + ak);
        const float* Wb = (kt < 256) ? (W1_rel + (size_t)kt * 1024)
                                     : (W1_root + (size_t)(kt - 256) * 1024);
        float2 bv = *(const float2*)(Wb + (size_t)bk * 1024 + n0 + bn);
        As[ak][arow] = av.x;
        As[ak + 1][arow] = av.y;
        *(float2*)&Bs[bk][bn] = bv;
        __syncthreads();
#pragma unroll
        for (int k = 0; k < 8; ++k) {
            float a[4], bb[4];
            *(float4*)a  = *(const float4*)&As[k][ty * 4];
            *(float4*)bb = *(const float4*)&Bs[k][tx * 4];
#pragma unroll
            for (int i = 0; i < 4; ++i)
#pragma unroll
                for (int j = 0; j < 4; ++j) acc[i][j] += a[i] * bb[j];
        }
        __syncthreads();
    }
#pragma unroll
    for (int i = 0; i < 4; ++i) {
        int row = m0 + ty * 4 + i;
#pragma unroll
        for (int j = 0; j < 4; ++j) {
            int col = n0 + tx * 4 + j;
            g_no[(size_t)row * 1024 + col] = fmaxf(acc[i][j] + b1[col], 0.f);
        }
    }
}

// ---------------- kernel 5: logits + value -----------------------------------
__global__ __launch_bounds__(256) void k_out(const float* __restrict__ Wl,
                                             const float* __restrict__ bl,
                                             const float* __restrict__ Wv,
                                             const float* __restrict__ bv,
                                             float* __restrict__ out, int out_size)
{
    int b = blockIdx.x;
    int w = threadIdx.x >> 5, lane = threadIdx.x & 31;
    const float* nb = g_no + (size_t)b * 1024;
    for (int o = w; o < 19; o += 8) {
        float acc = 0.f;
        if (o < 18) {
            for (int i = lane; i < 1024; i += 32) acc += nb[i] * Wl[i * 18 + o];
        } else {
            for (int i = lane; i < 1024; i += 32) acc += nb[i] * Wv[i];
        }
#pragma unroll
        for (int s = 16; s; s >>= 1) acc += __shfl_down_sync(0xffffffffu, acc, s);
        if (lane == 0) {
            if (o < 18) {
                int idx = b * NO + o;
                if (idx < out_size) out[idx] = acc + bl[o];
            } else {
                int idx = BB * NO + b;
                if (idx < out_size) out[idx] = acc + bv[0];
            }
        }
    }
}

// ---------------- launch ------------------------------------------------------
extern "C" void kernel_launch(void* const* d_in, const int* in_sizes, int n_in,
                              void* d_out, int out_size)
{
    const float* flat      = (const float*)d_in[0];
    const float* nodes     = (const float*)d_in[1];
    const int*   num_nodes = (const int*)d_in[2];
    const int*   adj       = (const int*)d_in[3];
    // d_in[4] = seq_lens (unused)
    const float* W0_rel  = (const float*)d_in[5];
    const float* b0      = (const float*)d_in[6];
    const float* W0_root = (const float*)d_in[7];
    const float* W1_rel  = (const float*)d_in[8];
    const float* b1      = (const float*)d_in[9];
    const float* W1_root = (const float*)d_in[10];
    const float* Wl      = (const float*)d_in[11];
    const float* bl      = (const float*)d_in[12];
    const float* Wv      = (const float*)d_in[13];
    const float* bv      = (const float*)d_in[14];
    float* out = (float*)d_out;

    static int s_attr_done = 0;
    if (!s_attr_done) {
        cudaFuncSetAttribute(k_gemm0_mma,
                             cudaFuncAttributeMaxDynamicSharedMemorySize, SMEM_DYN);
        s_attr_done = 1;
    }

    k_xsplit<<<(M_ROWS * OBS) / (16 * 256), 256>>>(flat, nodes, num_nodes);
    k_wsplit<<<dim3(32, 16), dim3(32, 8)>>>(W0_rel, W0_root);
    k_gemm0_mma<<<dim3(4, 256), 256, SMEM_DYN>>>();
    k_h0row<<<dim3(4, BB), 256>>>(adj, num_nodes, b0);
    k_gemm1<<<dim3(16, 4), 256>>>(W1_rel, W1_root, b1);
    k_out<<<BB, 256>>>(Wl, bl, Wv, bv, out, out_size);
}

// round 8
// speedup vs baseline: 3.0572x; 1.3926x over previous
#include <cuda_runtime.h>
#include <cuda_fp16.h>
#include <cstdint>

#define GS 128
#define OBS 1024
#define HH 256
#define OUTD 1024
#define NO 18
#define BB 256
#define M_ROWS (BB * GS)   // 32768

// ---------------- scratch (device globals: no allocation allowed) -------------
__device__ float g_Y[(size_t)M_ROWS * 512];    // [B*GS][512] = [x@W0_rel | x@W0_root]
__device__ float g_rh[BB * 512];               // [r1 | h0_n] per batch
__device__ float g_no[BB * OUTD];              // node_out per batch
__device__ __half g_Xf[(size_t)M_ROWS * OBS];  // gathered X, fp16
__device__ __half g_Wh[512 * 1024];            // Wt[n][k] = [W0_rel|W0_root]^T hi fp16
__device__ __half g_Wl[512 * 1024];            // lo residual fp16

// ---------------- helpers -----------------------------------------------------
__device__ __forceinline__ unsigned su32(const void* p) {
    return (unsigned)__cvta_generic_to_shared(p);
}
__device__ __forceinline__ unsigned pckh(float a, float b) {
    return (unsigned)__half_as_ushort(__float2half_rn(a))
         | ((unsigned)__half_as_ushort(__float2half_rn(b)) << 16);
}
#define CPASYNC16(saddr, gptr) \
    asm volatile("cp.async.cg.shared.global [%0], [%1], 16;" \
                 :: "r"(saddr), "l"(gptr))
#define CPCOMMIT() asm volatile("cp.async.commit_group;")
#define CPWAIT1()  asm volatile("cp.async.wait_group 1;")
#define CPWAIT0()  asm volatile("cp.async.wait_group 0;")
#define LDSM4(r0, r1, r2, r3, a) \
    asm volatile("ldmatrix.sync.aligned.m8n8.x4.shared.b16 {%0,%1,%2,%3}, [%4];" \
                 : "=r"(r0), "=r"(r1), "=r"(r2), "=r"(r3) : "r"(a))
#define LDSM2(r0, r1, a) \
    asm volatile("ldmatrix.sync.aligned.m8n8.x2.shared.b16 {%0,%1}, [%2];" \
                 : "=r"(r0), "=r"(r1) : "r"(a))

__device__ __forceinline__ void mma_f16(float* c, const unsigned* a, const unsigned* b) {
    asm volatile(
        "mma.sync.aligned.m16n8k16.row.col.f32.f16.f16.f32 "
        "{%0,%1,%2,%3}, {%4,%5,%6,%7}, {%8,%9}, {%0,%1,%2,%3};"
        : "+f"(c[0]), "+f"(c[1]), "+f"(c[2]), "+f"(c[3])
        : "r"(a[0]), "r"(a[1]), "r"(a[2]), "r"(a[3]), "r"(b[0]), "r"(b[1]));
}

// ---------------- kernel 0: gather X rows + fp16 convert ----------------------
__global__ __launch_bounds__(256) void k_xsplit(const float* __restrict__ flat,
                                                const float* __restrict__ nodes,
                                                const int* __restrict__ num_nodes)
{
    int gid = blockIdx.x * 256 + threadIdx.x;       // 0 .. 2M-1
    int row = gid >> 6;
    int c0 = (gid & 63) * 16;
    int b = row >> 7, j = row & 127;
    const float* src = (j == num_nodes[b]) ? (flat + (size_t)b * OBS)
                                           : (nodes + (size_t)row * OBS);
    __half* dh = g_Xf + (size_t)row * OBS + c0;
#pragma unroll
    for (int i = 0; i < 4; ++i) {
        float4 v = *(const float4*)(src + c0 + i * 4);
        *(uint2*)(dh + i * 4) = make_uint2(pckh(v.x, v.y), pckh(v.z, v.w));
    }
}

// ---------------- kernel 0b: transpose + fp16 hi/lo split of [W0_rel|W0_root]
__global__ void k_wsplit(const float* __restrict__ W0_rel,
                         const float* __restrict__ W0_root)
{
    __shared__ float tile[32][33];
    int kb = blockIdx.x * 32, nb = blockIdx.y * 32;
    int tx = threadIdx.x, ty = threadIdx.y;  // (32, 8)
#pragma unroll
    for (int j = 0; j < 32; j += 8) {
        int k = kb + ty + j, n = nb + tx;
        float v = (n < 256) ? W0_rel[(size_t)k * 256 + n]
                            : W0_root[(size_t)k * 256 + (n - 256)];
        tile[ty + j][tx] = v;
    }
    __syncthreads();
#pragma unroll
    for (int j = 0; j < 32; j += 8) {
        int n = nb + ty + j, k = kb + tx;
        float v = tile[tx][ty + j];
        __half h = __float2half_rn(v);
        g_Wh[(size_t)n * 1024 + k] = h;
        g_Wl[(size_t)n * 1024 + k] = __float2half_rn(v - __half2float(h));
    }
}

// ---------------- kernel 1: Y = Xf @ (Wh+Wl)^T, cp.async 2-stage + fp16 mma ---
// CTA tile 128m x 128n, K chunks of 64. Stage = X|Wh|Wl, 16KB each = 48KB.
// XOR swizzle: addr(r, cb16) = r*128 + ((cb16 ^ (r&7))<<4)
#define STAGE_BYTES 49152
#define SMEM_DYN (2 * STAGE_BYTES)     // 98304 -> 2 CTAs/SM

__global__ __launch_bounds__(256, 2) void k_gemm0_mma()
{
    extern __shared__ char dynsmem[];
    unsigned sm = su32(dynsmem);
    int tid = threadIdx.x, lane = tid & 31, wid = tid >> 5;
    int wm = wid >> 2, wn = wid & 3;               // warp tile: 64m x 32n
    int m0 = blockIdx.y * 128, n0 = blockIdx.x * 128;

    // cp.async slot geometry: r = i*32 + (tid>>3), cb = tid&7
    int cb = tid & 7;
    int r_lo = tid >> 3;
    unsigned swo = (unsigned)((cb ^ (r_lo & 7)) << 4);

    // fragment geometry
    int l7 = lane & 7;
    unsigned a_row = (unsigned)(wm * 64 + (lane & 15)) * 128;
    unsigned a_cbx = (unsigned)(lane >> 4);
    unsigned b_row = (unsigned)(wn * 32 + l7) * 128;
    unsigned b_cbx = (unsigned)((lane >> 3) & 1);

    float acc[4][4][4];
#pragma unroll
    for (int mt = 0; mt < 4; ++mt)
#pragma unroll
        for (int nt = 0; nt < 4; ++nt)
#pragma unroll
            for (int r = 0; r < 4; ++r) acc[mt][nt][r] = 0.f;

#define ISSUE(cc)                                                              \
    {                                                                          \
        unsigned sb = sm + ((cc) & 1) * STAGE_BYTES;                           \
        int kt = (cc) * 64;                                                    \
        _Pragma("unroll")                                                      \
        for (int i = 0; i < 4; ++i) {                                          \
            int r = i * 32 + r_lo;                                             \
            unsigned so = (unsigned)(r * 128) + swo;                           \
            size_t goA = (size_t)(m0 + r) * 1024 + kt + cb * 8;                \
            size_t goB = (size_t)(n0 + r) * 1024 + kt + cb * 8;                \
            CPASYNC16(sb + so,         g_Xf + goA);                            \
            CPASYNC16(sb + 16384 + so, g_Wh + goB);                            \
            CPASYNC16(sb + 32768 + so, g_Wl + goB);                            \
        }                                                                      \
        CPCOMMIT();                                                            \
    }

    ISSUE(0);

    for (int c = 0; c < 16; ++c) {
        if (c + 1 < 16) { ISSUE(c + 1); CPWAIT1(); }
        else            { CPWAIT0(); }
        __syncthreads();
        unsigned base = sm + (c & 1) * STAGE_BYTES;
#pragma unroll
        for (int s = 0; s < 4; ++s) {
            unsigned a[4][4], bh[4][2], bl[4][2];
            unsigned asw = (unsigned)((((unsigned)(s * 2) + a_cbx) ^ (unsigned)l7) << 4);
            unsigned bsw = (unsigned)((((unsigned)(s * 2) + b_cbx) ^ (unsigned)l7) << 4);
#pragma unroll
            for (int mt = 0; mt < 4; ++mt) {
                unsigned aaddr = base + a_row + mt * 2048 + asw;
                LDSM4(a[mt][0], a[mt][1], a[mt][2], a[mt][3], aaddr);
            }
#pragma unroll
            for (int nt = 0; nt < 4; ++nt) {
                unsigned baddr = base + 16384 + b_row + nt * 1024 + bsw;
                LDSM2(bh[nt][0], bh[nt][1], baddr);
                LDSM2(bl[nt][0], bl[nt][1], baddr + 16384);
            }
#pragma unroll
            for (int mt = 0; mt < 4; ++mt)
#pragma unroll
                for (int nt = 0; nt < 4; ++nt) {
                    mma_f16(acc[mt][nt], a[mt], bh[nt]);
                    mma_f16(acc[mt][nt], a[mt], bl[nt]);
                }
        }
        __syncthreads();
    }

#pragma unroll
    for (int mt = 0; mt < 4; ++mt) {
        int m = m0 + wm * 64 + mt * 16 + (lane >> 2);
#pragma unroll
        for (int nt = 0; nt < 4; ++nt) {
            int n = n0 + wn * 32 + nt * 8 + (lane & 3) * 2;
            *(float2*)(g_Y + (size_t)m * 512 + n) =
                make_float2(acc[mt][nt][0], acc[mt][nt][1]);
            *(float2*)(g_Y + (size_t)(m + 8) * 512 + n) =
                make_float2(acc[mt][nt][2], acc[mt][nt][3]);
        }
    }
#undef ISSUE
}

// ---------------- kernel 2: fused h0 + masked column-reduce -------------------
__global__ __launch_bounds__(256) void k_h0row(const int* __restrict__ adj,
                                               const int* __restrict__ num_nodes,
                                               const float* __restrict__ b0)
{
    __shared__ float2 Ysh[128][32];
    __shared__ unsigned bitw[128][4];
    __shared__ int s_n;
    int b = blockIdx.y;
    int c0 = blockIdx.x * 64;
    int tid = threadIdx.x;
    int c2 = tid & 31, ty = tid >> 5;

#pragma unroll
    for (int r = 0; r < 8; ++r) {
        int fi = r * 256 + tid;
        int k = fi >> 4;
        int c4 = (fi & 15) * 4;
        float4 v = *(const float4*)(g_Y + (size_t)(b * 128 + k) * 512 + c0 + c4);
        float2* dst = &Ysh[k][c4 >> 1];
        dst[0] = make_float2(v.x, v.y);
        dst[1] = make_float2(v.z, v.w);
    }
    const int* adjb = adj + (size_t)b * GS * GS;
#pragma unroll 4
    for (int it = 0; it < 64; ++it) {
        int idx = it * 256 + tid;
        unsigned m = __ballot_sync(0xffffffffu, adjb[idx] != 0);
        if ((tid & 31) == 0) bitw[idx >> 7][(idx & 127) >> 5] = m;
    }
    __syncthreads();
    if (tid == 0) {
        int n = num_nodes[b];
        s_n = n;
        bitw[n][n >> 5] |= 1u << (n & 31);
        if (n > 0) {
            bitw[n][(n - 1) >> 5] |= 1u << ((n - 1) & 31);
            bitw[n - 1][n >> 5] |= 1u << (n & 31);
        }
    }
    __syncthreads();

    float2 acc[16];
#pragma unroll
    for (int i = 0; i < 16; ++i) acc[i] = make_float2(0.f, 0.f);

    for (int k = 0; k < 128; ++k) {
        float2 y = Ysh[k][c2];
        unsigned bits = bitw[k][ty >> 1] >> ((ty & 1) * 16);
#pragma unroll
        for (int i = 0; i < 16; ++i) {
            if ((bits >> i) & 1u) { acc[i].x += y.x; acc[i].y += y.y; }
        }
    }

    int n = s_n;
    int c = c0 + c2 * 2;
    float2 bbv = *(const float2*)(b0 + c);
    float2 r1 = make_float2(0.f, 0.f);
#pragma unroll
    for (int i = 0; i < 16; ++i) {
        int j = ty * 16 + i;
        float2 root = *(const float2*)(g_Y + (size_t)(b * 128 + j) * 512 + 256 + c);
        float2 o;
        o.x = fmaxf(acc[i].x + root.x + bbv.x, 0.f);
        o.y = fmaxf(acc[i].y + root.y + bbv.y, 0.f);
        if ((bitw[j][n >> 5] >> (n & 31)) & 1u) { r1.x += o.x; r1.y += o.y; }
        if (j == n) *(float2*)(g_rh + b * 512 + 256 + c) = o;
    }
    __syncthreads();
    float2* part = (float2*)Ysh;
    part[ty * 32 + c2] = r1;
    __syncthreads();
    if (tid < 32) {
        float2 s = part[tid];
#pragma unroll
        for (int w = 1; w < 8; ++w) {
            float2 v = part[w * 32 + tid];
            s.x += v.x; s.y += v.y;
        }
        *(float2*)(g_rh + b * 512 + c0 + tid * 2) = s;
    }
}

// ---------------- kernel 4: node_out = relu(rh @ [W1_rel;W1_root] + b1) -------
__global__ __launch_bounds__(256) void k_gemm1(const float* __restrict__ W1_rel,
                                               const float* __restrict__ W1_root,
                                               const float* __restrict__ b1)
{
    __shared__ float As[8][64];
    __shared__ float Bs[8][64];
    int tid = threadIdx.x;
    int n0 = blockIdx.x * 64, m0 = blockIdx.y * 64;
    int arow = tid >> 2, ak = (tid & 3) * 2;
    int bk = tid >> 5, bn = (tid & 31) * 2;
    int tx = tid & 15, ty = tid >> 4;

    float acc[4][4];
#pragma unroll
    for (int i = 0; i < 4; ++i)
#pragma unroll
        for (int j = 0; j < 4; ++j) acc[i][j] = 0.f;

    for (int kt = 0; kt < 512; kt += 8) {
        float2 av = *(const float2*)(g_rh + (m0 + arow) * 512 + kt + ak);
        const float* Wb = (kt < 256) ? (W1_rel + (size_t)kt * 1024)
                                     : (W1_root + (size_t)(kt - 256) * 1024);
        float2 bv = *(const float2*)(Wb + (size_t)bk * 1024 + n0 + bn);
        As[ak][arow] = av.x;
        As[ak + 1][arow] = av.y;
        *(float2*)&Bs[bk][bn] = bv;
        __syncthreads();
#pragma unroll
        for (int k = 0; k < 8; ++k) {
            float a[4], bb[4];
            *(float4*)a  = *(const float4*)&As[k][ty * 4];
            *(float4*)bb = *(const float4*)&Bs[k][tx * 4];
#pragma unroll
            for (int i = 0; i < 4; ++i)
#pragma unroll
                for (int j = 0; j < 4; ++j) acc[i][j] += a[i] * bb[j];
        }
        __syncthreads();
    }
#pragma unroll
    for (int i = 0; i < 4; ++i) {
        int row = m0 + ty * 4 + i;
#pragma unroll
        for (int j = 0; j < 4; ++j) {
            int col = n0 + tx * 4 + j;
            g_no[(size_t)row * 1024 + col] = fmaxf(acc[i][j] + b1[col], 0.f);
        }
    }
}

// ---------------- kernel 5: logits + value -----------------------------------
__global__ __launch_bounds__(256) void k_out(const float* __restrict__ Wl,
                                             const float* __restrict__ bl,
                                             const float* __restrict__ Wv,
                                             const float* __restrict__ bv,
                                             float* __restrict__ out, int out_size)
{
    int b = blockIdx.x;
    int w = threadIdx.x >> 5, lane = threadIdx.x & 31;
    const float* nb = g_no + (size_t)b * 1024;
    for (int o = w; o < 19; o += 8) {
        float acc = 0.f;
        if (o < 18) {
            for (int i = lane; i < 1024; i += 32) acc += nb[i] * Wl[i * 18 + o];
        } else {
            for (int i = lane; i < 1024; i += 32) acc += nb[i] * Wv[i];
        }
#pragma unroll
        for (int s = 16; s; s >>= 1) acc += __shfl_down_sync(0xffffffffu, acc, s);
        if (lane == 0) {
            if (o < 18) {
                int idx = b * NO + o;
                if (idx < out_size) out[idx] = acc + bl[o];
            } else {
                int idx = BB * NO + b;
                if (idx < out_size) out[idx] = acc + bv[0];
            }
        }
    }
}

// ---------------- launch ------------------------------------------------------
extern "C" void kernel_launch(void* const* d_in, const int* in_sizes, int n_in,
                              void* d_out, int out_size)
{
    const float* flat      = (const float*)d_in[0];
    const float* nodes     = (const float*)d_in[1];
    const int*   num_nodes = (const int*)d_in[2];
    const int*   adj       = (const int*)d_in[3];
    // d_in[4] = seq_lens (unused)
    const float* W0_rel  = (const float*)d_in[5];
    const float* b0      = (const float*)d_in[6];
    const float* W0_root = (const float*)d_in[7];
    const float* W1_rel  = (const float*)d_in[8];
    const float* b1      = (const float*)d_in[9];
    const float* W1_root = (const float*)d_in[10];
    const float* Wl      = (const float*)d_in[11];
    const float* bl      = (const float*)d_in[12];
    const float* Wv      = (const float*)d_in[13];
    const float* bv      = (const float*)d_in[14];
    float* out = (float*)d_out;

    static int s_attr_done = 0;
    if (!s_attr_done) {
        cudaFuncSetAttribute(k_gemm0_mma,
                             cudaFuncAttributeMaxDynamicSharedMemorySize, SMEM_DYN);
        s_attr_done = 1;
    }

    k_xsplit<<<(M_ROWS * OBS) / (16 * 256), 256>>>(flat, nodes, num_nodes);
    k_wsplit<<<dim3(32, 16), dim3(32, 8)>>>(W0_rel, W0_root);
    k_gemm0_mma<<<dim3(4, 256), 256, SMEM_DYN>>>();
    k_h0row<<<dim3(4, BB), 256>>>(adj, num_nodes, b0);
    k_gemm1<<<dim3(16, 4), 256>>>(W1_rel, W1_root, b1);
    k_out<<<BB, 256>>>(Wl, bl, Wv, bv, out, out_size);
}

// round 9
// speedup vs baseline: 3.7891x; 1.2394x over previous
#include <cuda_runtime.h>
#include <cuda_fp16.h>
#include <cstdint>

#define GS 128
#define OBS 1024
#define HH 256
#define OUTD 1024
#define NO 18
#define BB 256
#define M_ROWS (BB * GS)   // 32768

// ---------------- scratch (device globals: no allocation allowed) -------------
__device__ float g_Y[(size_t)M_ROWS * 512];    // [B*GS][512] = [x@W0_rel | x@W0_root]
__device__ float g_rh[BB * 512];               // [r1 | h0_n] per batch
__device__ float g_no[BB * OUTD];              // node_out per batch
__device__ __half g_Xf[(size_t)M_ROWS * OBS];  // gathered X, fp16
__device__ __half g_Wf[512 * 1024];            // Wt[n][k] = [W0_rel|W0_root]^T fp16

// ---------------- helpers -----------------------------------------------------
__device__ __forceinline__ unsigned su32(const void* p) {
    return (unsigned)__cvta_generic_to_shared(p);
}
__device__ __forceinline__ unsigned pckh(float a, float b) {
    return (unsigned)__half_as_ushort(__float2half_rn(a))
         | ((unsigned)__half_as_ushort(__float2half_rn(b)) << 16);
}
#define STS8(addr, v) \
    asm volatile("st.shared.v2.u32 [%0], {%1, %2};" :: "r"(addr), "r"((v).x), "r"((v).y))
#define CPASYNC16(saddr, gptr) \
    asm volatile("cp.async.cg.shared.global [%0], [%1], 16;" \
                 :: "r"(saddr), "l"(gptr))
#define CPCOMMIT() asm volatile("cp.async.commit_group;")
#define CPWAIT1()  asm volatile("cp.async.wait_group 1;")
#define CPWAIT0()  asm volatile("cp.async.wait_group 0;")
#define LDSM4(r0, r1, r2, r3, a) \
    asm volatile("ldmatrix.sync.aligned.m8n8.x4.shared.b16 {%0,%1,%2,%3}, [%4];" \
                 : "=r"(r0), "=r"(r1), "=r"(r2), "=r"(r3) : "r"(a))
#define LDSM2(r0, r1, a) \
    asm volatile("ldmatrix.sync.aligned.m8n8.x2.shared.b16 {%0,%1}, [%2];" \
                 : "=r"(r0), "=r"(r1) : "r"(a))
#define LDSM2T(r0, r1, a) \
    asm volatile("ldmatrix.sync.aligned.m8n8.x2.trans.shared.b16 {%0,%1}, [%2];" \
                 : "=r"(r0), "=r"(r1) : "r"(a))

__device__ __forceinline__ void mma_f16(float* c, const unsigned* a, const unsigned* b) {
    asm volatile(
        "mma.sync.aligned.m16n8k16.row.col.f32.f16.f16.f32 "
        "{%0,%1,%2,%3}, {%4,%5,%6,%7}, {%8,%9}, {%0,%1,%2,%3};"
        : "+f"(c[0]), "+f"(c[1]), "+f"(c[2]), "+f"(c[3])
        : "r"(a[0]), "r"(a[1]), "r"(a[2]), "r"(a[3]), "r"(b[0]), "r"(b[1]));
}

// ---------------- kernel 0: gather X rows + fp16 convert ----------------------
__global__ __launch_bounds__(256) void k_xsplit(const float* __restrict__ flat,
                                                const float* __restrict__ nodes,
                                                const int* __restrict__ num_nodes)
{
    int gid = blockIdx.x * 256 + threadIdx.x;
    int row = gid >> 6;
    int c0 = (gid & 63) * 16;
    int b = row >> 7, j = row & 127;
    const float* src = (j == num_nodes[b]) ? (flat + (size_t)b * OBS)
                                           : (nodes + (size_t)row * OBS);
    __half* dh = g_Xf + (size_t)row * OBS + c0;
#pragma unroll
    for (int i = 0; i < 4; ++i) {
        float4 v = *(const float4*)(src + c0 + i * 4);
        *(uint2*)(dh + i * 4) = make_uint2(pckh(v.x, v.y), pckh(v.z, v.w));
    }
}

// ---------------- kernel 0b: transpose + fp16 convert of [W0_rel|W0_root] -----
__global__ void k_wsplit(const float* __restrict__ W0_rel,
                         const float* __restrict__ W0_root)
{
    __shared__ float tile[32][33];
    int kb = blockIdx.x * 32, nb = blockIdx.y * 32;
    int tx = threadIdx.x, ty = threadIdx.y;  // (32, 8)
#pragma unroll
    for (int j = 0; j < 32; j += 8) {
        int k = kb + ty + j, n = nb + tx;
        float v = (n < 256) ? W0_rel[(size_t)k * 256 + n]
                            : W0_root[(size_t)k * 256 + (n - 256)];
        tile[ty + j][tx] = v;
    }
    __syncthreads();
#pragma unroll
    for (int j = 0; j < 32; j += 8) {
        int n = nb + ty + j, k = kb + tx;
        g_Wf[(size_t)n * 1024 + k] = __float2half_rn(tile[tx][ty + j]);
    }
}

// ---------------- kernel 1: Y = Xf @ Wf^T, cp.async 2-stage, single product ---
#define STAGE_BYTES 32768
#define SMEM_DYN (2 * STAGE_BYTES)     // 65536 -> 2 CTAs/SM

__global__ __launch_bounds__(256, 2) void k_gemm0_mma()
{
    extern __shared__ char dynsmem[];
    unsigned sm = su32(dynsmem);
    int tid = threadIdx.x, lane = tid & 31, wid = tid >> 5;
    int wm = wid >> 2, wn = wid & 3;               // warp tile: 64m x 32n
    int m0 = blockIdx.y * 128, n0 = blockIdx.x * 128;

    int cb = tid & 7;
    int r_lo = tid >> 3;
    unsigned swo = (unsigned)((cb ^ (r_lo & 7)) << 4);

    int l7 = lane & 7;
    unsigned a_row = (unsigned)(wm * 64 + (lane & 15)) * 128;
    unsigned a_cbx = (unsigned)(lane >> 4);
    unsigned b_row = (unsigned)(wn * 32 + l7) * 128;
    unsigned b_cbx = (unsigned)((lane >> 3) & 1);

    float acc[4][4][4];
#pragma unroll
    for (int mt = 0; mt < 4; ++mt)
#pragma unroll
        for (int nt = 0; nt < 4; ++nt)
#pragma unroll
            for (int r = 0; r < 4; ++r) acc[mt][nt][r] = 0.f;

#define ISSUE(cc)                                                              \
    {                                                                          \
        unsigned sb = sm + ((cc) & 1) * STAGE_BYTES;                           \
        int kt = (cc) * 64;                                                    \
        _Pragma("unroll")                                                      \
        for (int i = 0; i < 4; ++i) {                                          \
            int r = i * 32 + r_lo;                                             \
            unsigned so = (unsigned)(r * 128) + swo;                           \
            size_t goA = (size_t)(m0 + r) * 1024 + kt + cb * 8;                \
            size_t goB = (size_t)(n0 + r) * 1024 + kt + cb * 8;                \
            CPASYNC16(sb + so,         g_Xf + goA);                            \
            CPASYNC16(sb + 16384 + so, g_Wf + goB);                            \
        }                                                                      \
        CPCOMMIT();                                                            \
    }

    ISSUE(0);

    for (int c = 0; c < 16; ++c) {
        if (c + 1 < 16) { ISSUE(c + 1); CPWAIT1(); }
        else            { CPWAIT0(); }
        __syncthreads();
        unsigned base = sm + (c & 1) * STAGE_BYTES;
#pragma unroll
        for (int s = 0; s < 4; ++s) {
            unsigned a[4][4], bh[4][2];
            unsigned asw = (unsigned)((((unsigned)(s * 2) + a_cbx) ^ (unsigned)l7) << 4);
            unsigned bsw = (unsigned)((((unsigned)(s * 2) + b_cbx) ^ (unsigned)l7) << 4);
#pragma unroll
            for (int mt = 0; mt < 4; ++mt) {
                unsigned aaddr = base + a_row + mt * 2048 + asw;
                LDSM4(a[mt][0], a[mt][1], a[mt][2], a[mt][3], aaddr);
            }
#pragma unroll
            for (int nt = 0; nt < 4; ++nt) {
                unsigned baddr = base + 16384 + b_row + nt * 1024 + bsw;
                LDSM2(bh[nt][0], bh[nt][1], baddr);
            }
#pragma unroll
            for (int mt = 0; mt < 4; ++mt)
#pragma unroll
                for (int nt = 0; nt < 4; ++nt)
                    mma_f16(acc[mt][nt], a[mt], bh[nt]);
        }
        __syncthreads();
    }

#pragma unroll
    for (int mt = 0; mt < 4; ++mt) {
        int m = m0 + wm * 64 + mt * 16 + (lane >> 2);
#pragma unroll
        for (int nt = 0; nt < 4; ++nt) {
            int n = n0 + wn * 32 + nt * 8 + (lane & 3) * 2;
            *(float2*)(g_Y + (size_t)m * 512 + n) =
                make_float2(acc[mt][nt][0], acc[mt][nt][1]);
            *(float2*)(g_Y + (size_t)(m + 8) * 512 + n) =
                make_float2(acc[mt][nt][2], acc[mt][nt][3]);
        }
    }
#undef ISSUE
}

// ---------------- kernel 2: mma-based fused h0 + masked column-reduce ---------
#define AT_OFF   0
#define YH_OFF   32768
#define YL_OFF   65536
#define BITW_OFF 98304
#define RED_OFF  100352
#define SN_OFF   102400
#define H0_SMEM  102912

__global__ __launch_bounds__(256, 2) void k_h0row_mma(const int* __restrict__ adj,
                                                      const int* __restrict__ num_nodes,
                                                      const float* __restrict__ b0)
{
    extern __shared__ char dynsmem[];
    unsigned sm = su32(dynsmem);
    unsigned At = sm + AT_OFF, Yh = sm + YH_OFF, Yl = sm + YL_OFF;
    unsigned* bitw = (unsigned*)(dynsmem + BITW_OFF);   // [128][4]
    float* red = (float*)(dynsmem + RED_OFF);           // [4][128]
    int* snp = (int*)(dynsmem + SN_OFF);
    int tid = threadIdx.x, lane = tid & 31, wid = tid >> 5;
    int wm = wid >> 1, wn = wid & 1;       // warp tile: 32 rows x 64 cols
    int b = blockIdx.y, ch = blockIdx.x;   // col half 0/1

    // Yrel[j][c] -> fp16 hi/lo, swizzled rows (stride 256B)
#pragma unroll
    for (int it = 0; it < 16; ++it) {
        int s = it * 256 + tid;
        int j = s >> 5, c0 = (s & 31) * 4;
        float4 v = *(const float4*)(g_Y + (size_t)(b * 128 + j) * 512 + ch * 128 + c0);
        float hx = __half2float(__float2half_rn(v.x));
        float hy = __half2float(__float2half_rn(v.y));
        float hz = __half2float(__float2half_rn(v.z));
        float hw = __half2float(__float2half_rn(v.w));
        unsigned so = (unsigned)(j * 256 + (((c0 >> 3) ^ (j & 7)) << 4) + (c0 & 7) * 2);
        STS8(Yh + so, make_uint2(pckh(v.x, v.y), pckh(v.z, v.w)));
        STS8(Yl + so, make_uint2(pckh(v.x - hx, v.y - hy), pckh(v.z - hz, v.w - hw)));
    }

    const int* adjb = adj + (size_t)b * GS * GS;
#pragma unroll 4
    for (int it = 0; it < 64; ++it) {
        int idx = it * 256 + tid;
        unsigned m = __ballot_sync(0xffffffffu, adjb[idx] != 0);
        if ((tid & 31) == 0) bitw[(idx >> 7) * 4 + ((idx & 127) >> 5)] = m;
    }
    __syncthreads();
    if (tid == 0) {
        int n = num_nodes[b];
        *snp = n;
        bitw[n * 4 + (n >> 5)] |= 1u << (n & 31);
        if (n > 0) {
            bitw[n * 4 + ((n - 1) >> 5)] |= 1u << ((n - 1) & 31);
            bitw[(n - 1) * 4 + (n >> 5)] |= 1u << (n & 31);
        }
    }
    __syncthreads();

    // expand A^T[i][j] = bit i of bitw[j] into fp16 0/1, swizzled
#pragma unroll
    for (int it = 0; it < 16; ++it) {
        int s = it * 256 + tid;
        int i = s >> 5, j0 = (s & 31) * 4;
        unsigned w = (unsigned)(i >> 5), bi = (unsigned)(i & 31);
        const unsigned ONE = 0x3C00u;
        unsigned e0 = (bitw[(j0 + 0) * 4 + w] >> bi) & 1u;
        unsigned e1 = (bitw[(j0 + 1) * 4 + w] >> bi) & 1u;
        unsigned e2 = (bitw[(j0 + 2) * 4 + w] >> bi) & 1u;
        unsigned e3 = (bitw[(j0 + 3) * 4 + w] >> bi) & 1u;
        unsigned p0 = (e0 * ONE) | ((e1 * ONE) << 16);
        unsigned p1 = (e2 * ONE) | ((e3 * ONE) << 16);
        unsigned so = (unsigned)(i * 256 + (((j0 >> 3) ^ (i & 7)) << 4) + (j0 & 7) * 2);
        STS8(At + so, make_uint2(p0, p1));
    }
    __syncthreads();

    float acc[2][8][4];
#pragma unroll
    for (int mt = 0; mt < 2; ++mt)
#pragma unroll
        for (int nt = 0; nt < 8; ++nt)
#pragma unroll
            for (int r = 0; r < 4; ++r) acc[mt][nt][r] = 0.f;

    for (int s = 0; s < 8; ++s) {
        unsigned af[2][4];
#pragma unroll
        for (int mt = 0; mt < 2; ++mt) {
            int r = wm * 32 + mt * 16 + (lane & 15);
            unsigned ad = At + (unsigned)(r * 256)
                        + ((((unsigned)(s * 2 + (lane >> 4))) ^ (unsigned)(r & 7)) << 4);
            LDSM4(af[mt][0], af[mt][1], af[mt][2], af[mt][3], ad);
        }
        int j = s * 16 + (lane & 15);
        unsigned brow = (unsigned)(j * 256);
        unsigned jx = (unsigned)(j & 7);
#pragma unroll
        for (int nt = 0; nt < 8; ++nt) {
            unsigned bd = brow + ((((unsigned)(wn * 8 + nt)) ^ jx) << 4);
            unsigned bh[2], bl[2];
            LDSM2T(bh[0], bh[1], Yh + bd);
            LDSM2T(bl[0], bl[1], Yl + bd);
#pragma unroll
            for (int mt = 0; mt < 2; ++mt) {
                mma_f16(acc[mt][nt], af[mt], bh);
                mma_f16(acc[mt][nt], af[mt], bl);
            }
        }
    }

    int n = *snp;
    unsigned nw = (unsigned)(n >> 5), nbit = 1u << (n & 31);
    float r1p[8][2];
#pragma unroll
    for (int nt = 0; nt < 8; ++nt) { r1p[nt][0] = 0.f; r1p[nt][1] = 0.f; }

#pragma unroll
    for (int mt = 0; mt < 2; ++mt)
#pragma unroll
        for (int hr = 0; hr < 2; ++hr) {
            int i = wm * 32 + mt * 16 + (lane >> 2) + hr * 8;
            bool msk = (bitw[i * 4 + nw] & nbit) != 0;
            const float* rootrow = g_Y + (size_t)(b * 128 + i) * 512 + 256 + ch * 128;
#pragma unroll
            for (int nt = 0; nt < 8; ++nt) {
                int cl = wn * 64 + nt * 8 + (lane & 3) * 2;
                float2 root = *(const float2*)(rootrow + cl);
                float2 bbv = *(const float2*)(b0 + ch * 128 + cl);
                float o0 = fmaxf(acc[mt][nt][hr * 2 + 0] + root.x + bbv.x, 0.f);
                float o1 = fmaxf(acc[mt][nt][hr * 2 + 1] + root.y + bbv.y, 0.f);
                if (msk) { r1p[nt][0] += o0; r1p[nt][1] += o1; }
                if (i == n)
                    *(float2*)(g_rh + b * 512 + 256 + ch * 128 + cl) = make_float2(o0, o1);
            }
        }

#pragma unroll
    for (int nt = 0; nt < 8; ++nt)
#pragma unroll
        for (int t = 0; t < 2; ++t) {
            float v = r1p[nt][t];
            v += __shfl_xor_sync(0xffffffffu, v, 4);
            v += __shfl_xor_sync(0xffffffffu, v, 8);
            v += __shfl_xor_sync(0xffffffffu, v, 16);
            r1p[nt][t] = v;
        }
    if ((lane >> 2) == 0) {
#pragma unroll
        for (int nt = 0; nt < 8; ++nt) {
            red[wm * 128 + wn * 64 + nt * 8 + (lane & 3) * 2 + 0] = r1p[nt][0];
            red[wm * 128 + wn * 64 + nt * 8 + (lane & 3) * 2 + 1] = r1p[nt][1];
        }
    }
    __syncthreads();
    if (tid < 128) {
        float ssum = red[tid] + red[128 + tid] + red[256 + tid] + red[384 + tid];
        g_rh[b * 512 + ch * 128 + tid] = ssum;
    }
}

// ---------------- kernel 4: node_out = relu(rh @ [W1_rel;W1_root] + b1) -------
__global__ __launch_bounds__(256) void k_gemm1(const float* __restrict__ W1_rel,
                                               const float* __restrict__ W1_root,
                                               const float* __restrict__ b1)
{
    __shared__ float As[8][64];
    __shared__ float Bs[8][64];
    int tid = threadIdx.x;
    int n0 = blockIdx.x * 64, m0 = blockIdx.y * 64;
    int arow = tid >> 2, ak = (tid & 3) * 2;
    int bk = tid >> 5, bn = (tid & 31) * 2;
    int tx = tid & 15, ty = tid >> 4;

    float acc[4][4];
#pragma unroll
    for (int i = 0; i < 4; ++i)
#pragma unroll
        for (int j = 0; j < 4; ++j) acc[i][j] = 0.f;

    for (int kt = 0; kt < 512; kt += 8) {
        float2 av = *(const float2*)(g_rh + (m0 + arow) * 512 + kt + ak);
        const float* Wb = (kt < 256) ? (W1_rel + (size_t)kt * 1024)
                                     : (W1_root + (size_t)(kt - 256) * 1024);
        float2 bv = *(const float2*)(Wb + (size_t)bk * 1024 + n0 + bn);
        As[ak][arow] = av.x;
        As[ak + 1][arow] = av.y;
        *(float2*)&Bs[bk][bn] = bv;
        __syncthreads();
#pragma unroll
        for (int k = 0; k < 8; ++k) {
            float a[4], bb[4];
            *(float4*)a  = *(const float4*)&As[k][ty * 4];
            *(float4*)bb = *(const float4*)&Bs[k][tx * 4];
#pragma unroll
            for (int i = 0; i < 4; ++i)
#pragma unroll
                for (int j = 0; j < 4; ++j) acc[i][j] += a[i] * bb[j];
        }
        __syncthreads();
    }
#pragma unroll
    for (int i = 0; i < 4; ++i) {
        int row = m0 + ty * 4 + i;
#pragma unroll
        for (int j = 0; j < 4; ++j) {
            int col = n0 + tx * 4 + j;
            g_no[(size_t)row * 1024 + col] = fmaxf(acc[i][j] + b1[col], 0.f);
        }
    }
}

// ---------------- kernel 5: logits + value -----------------------------------
__global__ __launch_bounds__(256) void k_out(const float* __restrict__ Wl,
                                             const float* __restrict__ bl,
                                             const float* __restrict__ Wv,
                                             const float* __restrict__ bv,
                                             float* __restrict__ out, int out_size)
{
    int b = blockIdx.x;
    int w = threadIdx.x >> 5, lane = threadIdx.x & 31;
    const float* nb = g_no + (size_t)b * 1024;
    for (int o = w; o < 19; o += 8) {
        float acc = 0.f;
        if (o < 18) {
            for (int i = lane; i < 1024; i += 32) acc += nb[i] * Wl[i * 18 + o];
        } else {
            for (int i = lane; i < 1024; i += 32) acc += nb[i] * Wv[i];
        }
#pragma unroll
        for (int s = 16; s; s >>= 1) acc += __shfl_down_sync(0xffffffffu, acc, s);
        if (lane == 0) {
            if (o < 18) {
                int idx = b * NO + o;
                if (idx < out_size) out[idx] = acc + bl[o];
            } else {
                int idx = BB * NO + b;
                if (idx < out_size) out[idx] = acc + bv[0];
            }
        }
    }
}

// ---------------- launch ------------------------------------------------------
extern "C" void kernel_launch(void* const* d_in, const int* in_sizes, int n_in,
                              void* d_out, int out_size)
{
    const float* flat      = (const float*)d_in[0];
    const float* nodes     = (const float*)d_in[1];
    const int*   num_nodes = (const int*)d_in[2];
    const int*   adj       = (const int*)d_in[3];
    // d_in[4] = seq_lens (unused)
    const float* W0_rel  = (const float*)d_in[5];
    const float* b0      = (const float*)d_in[6];
    const float* W0_root = (const float*)d_in[7];
    const float* W1_rel  = (const float*)d_in[8];
    const float* b1      = (const float*)d_in[9];
    const float* W1_root = (const float*)d_in[10];
    const float* Wl      = (const float*)d_in[11];
    const float* bl      = (const float*)d_in[12];
    const float* Wv      = (const float*)d_in[13];
    const float* bv      = (const float*)d_in[14];
    float* out = (float*)d_out;

    static int s_attr_done = 0;
    if (!s_attr_done) {
        cudaFuncSetAttribute(k_gemm0_mma,
                             cudaFuncAttributeMaxDynamicSharedMemorySize, SMEM_DYN);
        cudaFuncSetAttribute(k_h0row_mma,
                             cudaFuncAttributeMaxDynamicSharedMemorySize, H0_SMEM);
        s_attr_done = 1;
    }

    k_xsplit<<<(M_ROWS * OBS) / (16 * 256), 256>>>(flat, nodes, num_nodes);
    k_wsplit<<<dim3(32, 16), dim3(32, 8)>>>(W0_rel, W0_root);
    k_gemm0_mma<<<dim3(4, 256), 256, SMEM_DYN>>>();
    k_h0row_mma<<<dim3(2, BB), 256, H0_SMEM>>>(adj, num_nodes, b0);
    k_gemm1<<<dim3(16, 4), 256>>>(W1_rel, W1_root, b1);
    k_out<<<BB, 256>>>(Wl, bl, Wv, bv, out, out_size);
}

// round 11
// speedup vs baseline: 4.1653x; 1.0993x over previous
#include <cuda_runtime.h>
#include <cuda_fp16.h>
#include <cstdint>

#define GS 128
#define OBS 1024
#define HH 256
#define OUTD 1024
#define NO 18
#define BB 256
#define M_ROWS (BB * GS)   // 32768

// ---------------- scratch (device globals: no allocation allowed) -------------
__device__ __half g_Yh16[(size_t)M_ROWS * 256];  // rel half of Y, fp16
__device__ float g_Yroot[(size_t)M_ROWS * 256];  // root half of Y, fp32
__device__ float g_rh[BB * 512];                 // [r1 | h0_n] per batch
__device__ float g_no[BB * OUTD];                // node_out per batch
__device__ __half g_Xf[(size_t)M_ROWS * OBS];    // gathered X, fp16
__device__ __half g_Wf[512 * 1024];              // Wt[n][k] fp16

// ---------------- helpers -----------------------------------------------------
__device__ __forceinline__ unsigned su32(const void* p) {
    return (unsigned)__cvta_generic_to_shared(p);
}
__device__ __forceinline__ unsigned pckh(float a, float b) {
    return (unsigned)__half_as_ushort(__float2half_rn(a))
         | ((unsigned)__half_as_ushort(__float2half_rn(b)) << 16);
}
#define STS8(addr, v) \
    asm volatile("st.shared.v2.u32 [%0], {%1, %2};" :: "r"(addr), "r"((v).x), "r"((v).y))
#define STS16(addr, v) \
    asm volatile("st.shared.v4.u32 [%0], {%1, %2, %3, %4};" \
                 :: "r"(addr), "r"((v).x), "r"((v).y), "r"((v).z), "r"((v).w))
#define CPASYNC16(saddr, gptr) \
    asm volatile("cp.async.cg.shared.global [%0], [%1], 16;" \
                 :: "r"(saddr), "l"(gptr))
#define CPCOMMIT() asm volatile("cp.async.commit_group;")
#define CPWAIT1()  asm volatile("cp.async.wait_group 1;")
#define CPWAIT0()  asm volatile("cp.async.wait_group 0;")
#define LDSM4(r0, r1, r2, r3, a) \
    asm volatile("ldmatrix.sync.aligned.m8n8.x4.shared.b16 {%0,%1,%2,%3}, [%4];" \
                 : "=r"(r0), "=r"(r1), "=r"(r2), "=r"(r3) : "r"(a))
#define LDSM2(r0, r1, a) \
    asm volatile("ldmatrix.sync.aligned.m8n8.x2.shared.b16 {%0,%1}, [%2];" \
                 : "=r"(r0), "=r"(r1) : "r"(a))
#define LDSM2T(r0, r1, a) \
    asm volatile("ldmatrix.sync.aligned.m8n8.x2.trans.shared.b16 {%0,%1}, [%2];" \
                 : "=r"(r0), "=r"(r1) : "r"(a))

__device__ __forceinline__ void mma_f16(float* c, const unsigned* a, const unsigned* b) {
    asm volatile(
        "mma.sync.aligned.m16n8k16.row.col.f32.f16.f16.f32 "
        "{%0,%1,%2,%3}, {%4,%5,%6,%7}, {%8,%9}, {%0,%1,%2,%3};"
        : "+f"(c[0]), "+f"(c[1]), "+f"(c[2]), "+f"(c[3])
        : "r"(a[0]), "r"(a[1]), "r"(a[2]), "r"(a[3]), "r"(b[0]), "r"(b[1]));
}

// ---------------- kernel 0: gather X rows + fp16 convert ----------------------
__global__ __launch_bounds__(256) void k_xsplit(const float* __restrict__ flat,
                                                const float* __restrict__ nodes,
                                                const int* __restrict__ num_nodes)
{
    int gid = blockIdx.x * 256 + threadIdx.x;
    int row = gid >> 6;
    int c0 = (gid & 63) * 16;
    int b = row >> 7, j = row & 127;
    const float* src = (j == num_nodes[b]) ? (flat + (size_t)b * OBS)
                                           : (nodes + (size_t)row * OBS);
    __half* dh = g_Xf + (size_t)row * OBS + c0;
#pragma unroll
    for (int i = 0; i < 4; ++i) {
        float4 v = *(const float4*)(src + c0 + i * 4);
        *(uint2*)(dh + i * 4) = make_uint2(pckh(v.x, v.y), pckh(v.z, v.w));
    }
}

// ---------------- kernel 0b: transpose + fp16 convert of [W0_rel|W0_root] -----
__global__ void k_wsplit(const float* __restrict__ W0_rel,
                         const float* __restrict__ W0_root)
{
    __shared__ float tile[32][33];
    int kb = blockIdx.x * 32, nb = blockIdx.y * 32;
    int tx = threadIdx.x, ty = threadIdx.y;  // (32, 8)
#pragma unroll
    for (int j = 0; j < 32; j += 8) {
        int k = kb + ty + j, n = nb + tx;
        float v = (n < 256) ? W0_rel[(size_t)k * 256 + n]
                            : W0_root[(size_t)k * 256 + (n - 256)];
        tile[ty + j][tx] = v;
    }
    __syncthreads();
#pragma unroll
    for (int j = 0; j < 32; j += 8) {
        int n = nb + ty + j, k = kb + tx;
        g_Wf[(size_t)n * 1024 + k] = __float2half_rn(tile[tx][ty + j]);
    }
}

// ---------------- kernel 1: Y = Xf @ Wf^T, cp.async 2-stage, single product ---
// rel half (n<256) stored fp16 to g_Yh16; root half stored fp32 to g_Yroot.
#define STAGE_BYTES 32768
#define SMEM_DYN (2 * STAGE_BYTES)     // 65536 -> 2 CTAs/SM

__global__ __launch_bounds__(256, 2) void k_gemm0_mma()
{
    extern __shared__ char dynsmem[];
    unsigned sm = su32(dynsmem);
    int tid = threadIdx.x, lane = tid & 31, wid = tid >> 5;
    int wm = wid >> 2, wn = wid & 3;               // warp tile: 64m x 32n
    int m0 = blockIdx.y * 128, n0 = blockIdx.x * 128;

    int cb = tid & 7;
    int r_lo = tid >> 3;
    unsigned swo = (unsigned)((cb ^ (r_lo & 7)) << 4);

    int l7 = lane & 7;
    unsigned a_row = (unsigned)(wm * 64 + (lane & 15)) * 128;
    unsigned a_cbx = (unsigned)(lane >> 4);
    unsigned b_row = (unsigned)(wn * 32 + l7) * 128;
    unsigned b_cbx = (unsigned)((lane >> 3) & 1);

    float acc[4][4][4];
#pragma unroll
    for (int mt = 0; mt < 4; ++mt)
#pragma unroll
        for (int nt = 0; nt < 4; ++nt)
#pragma unroll
            for (int r = 0; r < 4; ++r) acc[mt][nt][r] = 0.f;

#define ISSUE(cc)                                                              \
    {                                                                          \
        unsigned sb = sm + ((cc) & 1) * STAGE_BYTES;                           \
        int kt = (cc) * 64;                                                    \
        _Pragma("unroll")                                                      \
        for (int i = 0; i < 4; ++i) {                                          \
            int r = i * 32 + r_lo;                                             \
            unsigned so = (unsigned)(r * 128) + swo;                           \
            size_t goA = (size_t)(m0 + r) * 1024 + kt + cb * 8;                \
            size_t goB = (size_t)(n0 + r) * 1024 + kt + cb * 8;                \
            CPASYNC16(sb + so,         g_Xf + goA);                            \
            CPASYNC16(sb + 16384 + so, g_Wf + goB);                            \
        }                                                                      \
        CPCOMMIT();                                                            \
    }

    ISSUE(0);

    for (int c = 0; c < 16; ++c) {
        if (c + 1 < 16) { ISSUE(c + 1); CPWAIT1(); }
        else            { CPWAIT0(); }
        __syncthreads();
        unsigned base = sm + (c & 1) * STAGE_BYTES;
#pragma unroll
        for (int s = 0; s < 4; ++s) {
            unsigned a[4][4], bh[4][2];
            unsigned asw = (unsigned)((((unsigned)(s * 2) + a_cbx) ^ (unsigned)l7) << 4);
            unsigned bsw = (unsigned)((((unsigned)(s * 2) + b_cbx) ^ (unsigned)l7) << 4);
#pragma unroll
            for (int mt = 0; mt < 4; ++mt) {
                unsigned aaddr = base + a_row + mt * 2048 + asw;
                LDSM4(a[mt][0], a[mt][1], a[mt][2], a[mt][3], aaddr);
            }
#pragma unroll
            for (int nt = 0; nt < 4; ++nt) {
                unsigned baddr = base + 16384 + b_row + nt * 1024 + bsw;
                LDSM2(bh[nt][0], bh[nt][1], baddr);
            }
#pragma unroll
            for (int mt = 0; mt < 4; ++mt)
#pragma unroll
                for (int nt = 0; nt < 4; ++nt)
                    mma_f16(acc[mt][nt], a[mt], bh[nt]);
        }
        __syncthreads();
    }

    // epilogue: rel half -> fp16 g_Yh16, root half -> fp32 g_Yroot
    bool isrel = (n0 < 256);
#pragma unroll
    for (int mt = 0; mt < 4; ++mt) {
        int m = m0 + wm * 64 + mt * 16 + (lane >> 2);
#pragma unroll
        for (int nt = 0; nt < 4; ++nt) {
            int n = n0 + wn * 32 + nt * 8 + (lane & 3) * 2;
            if (isrel) {
                *(unsigned*)(g_Yh16 + (size_t)m * 256 + n) =
                    pckh(acc[mt][nt][0], acc[mt][nt][1]);
                *(unsigned*)(g_Yh16 + (size_t)(m + 8) * 256 + n) =
                    pckh(acc[mt][nt][2], acc[mt][nt][3]);
            } else {
                *(float2*)(g_Yroot + (size_t)m * 256 + (n - 256)) =
                    make_float2(acc[mt][nt][0], acc[mt][nt][1]);
                *(float2*)(g_Yroot + (size_t)(m + 8) * 256 + (n - 256)) =
                    make_float2(acc[mt][nt][2], acc[mt][nt][3]);
            }
        }
    }
#undef ISSUE
}

// ---------------- kernel 2: one CTA per batch, fused h0 + masked reduce -------
// D = At(128x128 fp16 0/1) @ Yrel(128x128 fp16) per col-half, looped in-CTA.
// smem: At 32K | Yh 32K | bitw 2K | red 2K | sn
#define AT_OFF   0
#define YH_OFF   32768
#define BITW_OFF 65536
#define RED_OFF  67584
#define SN_OFF   69632
#define H0_SMEM  69648

__global__ __launch_bounds__(256, 2) void k_h0row_mma(const int* __restrict__ adj,
                                                      const int* __restrict__ num_nodes,
                                                      const float* __restrict__ b0)
{
    extern __shared__ char dynsmem[];
    unsigned sm = su32(dynsmem);
    unsigned At = sm + AT_OFF, Yh = sm + YH_OFF;
    unsigned* bitw = (unsigned*)(dynsmem + BITW_OFF);   // [128][4]
    float* red = (float*)(dynsmem + RED_OFF);           // [4][128]
    int* snp = (int*)(dynsmem + SN_OFF);
    int tid = threadIdx.x, lane = tid & 31, wid = tid >> 5;
    int wm = wid >> 1, wn = wid & 1;       // warp tile: 32 rows x 64 cols
    int b = blockIdx.x;

    // ---- adjacency bitset via ballot (once per batch) ----
    const int* adjb = adj + (size_t)b * GS * GS;
#pragma unroll 4
    for (int it = 0; it < 64; ++it) {
        int idx = it * 256 + tid;
        unsigned m = __ballot_sync(0xffffffffu, adjb[idx] != 0);
        if ((tid & 31) == 0) bitw[(idx >> 7) * 4 + ((idx & 127) >> 5)] = m;
    }
    __syncthreads();
    if (tid == 0) {
        int n = num_nodes[b];
        *snp = n;
        bitw[n * 4 + (n >> 5)] |= 1u << (n & 31);
        if (n > 0) {
            bitw[n * 4 + ((n - 1) >> 5)] |= 1u << ((n - 1) & 31);
            bitw[(n - 1) * 4 + (n >> 5)] |= 1u << (n & 31);
        }
    }
    __syncthreads();

    // ---- expand A^T[i][j] = bit i of bitw[j] into fp16 0/1, swizzled (once) --
#pragma unroll
    for (int it = 0; it < 16; ++it) {
        int s = it * 256 + tid;
        int i = s >> 5, j0 = (s & 31) * 4;
        unsigned w = (unsigned)(i >> 5), bi = (unsigned)(i & 31);
        const unsigned ONE = 0x3C00u;
        unsigned e0 = (bitw[(j0 + 0) * 4 + w] >> bi) & 1u;
        unsigned e1 = (bitw[(j0 + 1) * 4 + w] >> bi) & 1u;
        unsigned e2 = (bitw[(j0 + 2) * 4 + w] >> bi) & 1u;
        unsigned e3 = (bitw[(j0 + 3) * 4 + w] >> bi) & 1u;
        unsigned p0 = (e0 * ONE) | ((e1 * ONE) << 16);
        unsigned p1 = (e2 * ONE) | ((e3 * ONE) << 16);
        unsigned so = (unsigned)(i * 256 + (((j0 >> 3) ^ (i & 7)) << 4) + (j0 & 7) * 2);
        STS8(At + so, make_uint2(p0, p1));
    }

    int n = *snp;
    unsigned nw = (unsigned)(n >> 5), nbit = 1u << (n & 31);

    for (int ch = 0; ch < 2; ++ch) {
        // ---- load Yrel half (fp16, pre-converted) into swizzled smem --------
        // 2048 granules of 16 B (8 halves) = 32 KB
#pragma unroll
        for (int it = 0; it < 8; ++it) {
            int s = it * 256 + tid;            // granule 0..2047
            int j = s >> 4, g = s & 15;        // 128 rows x 16 granules
            uint4 v = *(const uint4*)(g_Yh16 + (size_t)(b * 128 + j) * 256
                                      + ch * 128 + g * 8);
            unsigned so = (unsigned)(j * 256 + ((g ^ (j & 7)) << 4));
            STS16(Yh + so, v);
        }
        __syncthreads();

        float acc[2][8][4];
#pragma unroll
        for (int mt = 0; mt < 2; ++mt)
#pragma unroll
            for (int nt = 0; nt < 8; ++nt)
#pragma unroll
                for (int r = 0; r < 4; ++r) acc[mt][nt][r] = 0.f;

        for (int s = 0; s < 8; ++s) {
            unsigned af[2][4];
#pragma unroll
            for (int mt = 0; mt < 2; ++mt) {
                int r = wm * 32 + mt * 16 + (lane & 15);
                unsigned ad = At + (unsigned)(r * 256)
                            + ((((unsigned)(s * 2 + (lane >> 4))) ^ (unsigned)(r & 7)) << 4);
                LDSM4(af[mt][0], af[mt][1], af[mt][2], af[mt][3], ad);
            }
            int j = s * 16 + (lane & 15);
            unsigned brow = (unsigned)(j * 256);
            unsigned jx = (unsigned)(j & 7);
#pragma unroll
            for (int nt = 0; nt < 8; ++nt) {
                unsigned bd = brow + ((((unsigned)(wn * 8 + nt)) ^ jx) << 4);
                unsigned bf[2];
                LDSM2T(bf[0], bf[1], Yh + bd);
#pragma unroll
                for (int mt = 0; mt < 2; ++mt)
                    mma_f16(acc[mt][nt], af[mt], bf);
            }
        }

        // ---- epilogue: relu(+root+bias), masked r1, h0_n ----
        float r1p[8][2];
#pragma unroll
        for (int nt = 0; nt < 8; ++nt) { r1p[nt][0] = 0.f; r1p[nt][1] = 0.f; }

#pragma unroll
        for (int mt = 0; mt < 2; ++mt)
#pragma unroll
            for (int hr = 0; hr < 2; ++hr) {
                int i = wm * 32 + mt * 16 + (lane >> 2) + hr * 8;
                bool msk = (bitw[i * 4 + nw] & nbit) != 0;
                const float* rootrow = g_Yroot + (size_t)(b * 128 + i) * 256 + ch * 128;
#pragma unroll
                for (int nt = 0; nt < 8; ++nt) {
                    int cl = wn * 64 + nt * 8 + (lane & 3) * 2;
                    float2 root = *(const float2*)(rootrow + cl);
                    float2 bbv = *(const float2*)(b0 + ch * 128 + cl);
                    float o0 = fmaxf(acc[mt][nt][hr * 2 + 0] + root.x + bbv.x, 0.f);
                    float o1 = fmaxf(acc[mt][nt][hr * 2 + 1] + root.y + bbv.y, 0.f);
                    if (msk) { r1p[nt][0] += o0; r1p[nt][1] += o1; }
                    if (i == n)
                        *(float2*)(g_rh + b * 512 + 256 + ch * 128 + cl) =
                            make_float2(o0, o1);
                }
            }

#pragma unroll
        for (int nt = 0; nt < 8; ++nt)
#pragma unroll
            for (int t = 0; t < 2; ++t) {
                float v = r1p[nt][t];
                v += __shfl_xor_sync(0xffffffffu, v, 4);
                v += __shfl_xor_sync(0xffffffffu, v, 8);
                v += __shfl_xor_sync(0xffffffffu, v, 16);
                r1p[nt][t] = v;
            }
        if ((lane >> 2) == 0) {
#pragma unroll
            for (int nt = 0; nt < 8; ++nt) {
                red[wm * 128 + wn * 64 + nt * 8 + (lane & 3) * 2 + 0] = r1p[nt][0];
                red[wm * 128 + wn * 64 + nt * 8 + (lane & 3) * 2 + 1] = r1p[nt][1];
            }
        }
        __syncthreads();
        if (tid < 128) {
            float ssum = red[tid] + red[128 + tid] + red[256 + tid] + red[384 + tid];
            g_rh[b * 512 + ch * 128 + tid] = ssum;
        }
        __syncthreads();
    }
}

// ---------------- kernel 4: node_out = relu(rh @ [W1_rel;W1_root] + b1) -------
__global__ __launch_bounds__(256) void k_gemm1(const float* __restrict__ W1_rel,
                                               const float* __restrict__ W1_root,
                                               const float* __restrict__ b1)
{
    __shared__ float As[8][64];
    __shared__ float Bs[8][64];
    int tid = threadIdx.x;
    int n0 = blockIdx.x * 64, m0 = blockIdx.y * 64;
    int arow = tid >> 2, ak = (tid & 3) * 2;
    int bk = tid >> 5, bn = (tid & 31) * 2;
    int tx = tid & 15, ty = tid >> 4;

    float acc[4][4];
#pragma unroll
    for (int i = 0; i < 4; ++i)
#pragma unroll
        for (int j = 0; j < 4; ++j) acc[i][j] = 0.f;

    for (int kt = 0; kt < 512; kt += 8) {
        float2 av = *(const float2*)(g_rh + (m0 + arow) * 512 + kt + ak);
        const float* Wb = (kt < 256) ? (W1_rel + (size_t)kt * 1024)
                                     : (W1_root + (size_t)(kt - 256) * 1024);
        float2 bv = *(const float2*)(Wb + (size_t)bk * 1024 + n0 + bn);
        As[ak][arow] = av.x;
        As[ak + 1][arow] = av.y;
        *(float2*)&Bs[bk][bn] = bv;
        __syncthreads();
#pragma unroll
        for (int k = 0; k < 8; ++k) {
            float a[4], bb[4];
            *(float4*)a  = *(const float4*)&As[k][ty * 4];
            *(float4*)bb = *(const float4*)&Bs[k][tx * 4];
#pragma unroll
            for (int i = 0; i < 4; ++i)
#pragma unroll
                for (int j = 0; j < 4; ++j) acc[i][j] += a[i] * bb[j];
        }
        __syncthreads();
    }
#pragma unroll
    for (int i = 0; i < 4; ++i) {
        int row = m0 + ty * 4 + i;
#pragma unroll
        for (int j = 0; j < 4; ++j) {
            int col = n0 + tx * 4 + j;
            g_no[(size_t)row * 1024 + col] = fmaxf(acc[i][j] + b1[col], 0.f);
        }
    }
}

// ---------------- kernel 5: logits + value -----------------------------------
__global__ __launch_bounds__(256) void k_out(const float* __restrict__ Wl,
                                             const float* __restrict__ bl,
                                             const float* __restrict__ Wv,
                                             const float* __restrict__ bv,
                                             float* __restrict__ out, int out_size)
{
    int b = blockIdx.x;
    int w = threadIdx.x >> 5, lane = threadIdx.x & 31;
    const float* nb = g_no + (size_t)b * 1024;
    for (int o = w; o < 19; o += 8) {
        float acc = 0.f;
        if (o < 18) {
            for (int i = lane; i < 1024; i += 32) acc += nb[i] * Wl[i * 18 + o];
        } else {
            for (int i = lane; i < 1024; i += 32) acc += nb[i] * Wv[i];
        }
#pragma unroll
        for (int s = 16; s; s >>= 1) acc += __shfl_down_sync(0xffffffffu, acc, s);
        if (lane == 0) {
            if (o < 18) {
                int idx = b * NO + o;
                if (idx < out_size) out[idx] = acc + bl[o];
            } else {
                int idx = BB * NO + b;
                if (idx < out_size) out[idx] = acc + bv[0];
            }
        }
    }
}

// ---------------- launch ------------------------------------------------------
extern "C" void kernel_launch(void* const* d_in, const int* in_sizes, int n_in,
                              void* d_out, int out_size)
{
    const float* flat      = (const float*)d_in[0];
    const float* nodes     = (const float*)d_in[1];
    const int*   num_nodes = (const int*)d_in[2];
    const int*   adj       = (const int*)d_in[3];
    // d_in[4] = seq_lens (unused)
    const float* W0_rel  = (const float*)d_in[5];
    const float* b0      = (const float*)d_in[6];
    const float* W0_root = (const float*)d_in[7];
    const float* W1_rel  = (const float*)d_in[8];
    const float* b1      = (const float*)d_in[9];
    const float* W1_root = (const float*)d_in[10];
    const float* Wl      = (const float*)d_in[11];
    const float* bl      = (const float*)d_in[12];
    const float* Wv      = (const float*)d_in[13];
    const float* bv      = (const float*)d_in[14];
    float* out = (float*)d_out;

    static int s_attr_done = 0;
    if (!s_attr_done) {
        cudaFuncSetAttribute(k_gemm0_mma,
                             cudaFuncAttributeMaxDynamicSharedMemorySize, SMEM_DYN);
        cudaFuncSetAttribute(k_h0row_mma,
                             cudaFuncAttributeMaxDynamicSharedMemorySize, H0_SMEM);
        s_attr_done = 1;
    }

    k_xsplit<<<(M_ROWS * OBS) / (16 * 256), 256>>>(flat, nodes, num_nodes);
    k_wsplit<<<dim3(32, 16), dim3(32, 8)>>>(W0_rel, W0_root);
    k_gemm0_mma<<<dim3(4, 256), 256, SMEM_DYN>>>();
    k_h0row_mma<<<BB, 256, H0_SMEM>>>(adj, num_nodes, b0);
    k_gemm1<<<dim3(16, 4), 256>>>(W1_rel, W1_root, b1);
    k_out<<<BB, 256>>>(Wl, bl, Wv, bv, out, out_size);
}

// round 12
// speedup vs baseline: 4.3425x; 1.0425x over previous
#include <cuda_runtime.h>
#include <cuda_fp16.h>
#include <cstdint>

#define GS 128
#define OBS 1024
#define HH 256
#define OUTD 1024
#define NO 18
#define BB 256
#define M_ROWS (BB * GS)   // 32768

// ---------------- scratch (device globals: no allocation allowed) -------------
__device__ __half g_Yh16[(size_t)M_ROWS * 256];  // rel half of Y, fp16
__device__ __half g_Yr16[(size_t)M_ROWS * 256];  // root half of Y, fp16
__device__ float g_rh[BB * 512];                 // [r1 | h0_n] per batch
__device__ float g_no[BB * OUTD];                // node_out per batch
__device__ __half g_Xf[(size_t)M_ROWS * OBS];    // gathered X, fp16
__device__ __half g_Wf[512 * 1024];              // Wt[n][k] fp16

// ---------------- helpers -----------------------------------------------------
__device__ __forceinline__ unsigned su32(const void* p) {
    return (unsigned)__cvta_generic_to_shared(p);
}
__device__ __forceinline__ unsigned pckh(float a, float b) {
    return (unsigned)__half_as_ushort(__float2half_rn(a))
         | ((unsigned)__half_as_ushort(__float2half_rn(b)) << 16);
}
#define STS8(addr, v) \
    asm volatile("st.shared.v2.u32 [%0], {%1, %2};" :: "r"(addr), "r"((v).x), "r"((v).y))
#define CPASYNC16(saddr, gptr) \
    asm volatile("cp.async.cg.shared.global [%0], [%1], 16;" \
                 :: "r"(saddr), "l"(gptr))
#define CPCOMMIT() asm volatile("cp.async.commit_group;")
#define CPWAIT1()  asm volatile("cp.async.wait_group 1;")
#define CPWAIT0()  asm volatile("cp.async.wait_group 0;")
#define LDSM4(r0, r1, r2, r3, a) \
    asm volatile("ldmatrix.sync.aligned.m8n8.x4.shared.b16 {%0,%1,%2,%3}, [%4];" \
                 : "=r"(r0), "=r"(r1), "=r"(r2), "=r"(r3) : "r"(a))
#define LDSM2(r0, r1, a) \
    asm volatile("ldmatrix.sync.aligned.m8n8.x2.shared.b16 {%0,%1}, [%2];" \
                 : "=r"(r0), "=r"(r1) : "r"(a))
#define LDSM2T(r0, r1, a) \
    asm volatile("ldmatrix.sync.aligned.m8n8.x2.trans.shared.b16 {%0,%1}, [%2];" \
                 : "=r"(r0), "=r"(r1) : "r"(a))

__device__ __forceinline__ void mma_f16(float* c, const unsigned* a, const unsigned* b) {
    asm volatile(
        "mma.sync.aligned.m16n8k16.row.col.f32.f16.f16.f32 "
        "{%0,%1,%2,%3}, {%4,%5,%6,%7}, {%8,%9}, {%0,%1,%2,%3};"
        : "+f"(c[0]), "+f"(c[1]), "+f"(c[2]), "+f"(c[3])
        : "r"(a[0]), "r"(a[1]), "r"(a[2]), "r"(a[3]), "r"(b[0]), "r"(b[1]));
}

// ---------------- kernel 0: gather X rows + fp16 convert ----------------------
__global__ __launch_bounds__(256) void k_xsplit(const float* __restrict__ flat,
                                                const float* __restrict__ nodes,
                                                const int* __restrict__ num_nodes)
{
    int gid = blockIdx.x * 256 + threadIdx.x;
    int row = gid >> 6;
    int c0 = (gid & 63) * 16;
    int b = row >> 7, j = row & 127;
    const float* src = (j == num_nodes[b]) ? (flat + (size_t)b * OBS)
                                           : (nodes + (size_t)row * OBS);
    __half* dh = g_Xf + (size_t)row * OBS + c0;
#pragma unroll
    for (int i = 0; i < 4; ++i) {
        float4 v = *(const float4*)(src + c0 + i * 4);
        *(uint2*)(dh + i * 4) = make_uint2(pckh(v.x, v.y), pckh(v.z, v.w));
    }
}

// ---------------- kernel 0b: transpose + fp16 convert of [W0_rel|W0_root] -----
__global__ void k_wsplit(const float* __restrict__ W0_rel,
                         const float* __restrict__ W0_root)
{
    __shared__ float tile[32][33];
    int kb = blockIdx.x * 32, nb = blockIdx.y * 32;
    int tx = threadIdx.x, ty = threadIdx.y;  // (32, 8)
#pragma unroll
    for (int j = 0; j < 32; j += 8) {
        int k = kb + ty + j, n = nb + tx;
        float v = (n < 256) ? W0_rel[(size_t)k * 256 + n]
                            : W0_root[(size_t)k * 256 + (n - 256)];
        tile[ty + j][tx] = v;
    }
    __syncthreads();
#pragma unroll
    for (int j = 0; j < 32; j += 8) {
        int n = nb + ty + j, k = kb + tx;
        g_Wf[(size_t)n * 1024 + k] = __float2half_rn(tile[tx][ty + j]);
    }
}

// ---------------- kernel 1: Y = Xf @ Wf^T, cp.async 2-stage, single product ---
// rel half (n<256) -> fp16 g_Yh16; root half -> fp16 g_Yr16.
#define STAGE_BYTES 32768
#define SMEM_DYN (2 * STAGE_BYTES)     // 65536 -> 2 CTAs/SM

__global__ __launch_bounds__(256, 2) void k_gemm0_mma()
{
    extern __shared__ char dynsmem[];
    unsigned sm = su32(dynsmem);
    int tid = threadIdx.x, lane = tid & 31, wid = tid >> 5;
    int wm = wid >> 2, wn = wid & 3;               // warp tile: 64m x 32n
    int m0 = blockIdx.y * 128, n0 = blockIdx.x * 128;

    int cb = tid & 7;
    int r_lo = tid >> 3;
    unsigned swo = (unsigned)((cb ^ (r_lo & 7)) << 4);

    int l7 = lane & 7;
    unsigned a_row = (unsigned)(wm * 64 + (lane & 15)) * 128;
    unsigned a_cbx = (unsigned)(lane >> 4);
    unsigned b_row = (unsigned)(wn * 32 + l7) * 128;
    unsigned b_cbx = (unsigned)((lane >> 3) & 1);

    float acc[4][4][4];
#pragma unroll
    for (int mt = 0; mt < 4; ++mt)
#pragma unroll
        for (int nt = 0; nt < 4; ++nt)
#pragma unroll
            for (int r = 0; r < 4; ++r) acc[mt][nt][r] = 0.f;

#define ISSUE(cc)                                                              \
    {                                                                          \
        unsigned sb = sm + ((cc) & 1) * STAGE_BYTES;                           \
        int kt = (cc) * 64;                                                    \
        _Pragma("unroll")                                                      \
        for (int i = 0; i < 4; ++i) {                                          \
            int r = i * 32 + r_lo;                                             \
            unsigned so = (unsigned)(r * 128) + swo;                           \
            size_t goA = (size_t)(m0 + r) * 1024 + kt + cb * 8;                \
            size_t goB = (size_t)(n0 + r) * 1024 + kt + cb * 8;                \
            CPASYNC16(sb + so,         g_Xf + goA);                            \
            CPASYNC16(sb + 16384 + so, g_Wf + goB);                            \
        }                                                                      \
        CPCOMMIT();                                                            \
    }

    ISSUE(0);

    for (int c = 0; c < 16; ++c) {
        if (c + 1 < 16) { ISSUE(c + 1); CPWAIT1(); }
        else            { CPWAIT0(); }
        __syncthreads();
        unsigned base = sm + (c & 1) * STAGE_BYTES;
#pragma unroll
        for (int s = 0; s < 4; ++s) {
            unsigned a[4][4], bh[4][2];
            unsigned asw = (unsigned)((((unsigned)(s * 2) + a_cbx) ^ (unsigned)l7) << 4);
            unsigned bsw = (unsigned)((((unsigned)(s * 2) + b_cbx) ^ (unsigned)l7) << 4);
#pragma unroll
            for (int mt = 0; mt < 4; ++mt) {
                unsigned aaddr = base + a_row + mt * 2048 + asw;
                LDSM4(a[mt][0], a[mt][1], a[mt][2], a[mt][3], aaddr);
            }
#pragma unroll
            for (int nt = 0; nt < 4; ++nt) {
                unsigned baddr = base + 16384 + b_row + nt * 1024 + bsw;
                LDSM2(bh[nt][0], bh[nt][1], baddr);
            }
#pragma unroll
            for (int mt = 0; mt < 4; ++mt)
#pragma unroll
                for (int nt = 0; nt < 4; ++nt)
                    mma_f16(acc[mt][nt], a[mt], bh[nt]);
        }
        __syncthreads();
    }

    // epilogue: both halves stored fp16 (rel -> g_Yh16, root -> g_Yr16)
    bool isrel = (n0 < 256);
#pragma unroll
    for (int mt = 0; mt < 4; ++mt) {
        int m = m0 + wm * 64 + mt * 16 + (lane >> 2);
#pragma unroll
        for (int nt = 0; nt < 4; ++nt) {
            int n = n0 + wn * 32 + nt * 8 + (lane & 3) * 2;
            __half* dst0 = isrel ? (g_Yh16 + (size_t)m * 256 + n)
                                 : (g_Yr16 + (size_t)m * 256 + (n - 256));
            __half* dst1 = isrel ? (g_Yh16 + (size_t)(m + 8) * 256 + n)
                                 : (g_Yr16 + (size_t)(m + 8) * 256 + (n - 256));
            *(unsigned*)dst0 = pckh(acc[mt][nt][0], acc[mt][nt][1]);
            *(unsigned*)dst1 = pckh(acc[mt][nt][2], acc[mt][nt][3]);
        }
    }
#undef ISSUE
}

// ---------------- kernel 2: one CTA per batch, fused h0 + masked reduce -------
// cp.async prefetch of BOTH Yrel ch-tiles at entry overlaps ballot/At expand.
// smem: At 32K | Yh0 32K | Yh1 32K | bitw 2K | red 2K | sn
#define AT_OFF   0
#define YH0_OFF  32768
#define YH1_OFF  65536
#define BITW_OFF 98304
#define RED_OFF  100352
#define SN_OFF   102400
#define H0_SMEM  102416

__global__ __launch_bounds__(256, 2) void k_h0row_mma(const int* __restrict__ adj,
                                                      const int* __restrict__ num_nodes,
                                                      const float* __restrict__ b0)
{
    extern __shared__ char dynsmem[];
    unsigned sm = su32(dynsmem);
    unsigned At = sm + AT_OFF;
    unsigned YhBuf[2] = {sm + YH0_OFF, sm + YH1_OFF};
    unsigned* bitw = (unsigned*)(dynsmem + BITW_OFF);   // [128][4]
    float* red = (float*)(dynsmem + RED_OFF);           // [4][128]
    int* snp = (int*)(dynsmem + SN_OFF);
    int tid = threadIdx.x, lane = tid & 31, wid = tid >> 5;
    int wm = wid >> 1, wn = wid & 1;       // warp tile: 32 rows x 64 cols
    int b = blockIdx.x;

    // ---- prefetch both Yrel ch-tiles via cp.async (overlaps ballot phase) ----
#pragma unroll
    for (int ch = 0; ch < 2; ++ch) {
#pragma unroll
        for (int it = 0; it < 8; ++it) {
            int s = it * 256 + tid;            // 16B granule 0..2047
            int j = s >> 4, g = s & 15;
            unsigned so = (unsigned)(j * 256 + ((g ^ (j & 7)) << 4));
            CPASYNC16(YhBuf[ch] + so,
                      g_Yh16 + (size_t)(b * 128 + j) * 256 + ch * 128 + g * 8);
        }
        CPCOMMIT();
    }

    // ---- adjacency bitset via ballot ----
    const int* adjb = adj + (size_t)b * GS * GS;
#pragma unroll 4
    for (int it = 0; it < 64; ++it) {
        int idx = it * 256 + tid;
        unsigned m = __ballot_sync(0xffffffffu, adjb[idx] != 0);
        if ((tid & 31) == 0) bitw[(idx >> 7) * 4 + ((idx & 127) >> 5)] = m;
    }
    __syncthreads();
    if (tid == 0) {
        int n = num_nodes[b];
        *snp = n;
        bitw[n * 4 + (n >> 5)] |= 1u << (n & 31);
        if (n > 0) {
            bitw[n * 4 + ((n - 1) >> 5)] |= 1u << ((n - 1) & 31);
            bitw[(n - 1) * 4 + (n >> 5)] |= 1u << (n & 31);
        }
    }
    __syncthreads();

    // ---- expand A^T[i][j] = bit i of bitw[j] into fp16 0/1, swizzled ----
#pragma unroll
    for (int it = 0; it < 16; ++it) {
        int s = it * 256 + tid;
        int i = s >> 5, j0 = (s & 31) * 4;
        unsigned w = (unsigned)(i >> 5), bi = (unsigned)(i & 31);
        const unsigned ONE = 0x3C00u;
        unsigned e0 = (bitw[(j0 + 0) * 4 + w] >> bi) & 1u;
        unsigned e1 = (bitw[(j0 + 1) * 4 + w] >> bi) & 1u;
        unsigned e2 = (bitw[(j0 + 2) * 4 + w] >> bi) & 1u;
        unsigned e3 = (bitw[(j0 + 3) * 4 + w] >> bi) & 1u;
        unsigned p0 = (e0 * ONE) | ((e1 * ONE) << 16);
        unsigned p1 = (e2 * ONE) | ((e3 * ONE) << 16);
        unsigned so = (unsigned)(i * 256 + (((j0 >> 3) ^ (i & 7)) << 4) + (j0 & 7) * 2);
        STS8(At + so, make_uint2(p0, p1));
    }

    int n = *snp;
    unsigned nw = (unsigned)(n >> 5), nbit = 1u << (n & 31);

#pragma unroll
    for (int ch = 0; ch < 2; ++ch) {
        if (ch == 0) CPWAIT1(); else CPWAIT0();
        __syncthreads();
        unsigned Yh = YhBuf[ch];

        float acc[2][8][4];
#pragma unroll
        for (int mt = 0; mt < 2; ++mt)
#pragma unroll
            for (int nt = 0; nt < 8; ++nt)
#pragma unroll
                for (int r = 0; r < 4; ++r) acc[mt][nt][r] = 0.f;

        for (int s = 0; s < 8; ++s) {
            unsigned af[2][4];
#pragma unroll
            for (int mt = 0; mt < 2; ++mt) {
                int r = wm * 32 + mt * 16 + (lane & 15);
                unsigned ad = At + (unsigned)(r * 256)
                            + ((((unsigned)(s * 2 + (lane >> 4))) ^ (unsigned)(r & 7)) << 4);
                LDSM4(af[mt][0], af[mt][1], af[mt][2], af[mt][3], ad);
            }
            int j = s * 16 + (lane & 15);
            unsigned brow = (unsigned)(j * 256);
            unsigned jx = (unsigned)(j & 7);
#pragma unroll
            for (int nt = 0; nt < 8; ++nt) {
                unsigned bd = brow + ((((unsigned)(wn * 8 + nt)) ^ jx) << 4);
                unsigned bf[2];
                LDSM2T(bf[0], bf[1], Yh + bd);
#pragma unroll
                for (int mt = 0; mt < 2; ++mt)
                    mma_f16(acc[mt][nt], af[mt], bf);
            }
        }

        // ---- epilogue: relu(+root(fp16)+bias), masked r1, h0_n ----
        float r1p[8][2];
#pragma unroll
        for (int nt = 0; nt < 8; ++nt) { r1p[nt][0] = 0.f; r1p[nt][1] = 0.f; }

#pragma unroll
        for (int mt = 0; mt < 2; ++mt)
#pragma unroll
            for (int hr = 0; hr < 2; ++hr) {
                int i = wm * 32 + mt * 16 + (lane >> 2) + hr * 8;
                bool msk = (bitw[i * 4 + nw] & nbit) != 0;
                const __half* rootrow = g_Yr16 + (size_t)(b * 128 + i) * 256 + ch * 128;
#pragma unroll
                for (int nt = 0; nt < 8; ++nt) {
                    int cl = wn * 64 + nt * 8 + (lane & 3) * 2;
                    float2 root = __half22float2(*(const __half2*)(rootrow + cl));
                    float2 bbv = *(const float2*)(b0 + ch * 128 + cl);
                    float o0 = fmaxf(acc[mt][nt][hr * 2 + 0] + root.x + bbv.x, 0.f);
                    float o1 = fmaxf(acc[mt][nt][hr * 2 + 1] + root.y + bbv.y, 0.f);
                    if (msk) { r1p[nt][0] += o0; r1p[nt][1] += o1; }
                    if (i == n)
                        *(float2*)(g_rh + b * 512 + 256 + ch * 128 + cl) =
                            make_float2(o0, o1);
                }
            }

#pragma unroll
        for (int nt = 0; nt < 8; ++nt)
#pragma unroll
            for (int t = 0; t < 2; ++t) {
                float v = r1p[nt][t];
                v += __shfl_xor_sync(0xffffffffu, v, 4);
                v += __shfl_xor_sync(0xffffffffu, v, 8);
                v += __shfl_xor_sync(0xffffffffu, v, 16);
                r1p[nt][t] = v;
            }
        if ((lane >> 2) == 0) {
#pragma unroll
            for (int nt = 0; nt < 8; ++nt) {
                red[wm * 128 + wn * 64 + nt * 8 + (lane & 3) * 2 + 0] = r1p[nt][0];
                red[wm * 128 + wn * 64 + nt * 8 + (lane & 3) * 2 + 1] = r1p[nt][1];
            }
        }
        __syncthreads();
        if (tid < 128) {
            float ssum = red[tid] + red[128 + tid] + red[256 + tid] + red[384 + tid];
            g_rh[b * 512 + ch * 128 + tid] = ssum;
        }
        __syncthreads();
    }
}

// ---------------- kernel 4: node_out = relu(rh @ [W1_rel;W1_root] + b1) -------
__global__ __launch_bounds__(256) void k_gemm1(const float* __restrict__ W1_rel,
                                               const float* __restrict__ W1_root,
                                               const float* __restrict__ b1)
{
    __shared__ float As[8][64];
    __shared__ float Bs[8][64];
    int tid = threadIdx.x;
    int n0 = blockIdx.x * 64, m0 = blockIdx.y * 64;
    int arow = tid >> 2, ak = (tid & 3) * 2;
    int bk = tid >> 5, bn = (tid & 31) * 2;
    int tx = tid & 15, ty = tid >> 4;

    float acc[4][4];
#pragma unroll
    for (int i = 0; i < 4; ++i)
#pragma unroll
        for (int j = 0; j < 4; ++j) acc[i][j] = 0.f;

    for (int kt = 0; kt < 512; kt += 8) {
        float2 av = *(const float2*)(g_rh + (m0 + arow) * 512 + kt + ak);
        const float* Wb = (kt < 256) ? (W1_rel + (size_t)kt * 1024)
                                     : (W1_root + (size_t)(kt - 256) * 1024);
        float2 bv = *(const float2*)(Wb + (size_t)bk * 1024 + n0 + bn);
        As[ak][arow] = av.x;
        As[ak + 1][arow] = av.y;
        *(float2*)&Bs[bk][bn] = bv;
        __syncthreads();
#pragma unroll
        for (int k = 0; k < 8; ++k) {
            float a[4], bb[4];
            *(float4*)a  = *(const float4*)&As[k][ty * 4];
            *(float4*)bb = *(const float4*)&Bs[k][tx * 4];
#pragma unroll
            for (int i = 0; i < 4; ++i)
#pragma unroll
                for (int j = 0; j < 4; ++j) acc[i][j] += a[i] * bb[j];
        }
        __syncthreads();
    }
#pragma unroll
    for (int i = 0; i < 4; ++i) {
        int row = m0 + ty * 4 + i;
#pragma unroll
        for (int j = 0; j < 4; ++j) {
            int col = n0 + tx * 4 + j;
            g_no[(size_t)row * 1024 + col] = fmaxf(acc[i][j] + b1[col], 0.f);
        }
    }
}

// ---------------- kernel 5: logits + value -----------------------------------
__global__ __launch_bounds__(256) void k_out(const float* __restrict__ Wl,
                                             const float* __restrict__ bl,
                                             const float* __restrict__ Wv,
                                             const float* __restrict__ bv,
                                             float* __restrict__ out, int out_size)
{
    int b = blockIdx.x;
    int w = threadIdx.x >> 5, lane = threadIdx.x & 31;
    const float* nb = g_no + (size_t)b * 1024;
    for (int o = w; o < 19; o += 8) {
        float acc = 0.f;
        if (o < 18) {
            for (int i = lane; i < 1024; i += 32) acc += nb[i] * Wl[i * 18 + o];
        } else {
            for (int i = lane; i < 1024; i += 32) acc += nb[i] * Wv[i];
        }
#pragma unroll
        for (int s = 16; s; s >>= 1) acc += __shfl_down_sync(0xffffffffu, acc, s);
        if (lane == 0) {
            if (o < 18) {
                int idx = b * NO + o;
                if (idx < out_size) out[idx] = acc + bl[o];
            } else {
                int idx = BB * NO + b;
                if (idx < out_size) out[idx] = acc + bv[0];
            }
        }
    }
}

// ---------------- launch ------------------------------------------------------
extern "C" void kernel_launch(void* const* d_in, const int* in_sizes, int n_in,
                              void* d_out, int out_size)
{
    const float* flat      = (const float*)d_in[0];
    const float* nodes     = (const float*)d_in[1];
    const int*   num_nodes = (const int*)d_in[2];
    const int*   adj       = (const int*)d_in[3];
    // d_in[4] = seq_lens (unused)
    const float* W0_rel  = (const float*)d_in[5];
    const float* b0      = (const float*)d_in[6];
    const float* W0_root = (const float*)d_in[7];
    const float* W1_rel  = (const float*)d_in[8];
    const float* b1      = (const float*)d_in[9];
    const float* W1_root = (const float*)d_in[10];
    const float* Wl      = (const float*)d_in[11];
    const float* bl      = (const float*)d_in[12];
    const float* Wv      = (const float*)d_in[13];
    const float* bv      = (const float*)d_in[14];
    float* out = (float*)d_out;

    static int s_attr_done = 0;
    if (!s_attr_done) {
        cudaFuncSetAttribute(k_gemm0_mma,
                             cudaFuncAttributeMaxDynamicSharedMemorySize, SMEM_DYN);
        cudaFuncSetAttribute(k_h0row_mma,
                             cudaFuncAttributeMaxDynamicSharedMemorySize, H0_SMEM);
        s_attr_done = 1;
    }

    k_xsplit<<<(M_ROWS * OBS) / (16 * 256), 256>>>(flat, nodes, num_nodes);
    k_wsplit<<<dim3(32, 16), dim3(32, 8)>>>(W0_rel, W0_root);
    k_gemm0_mma<<<dim3(4, 256), 256, SMEM_DYN>>>();
    k_h0row_mma<<<BB, 256, H0_SMEM>>>(adj, num_nodes, b0);
    k_gemm1<<<dim3(16, 4), 256>>>(W1_rel, W1_root, b1);
    k_out<<<BB, 256>>>(Wl, bl, Wv, bv, out, out_size);
}

// round 13
// speedup vs baseline: 4.4628x; 1.0277x over previous
#include <cuda_runtime.h>
#include <cuda_fp16.h>
#include <cstdint>

#define GS 128
#define OBS 1024
#define HH 256
#define OUTD 1024
#define NO 18
#define BB 256
#define M_ROWS (BB * GS)   // 32768

// ---------------- scratch (device globals: no allocation allowed) -------------
__device__ __half g_Yh16[(size_t)M_ROWS * 256];  // rel half of Y, fp16
__device__ __half g_Yr16[(size_t)M_ROWS * 256];  // root half of Y, fp16
__device__ float g_rh[BB * 512];                 // [r1 | h0_n] per batch
__device__ float g_no[BB * OUTD];                // node_out per batch
__device__ __half g_Xf[(size_t)M_ROWS * OBS];    // gathered X, fp16
__device__ __half g_Wf[512 * 1024];              // Wt[n][k] fp16

// ---------------- helpers -----------------------------------------------------
__device__ __forceinline__ unsigned su32(const void* p) {
    return (unsigned)__cvta_generic_to_shared(p);
}
__device__ __forceinline__ unsigned pckh(float a, float b) {
    return (unsigned)__half_as_ushort(__float2half_rn(a))
         | ((unsigned)__half_as_ushort(__float2half_rn(b)) << 16);
}
#define STS8(addr, v) \
    asm volatile("st.shared.v2.u32 [%0], {%1, %2};" :: "r"(addr), "r"((v).x), "r"((v).y))
#define CPASYNC16(saddr, gptr) \
    asm volatile("cp.async.cg.shared.global [%0], [%1], 16;" \
                 :: "r"(saddr), "l"(gptr))
#define CPCOMMIT() asm volatile("cp.async.commit_group;")
#define CPWAIT1()  asm volatile("cp.async.wait_group 1;")
#define CPWAIT0()  asm volatile("cp.async.wait_group 0;")
#define LDSM4(r0, r1, r2, r3, a) \
    asm volatile("ldmatrix.sync.aligned.m8n8.x4.shared.b16 {%0,%1,%2,%3}, [%4];" \
                 : "=r"(r0), "=r"(r1), "=r"(r2), "=r"(r3) : "r"(a))
#define LDSM2T(r0, r1, a) \
    asm volatile("ldmatrix.sync.aligned.m8n8.x2.trans.shared.b16 {%0,%1}, [%2];" \
                 : "=r"(r0), "=r"(r1) : "r"(a))

__device__ __forceinline__ void mma_f16(float* c, const unsigned* a, const unsigned* b) {
    asm volatile(
        "mma.sync.aligned.m16n8k16.row.col.f32.f16.f16.f32 "
        "{%0,%1,%2,%3}, {%4,%5,%6,%7}, {%8,%9}, {%0,%1,%2,%3};"
        : "+f"(c[0]), "+f"(c[1]), "+f"(c[2]), "+f"(c[3])
        : "r"(a[0]), "r"(a[1]), "r"(a[2]), "r"(a[3]), "r"(b[0]), "r"(b[1]));
}

// ---------------- kernel 0: gather X rows + fp16 convert ----------------------
__global__ __launch_bounds__(256) void k_xsplit(const float* __restrict__ flat,
                                                const float* __restrict__ nodes,
                                                const int* __restrict__ num_nodes)
{
    int gid = blockIdx.x * 256 + threadIdx.x;
    int row = gid >> 6;
    int c0 = (gid & 63) * 16;
    int b = row >> 7, j = row & 127;
    const float* src = (j == num_nodes[b]) ? (flat + (size_t)b * OBS)
                                           : (nodes + (size_t)row * OBS);
    __half* dh = g_Xf + (size_t)row * OBS + c0;
#pragma unroll
    for (int i = 0; i < 4; ++i) {
        float4 v = *(const float4*)(src + c0 + i * 4);
        *(uint2*)(dh + i * 4) = make_uint2(pckh(v.x, v.y), pckh(v.z, v.w));
    }
}

// ---------------- kernel 0b: transpose + fp16 convert of [W0_rel|W0_root] -----
__global__ void k_wsplit(const float* __restrict__ W0_rel,
                         const float* __restrict__ W0_root)
{
    __shared__ float tile[32][33];
    int kb = blockIdx.x * 32, nb = blockIdx.y * 32;
    int tx = threadIdx.x, ty = threadIdx.y;  // (32, 8)
#pragma unroll
    for (int j = 0; j < 32; j += 8) {
        int k = kb + ty + j, n = nb + tx;
        float v = (n < 256) ? W0_rel[(size_t)k * 256 + n]
                            : W0_root[(size_t)k * 256 + (n - 256)];
        tile[ty + j][tx] = v;
    }
    __syncthreads();
#pragma unroll
    for (int j = 0; j < 32; j += 8) {
        int n = nb + ty + j, k = kb + tx;
        g_Wf[(size_t)n * 1024 + k] = __float2half_rn(tile[tx][ty + j]);
    }
}

// ---------------- kernel 1: Y = Xf @ Wf^T, cp.async 2-stage, single product ---
// rel half (n<256) -> fp16 g_Yh16; root half -> fp16 g_Yr16.
// B fragments loaded as LDSM4 pairs (2 n-tiles per op).
#define STAGE_BYTES 32768
#define SMEM_DYN (2 * STAGE_BYTES)     // 65536 -> 2 CTAs/SM

__global__ __launch_bounds__(256, 2) void k_gemm0_mma()
{
    extern __shared__ char dynsmem[];
    unsigned sm = su32(dynsmem);
    int tid = threadIdx.x, lane = tid & 31, wid = tid >> 5;
    int wm = wid >> 2, wn = wid & 3;               // warp tile: 64m x 32n
    int m0 = blockIdx.y * 128, n0 = blockIdx.x * 128;

    int cb = tid & 7;
    int r_lo = tid >> 3;
    unsigned swo = (unsigned)((cb ^ (r_lo & 7)) << 4);

    int l7 = lane & 7;
    unsigned a_row = (unsigned)(wm * 64 + (lane & 15)) * 128;
    unsigned a_cbx = (unsigned)(lane >> 4);
    unsigned b_row = (unsigned)(wn * 32 + l7) * 128;
    unsigned b_cbx = (unsigned)((lane >> 3) & 1);       // k-half within fragment
    unsigned b_nt4 = (unsigned)((lane >> 4) & 1) * 1024; // nt+1 rows for LDSM4

    float acc[4][4][4];
#pragma unroll
    for (int mt = 0; mt < 4; ++mt)
#pragma unroll
        for (int nt = 0; nt < 4; ++nt)
#pragma unroll
            for (int r = 0; r < 4; ++r) acc[mt][nt][r] = 0.f;

#define ISSUE(cc)                                                              \
    {                                                                          \
        unsigned sb = sm + ((cc) & 1) * STAGE_BYTES;                           \
        int kt = (cc) * 64;                                                    \
        _Pragma("unroll")                                                      \
        for (int i = 0; i < 4; ++i) {                                          \
            int r = i * 32 + r_lo;                                             \
            unsigned so = (unsigned)(r * 128) + swo;                           \
            size_t goA = (size_t)(m0 + r) * 1024 + kt + cb * 8;                \
            size_t goB = (size_t)(n0 + r) * 1024 + kt + cb * 8;                \
            CPASYNC16(sb + so,         g_Xf + goA);                            \
            CPASYNC16(sb + 16384 + so, g_Wf + goB);                            \
        }                                                                      \
        CPCOMMIT();                                                            \
    }

    ISSUE(0);

    for (int c = 0; c < 16; ++c) {
        if (c + 1 < 16) { ISSUE(c + 1); CPWAIT1(); }
        else            { CPWAIT0(); }
        __syncthreads();
        unsigned base = sm + (c & 1) * STAGE_BYTES;
#pragma unroll
        for (int s = 0; s < 4; ++s) {
            unsigned a[4][4], bf[2][4];
            unsigned asw = (unsigned)((((unsigned)(s * 2) + a_cbx) ^ (unsigned)l7) << 4);
            unsigned bsw = (unsigned)((((unsigned)(s * 2) + b_cbx) ^ (unsigned)l7) << 4);
#pragma unroll
            for (int mt = 0; mt < 4; ++mt) {
                unsigned aaddr = base + a_row + mt * 2048 + asw;
                LDSM4(a[mt][0], a[mt][1], a[mt][2], a[mt][3], aaddr);
            }
            // B: one LDSM4 per nt-pair; lanes 16-31 fetch the nt+1 fragment
#pragma unroll
            for (int p = 0; p < 2; ++p) {
                unsigned baddr = base + 16384 + b_row + p * 2048 + b_nt4 + bsw;
                LDSM4(bf[p][0], bf[p][1], bf[p][2], bf[p][3], baddr);
            }
#pragma unroll
            for (int mt = 0; mt < 4; ++mt)
#pragma unroll
                for (int p = 0; p < 2; ++p) {
                    mma_f16(acc[mt][p * 2 + 0], a[mt], bf[p] + 0);
                    mma_f16(acc[mt][p * 2 + 1], a[mt], bf[p] + 2);
                }
        }
        __syncthreads();
    }

    // epilogue: both halves stored fp16 (rel -> g_Yh16, root -> g_Yr16)
    bool isrel = (n0 < 256);
#pragma unroll
    for (int mt = 0; mt < 4; ++mt) {
        int m = m0 + wm * 64 + mt * 16 + (lane >> 2);
#pragma unroll
        for (int nt = 0; nt < 4; ++nt) {
            int n = n0 + wn * 32 + nt * 8 + (lane & 3) * 2;
            __half* dst0 = isrel ? (g_Yh16 + (size_t)m * 256 + n)
                                 : (g_Yr16 + (size_t)m * 256 + (n - 256));
            __half* dst1 = isrel ? (g_Yh16 + (size_t)(m + 8) * 256 + n)
                                 : (g_Yr16 + (size_t)(m + 8) * 256 + (n - 256));
            *(unsigned*)dst0 = pckh(acc[mt][nt][0], acc[mt][nt][1]);
            *(unsigned*)dst1 = pckh(acc[mt][nt][2], acc[mt][nt][3]);
        }
    }
#undef ISSUE
}

// ---------------- kernel 2: one CTA per batch, fused h0 + masked reduce -------
// cp.async prefetch of BOTH Yrel ch-tiles at entry overlaps ballot/At expand.
// smem: At 32K | Yh0 32K | Yh1 32K | bitw 2K | red 2K | sn
#define AT_OFF   0
#define YH0_OFF  32768
#define YH1_OFF  65536
#define BITW_OFF 98304
#define RED_OFF  100352
#define SN_OFF   102400
#define H0_SMEM  102416

__global__ __launch_bounds__(256, 2) void k_h0row_mma(const int* __restrict__ adj,
                                                      const int* __restrict__ num_nodes,
                                                      const float* __restrict__ b0)
{
    extern __shared__ char dynsmem[];
    unsigned sm = su32(dynsmem);
    unsigned At = sm + AT_OFF;
    unsigned YhBuf[2] = {sm + YH0_OFF, sm + YH1_OFF};
    unsigned* bitw = (unsigned*)(dynsmem + BITW_OFF);   // [128][4]
    float* red = (float*)(dynsmem + RED_OFF);           // [4][128]
    int* snp = (int*)(dynsmem + SN_OFF);
    int tid = threadIdx.x, lane = tid & 31, wid = tid >> 5;
    int wm = wid >> 1, wn = wid & 1;       // warp tile: 32 rows x 64 cols
    int b = blockIdx.x;

    // ---- prefetch both Yrel ch-tiles via cp.async (overlaps ballot phase) ----
#pragma unroll
    for (int ch = 0; ch < 2; ++ch) {
#pragma unroll
        for (int it = 0; it < 8; ++it) {
            int s = it * 256 + tid;            // 16B granule 0..2047
            int j = s >> 4, g = s & 15;
            unsigned so = (unsigned)(j * 256 + ((g ^ (j & 7)) << 4));
            CPASYNC16(YhBuf[ch] + so,
                      g_Yh16 + (size_t)(b * 128 + j) * 256 + ch * 128 + g * 8);
        }
        CPCOMMIT();
    }

    // ---- adjacency bitset via ballot, MLP-8 batched loads ----
    const int* adjb = adj + (size_t)b * GS * GS;
#pragma unroll
    for (int g8 = 0; g8 < 8; ++g8) {
        int va[8];
#pragma unroll
        for (int it = 0; it < 8; ++it)
            va[it] = adjb[g8 * 2048 + it * 256 + tid];
#pragma unroll
        for (int it = 0; it < 8; ++it) {
            int idx = g8 * 2048 + it * 256 + tid;
            unsigned m = __ballot_sync(0xffffffffu, va[it] != 0);
            if ((tid & 31) == 0) bitw[(idx >> 7) * 4 + ((idx & 127) >> 5)] = m;
        }
    }
    __syncthreads();
    if (tid == 0) {
        int n = num_nodes[b];
        *snp = n;
        bitw[n * 4 + (n >> 5)] |= 1u << (n & 31);
        if (n > 0) {
            bitw[n * 4 + ((n - 1) >> 5)] |= 1u << ((n - 1) & 31);
            bitw[(n - 1) * 4 + (n >> 5)] |= 1u << (n & 31);
        }
    }
    __syncthreads();

    // ---- expand A^T[i][j] = bit i of bitw[j] into fp16 0/1, swizzled ----
#pragma unroll
    for (int it = 0; it < 16; ++it) {
        int s = it * 256 + tid;
        int i = s >> 5, j0 = (s & 31) * 4;
        unsigned w = (unsigned)(i >> 5), bi = (unsigned)(i & 31);
        const unsigned ONE = 0x3C00u;
        unsigned e0 = (bitw[(j0 + 0) * 4 + w] >> bi) & 1u;
        unsigned e1 = (bitw[(j0 + 1) * 4 + w] >> bi) & 1u;
        unsigned e2 = (bitw[(j0 + 2) * 4 + w] >> bi) & 1u;
        unsigned e3 = (bitw[(j0 + 3) * 4 + w] >> bi) & 1u;
        unsigned p0 = (e0 * ONE) | ((e1 * ONE) << 16);
        unsigned p1 = (e2 * ONE) | ((e3 * ONE) << 16);
        unsigned so = (unsigned)(i * 256 + (((j0 >> 3) ^ (i & 7)) << 4) + (j0 & 7) * 2);
        STS8(At + so, make_uint2(p0, p1));
    }

    int n = *snp;
    unsigned nw = (unsigned)(n >> 5), nbit = 1u << (n & 31);

#pragma unroll
    for (int ch = 0; ch < 2; ++ch) {
        if (ch == 0) CPWAIT1(); else CPWAIT0();
        __syncthreads();
        unsigned Yh = YhBuf[ch];

        float acc[2][8][4];
#pragma unroll
        for (int mt = 0; mt < 2; ++mt)
#pragma unroll
            for (int nt = 0; nt < 8; ++nt)
#pragma unroll
                for (int r = 0; r < 4; ++r) acc[mt][nt][r] = 0.f;

        for (int s = 0; s < 8; ++s) {
            unsigned af[2][4];
#pragma unroll
            for (int mt = 0; mt < 2; ++mt) {
                int r = wm * 32 + mt * 16 + (lane & 15);
                unsigned ad = At + (unsigned)(r * 256)
                            + ((((unsigned)(s * 2 + (lane >> 4))) ^ (unsigned)(r & 7)) << 4);
                LDSM4(af[mt][0], af[mt][1], af[mt][2], af[mt][3], ad);
            }
            int j = s * 16 + (lane & 15);
            unsigned brow = (unsigned)(j * 256);
            unsigned jx = (unsigned)(j & 7);
#pragma unroll
            for (int nt = 0; nt < 8; ++nt) {
                unsigned bd = brow + ((((unsigned)(wn * 8 + nt)) ^ jx) << 4);
                unsigned bf[2];
                LDSM2T(bf[0], bf[1], Yh + bd);
#pragma unroll
                for (int mt = 0; mt < 2; ++mt)
                    mma_f16(acc[mt][nt], af[mt], bf);
            }
        }

        // ---- epilogue: relu(+root(fp16)+bias), masked r1, h0_n ----
        float r1p[8][2];
#pragma unroll
        for (int nt = 0; nt < 8; ++nt) { r1p[nt][0] = 0.f; r1p[nt][1] = 0.f; }

#pragma unroll
        for (int mt = 0; mt < 2; ++mt)
#pragma unroll
            for (int hr = 0; hr < 2; ++hr) {
                int i = wm * 32 + mt * 16 + (lane >> 2) + hr * 8;
                bool msk = (bitw[i * 4 + nw] & nbit) != 0;
                const __half* rootrow = g_Yr16 + (size_t)(b * 128 + i) * 256 + ch * 128;
#pragma unroll
                for (int nt = 0; nt < 8; ++nt) {
                    int cl = wn * 64 + nt * 8 + (lane & 3) * 2;
                    float2 root = __half22float2(*(const __half2*)(rootrow + cl));
                    float2 bbv = *(const float2*)(b0 + ch * 128 + cl);
                    float o0 = fmaxf(acc[mt][nt][hr * 2 + 0] + root.x + bbv.x, 0.f);
                    float o1 = fmaxf(acc[mt][nt][hr * 2 + 1] + root.y + bbv.y, 0.f);
                    if (msk) { r1p[nt][0] += o0; r1p[nt][1] += o1; }
                    if (i == n)
                        *(float2*)(g_rh + b * 512 + 256 + ch * 128 + cl) =
                            make_float2(o0, o1);
                }
            }

#pragma unroll
        for (int nt = 0; nt < 8; ++nt)
#pragma unroll
            for (int t = 0; t < 2; ++t) {
                float v = r1p[nt][t];
                v += __shfl_xor_sync(0xffffffffu, v, 4);
                v += __shfl_xor_sync(0xffffffffu, v, 8);
                v += __shfl_xor_sync(0xffffffffu, v, 16);
                r1p[nt][t] = v;
            }
        if ((lane >> 2) == 0) {
#pragma unroll
            for (int nt = 0; nt < 8; ++nt) {
                red[wm * 128 + wn * 64 + nt * 8 + (lane & 3) * 2 + 0] = r1p[nt][0];
                red[wm * 128 + wn * 64 + nt * 8 + (lane & 3) * 2 + 1] = r1p[nt][1];
            }
        }
        __syncthreads();
        if (tid < 128) {
            float ssum = red[tid] + red[128 + tid] + red[256 + tid] + red[384 + tid];
            g_rh[b * 512 + ch * 128 + tid] = ssum;
        }
        __syncthreads();
    }
}

// ---------------- kernel 4: node_out = relu(rh @ [W1_rel;W1_root] + b1) -------
__global__ __launch_bounds__(256) void k_gemm1(const float* __restrict__ W1_rel,
                                               const float* __restrict__ W1_root,
                                               const float* __restrict__ b1)
{
    __shared__ float As[8][64];
    __shared__ float Bs[8][64];
    int tid = threadIdx.x;
    int n0 = blockIdx.x * 64, m0 = blockIdx.y * 64;
    int arow = tid >> 2, ak = (tid & 3) * 2;
    int bk = tid >> 5, bn = (tid & 31) * 2;
    int tx = tid & 15, ty = tid >> 4;

    float acc[4][4];
#pragma unroll
    for (int i = 0; i < 4; ++i)
#pragma unroll
        for (int j = 0; j < 4; ++j) acc[i][j] = 0.f;

    for (int kt = 0; kt < 512; kt += 8) {
        float2 av = *(const float2*)(g_rh + (m0 + arow) * 512 + kt + ak);
        const float* Wb = (kt < 256) ? (W1_rel + (size_t)kt * 1024)
                                     : (W1_root + (size_t)(kt - 256) * 1024);
        float2 bv = *(const float2*)(Wb + (size_t)bk * 1024 + n0 + bn);
        As[ak][arow] = av.x;
        As[ak + 1][arow] = av.y;
        *(float2*)&Bs[bk][bn] = bv;
        __syncthreads();
#pragma unroll
        for (int k = 0; k < 8; ++k) {
            float a[4], bb[4];
            *(float4*)a  = *(const float4*)&As[k][ty * 4];
            *(float4*)bb = *(const float4*)&Bs[k][tx * 4];
#pragma unroll
            for (int i = 0; i < 4; ++i)
#pragma unroll
                for (int j = 0; j < 4; ++j) acc[i][j] += a[i] * bb[j];
        }
        __syncthreads();
    }
#pragma unroll
    for (int i = 0; i < 4; ++i) {
        int row = m0 + ty * 4 + i;
#pragma unroll
        for (int j = 0; j < 4; ++j) {
            int col = n0 + tx * 4 + j;
            g_no[(size_t)row * 1024 + col] = fmaxf(acc[i][j] + b1[col], 0.f);
        }
    }
}

// ---------------- kernel 5: logits + value -----------------------------------
__global__ __launch_bounds__(256) void k_out(const float* __restrict__ Wl,
                                             const float* __restrict__ bl,
                                             const float* __restrict__ Wv,
                                             const float* __restrict__ bv,
                                             float* __restrict__ out, int out_size)
{
    int b = blockIdx.x;
    int w = threadIdx.x >> 5, lane = threadIdx.x & 31;
    const float* nb = g_no + (size_t)b * 1024;
    for (int o = w; o < 19; o += 8) {
        float acc = 0.f;
        if (o < 18) {
            for (int i = lane; i < 1024; i += 32) acc += nb[i] * Wl[i * 18 + o];
        } else {
            for (int i = lane; i < 1024; i += 32) acc += nb[i] * Wv[i];
        }
#pragma unroll
        for (int s = 16; s; s >>= 1) acc += __shfl_down_sync(0xffffffffu, acc, s);
        if (lane == 0) {
            if (o < 18) {
                int idx = b * NO + o;
                if (idx < out_size) out[idx] = acc + bl[o];
            } else {
                int idx = BB * NO + b;
                if (idx < out_size) out[idx] = acc + bv[0];
            }
        }
    }
}

// ---------------- launch ------------------------------------------------------
extern "C" void kernel_launch(void* const* d_in, const int* in_sizes, int n_in,
                              void* d_out, int out_size)
{
    const float* flat      = (const float*)d_in[0];
    const float* nodes     = (const float*)d_in[1];
    const int*   num_nodes = (const int*)d_in[2];
    const int*   adj       = (const int*)d_in[3];
    // d_in[4] = seq_lens (unused)
    const float* W0_rel  = (const float*)d_in[5];
    const float* b0      = (const float*)d_in[6];
    const float* W0_root = (const float*)d_in[7];
    const float* W1_rel  = (const float*)d_in[8];
    const float* b1      = (const float*)d_in[9];
    const float* W1_root = (const float*)d_in[10];
    const float* Wl      = (const float*)d_in[11];
    const float* bl      = (const float*)d_in[12];
    const float* Wv      = (const float*)d_in[13];
    const float* bv      = (const float*)d_in[14];
    float* out = (float*)d_out;

    static int s_attr_done = 0;
    if (!s_attr_done) {
        cudaFuncSetAttribute(k_gemm0_mma,
                             cudaFuncAttributeMaxDynamicSharedMemorySize, SMEM_DYN);
        cudaFuncSetAttribute(k_h0row_mma,
                             cudaFuncAttributeMaxDynamicSharedMemorySize, H0_SMEM);
        s_attr_done = 1;
    }

    k_xsplit<<<(M_ROWS * OBS) / (16 * 256), 256>>>(flat, nodes, num_nodes);
    k_wsplit<<<dim3(32, 16), dim3(32, 8)>>>(W0_rel, W0_root);
    k_gemm0_mma<<<dim3(4, 256), 256, SMEM_DYN>>>();
    k_h0row_mma<<<BB, 256, H0_SMEM>>>(adj, num_nodes, b0);
    k_gemm1<<<dim3(16, 4), 256>>>(W1_rel, W1_root, b1);
    k_out<<<BB, 256>>>(Wl, bl, Wv, bv, out, out_size);
}